// round 3
// baseline (speedup 1.0000x reference)
#include <cuda_runtime.h>
#include <cstdint>

#define BB 2
#define QL 1024
#define ML 1024
#define KLEN 2048
#define EMB 1024
#define NH 16
#define DH 64

// ---------------- scratch (static device, allocation-free) ----------------
__device__ float g_Q[BB * QL * EMB];               // [b,q,h,d]
__device__ float g_K[BB * KLEN * EMB];             // [b,k,h,d]
__device__ float g_V[BB * KLEN * EMB];             // [b,k,h,d]
__device__ float g_R[KLEN * EMB];                  // [p,h,d]
__device__ float g_BD[(size_t)BB * NH * QL * KLEN];// pre-shifted BD [b,h,q,j]
__device__ float g_AO[BB * QL * EMB];              // attention out (tf32-rounded)
__device__ float g_X[BB * QL * EMB];               // pre-LN residual sum
__device__ float g_WT[5ull * 1024 * 1024];         // transposed weights [n][k] (tf32-rounded)
__device__ float g_cat[BB * KLEN * EMB];           // rounded cat(member, w)
__device__ float g_rR[KLEN * EMB];                 // rounded r

__device__ __forceinline__ uint32_t smem_u32(const void* p) {
    uint32_t a;
    asm("{ .reg .u64 t; cvta.to.shared.u64 t, %1; cvt.u32.u64 %0, t; }" : "=r"(a) : "l"(p));
    return a;
}
__device__ __forceinline__ float rna_tf32(float x) {
    uint32_t o;
    asm("cvt.rna.tf32.f32 %0, %1;" : "=r"(o) : "f"(x));
    return __uint_as_float(o);
}

// ---------------- prep: round inputs to tf32 ----------------
// g_cat[b][t][e] = rna(cat(member,w)); g_rR = rna(r)
__global__ __launch_bounds__(256) void prep_round(
    const float* __restrict__ w, const float* __restrict__ member,
    const float* __restrict__ r)
{
    const int CAT4 = BB * KLEN * EMB / 4;  // 1048576
    int i = blockIdx.x * 256 + threadIdx.x;
    if (i < CAT4) {
        int f = i * 4;
        int b = f >> 21;
        int rem = f & ((1 << 21) - 1);
        int t = rem >> 10;
        int e = rem & 1023;
        const float* src = (t < ML)
            ? (member + ((size_t)b * ML + t) * EMB + e)
            : (w + ((size_t)b * QL + (t - ML)) * EMB + e);
        float4 v = *(const float4*)src;
        v.x = rna_tf32(v.x); v.y = rna_tf32(v.y);
        v.z = rna_tf32(v.z); v.w = rna_tf32(v.w);
        ((float4*)g_cat)[i] = v;
    } else {
        int j = i - CAT4;
        float4 v = ((const float4*)r)[j];
        v.x = rna_tf32(v.x); v.y = rna_tf32(v.y);
        v.z = rna_tf32(v.z); v.w = rna_tf32(v.w);
        ((float4*)g_rR)[j] = v;
    }
}

// ---------------- weight transpose (+ tf32 round): g_WT[z][n][k] = rna(W_z[k][n]) ----------------
__global__ __launch_bounds__(256) void transposeW(
    const float* __restrict__ w0, const float* __restrict__ w1,
    const float* __restrict__ w2, const float* __restrict__ w3,
    const float* __restrict__ w4)
{
    __shared__ float t[32][33];
    const float* src;
    switch (blockIdx.z) {
        case 0: src = w0; break;
        case 1: src = w1; break;
        case 2: src = w2; break;
        case 3: src = w3; break;
        default: src = w4; break;
    }
    float* dst = g_WT + ((size_t)blockIdx.z << 20);
    int tx = threadIdx.x & 31, ty = threadIdx.x >> 5;
    int x = blockIdx.x * 32 + tx;
    int y = blockIdx.y * 32 + ty;
#pragma unroll
    for (int j = 0; j < 32; j += 8)
        t[ty + j][tx] = src[(size_t)(y + j) * EMB + x];
    __syncthreads();
    x = blockIdx.y * 32 + tx;
    y = blockIdx.x * 32 + ty;
#pragma unroll
    for (int j = 0; j < 32; j += 8)
        dst[(size_t)(y + j) * EMB + x] = rna_tf32(t[tx][ty + j]);
}

// ---------------- tf32 mma.sync GEMM: C[M,1024] = A[M,1024] @ WT^T ----------------
// WT layout [n][k]. Tile 128x128, 8 warps (4x2), warp tile 32x64, K-chunk 32,
// cp.async double-buffered. qmode=1: row gather m -> cat row b*2048+1024+q.
#define BUF_BYTES 36864                 // (128*36)*2 regions * 4B
#define SMEM_GEMM (2 * BUF_BYTES)       // 73728
__global__ __launch_bounds__(256) void mma_gemm(
    const float* __restrict__ A, const float* __restrict__ WT,
    float* __restrict__ C, const float* __restrict__ resid, int qmode)
{
    extern __shared__ float sm[];
    const uint32_t sb = smem_u32(sm);
    const int tid = threadIdx.x;
    const int lane = tid & 31, wid = tid >> 5;
    const int m0 = blockIdx.y * 128, n0 = blockIdx.x * 128;
    const int wm = wid >> 1, wn = wid & 1;
    const int g = lane >> 2, tig = lane & 3;

    // load geometry: 4 float4 per thread for each of A,B per 32-K chunk
    const float* ag[4];
    const float* bg[4];
    uint32_t soff[4];
#pragma unroll
    for (int u = 0; u < 4; u++) {
        int f4 = tid + 256 * u;
        int row = f4 >> 3, c4 = f4 & 7;
        int m = m0 + row;
        int arow = qmode ? (((m >> 10) << 11) + 1024 + (m & 1023)) : m;
        ag[u] = A + (size_t)arow * EMB + c4 * 4;
        bg[u] = WT + (size_t)(n0 + row) * EMB + c4 * 4;
        soff[u] = (uint32_t)(row * 36 + c4 * 4) * 4;
    }

#define CPA(dst, src) asm volatile("cp.async.cg.shared.global [%0], [%1], 16;" :: "r"(dst), "l"(src) : "memory")
#define LOADC(k0, bb) do { \
        uint32_t base_ = sb + (bb) * BUF_BYTES; \
        _Pragma("unroll") \
        for (int u = 0; u < 4; u++) { \
            CPA(base_ + soff[u], ag[u] + (k0)); \
            CPA(base_ + 18432 + soff[u], bg[u] + (k0)); \
        } \
        asm volatile("cp.async.commit_group;" ::: "memory"); \
    } while (0)

    float c[2][8][4];
#pragma unroll
    for (int mf = 0; mf < 2; mf++)
#pragma unroll
        for (int nf = 0; nf < 8; nf++)
#pragma unroll
            for (int e = 0; e < 4; e++) c[mf][nf][e] = 0.f;

    LOADC(0, 0);

    for (int it = 0; it < 32; it++) {
        asm volatile("cp.async.wait_group 0;" ::: "memory");
        __syncthreads();
        if (it + 1 < 32) LOADC((it + 1) * 32, (it + 1) & 1);

        const float* As = sm + (it & 1) * 9216 + (wm * 32) * 36;
        const float* Bs = sm + (it & 1) * 9216 + 4608 + (wn * 64) * 36;

#pragma unroll
        for (int ks = 0; ks < 4; ks++) {
            uint32_t a[2][4];
            const float* ap = As + g * 36 + ks * 8 + tig;
#pragma unroll
            for (int mf = 0; mf < 2; mf++) {
                const float* p = ap + mf * 576;       // 16*36
                a[mf][0] = __float_as_uint(p[0]);
                a[mf][1] = __float_as_uint(p[288]);   // +8 rows
                a[mf][2] = __float_as_uint(p[4]);     // +4 cols
                a[mf][3] = __float_as_uint(p[292]);
            }
#pragma unroll
            for (int nf = 0; nf < 8; nf++) {
                const float* p = Bs + (nf * 8 + g) * 36 + ks * 8 + tig;
                uint32_t b0 = __float_as_uint(p[0]);
                uint32_t b1 = __float_as_uint(p[4]);
#pragma unroll
                for (int mf = 0; mf < 2; mf++) {
                    asm volatile(
                        "mma.sync.aligned.m16n8k8.row.col.f32.tf32.tf32.f32 "
                        "{%0,%1,%2,%3}, {%4,%5,%6,%7}, {%8,%9}, {%0,%1,%2,%3};"
                        : "+f"(c[mf][nf][0]), "+f"(c[mf][nf][1]),
                          "+f"(c[mf][nf][2]), "+f"(c[mf][nf][3])
                        : "r"(a[mf][0]), "r"(a[mf][1]), "r"(a[mf][2]), "r"(a[mf][3]),
                          "r"(b0), "r"(b1));
                }
            }
        }
    }

    // epilogue: c[mf][nf]: rows m0+wm*32+mf*16+g(+8), cols n0+wn*64+nf*8+2*tig(+1)
#pragma unroll
    for (int mf = 0; mf < 2; mf++) {
        int r0 = m0 + wm * 32 + mf * 16 + g;
#pragma unroll
        for (int nf = 0; nf < 8; nf++) {
            int col = n0 + wn * 64 + nf * 8 + tig * 2;
            float2 v0 = make_float2(c[mf][nf][0], c[mf][nf][1]);
            float2 v1 = make_float2(c[mf][nf][2], c[mf][nf][3]);
            if (resid) {
                float2 a0 = *(const float2*)(resid + (size_t)r0 * EMB + col);
                float2 a1 = *(const float2*)(resid + (size_t)(r0 + 8) * EMB + col);
                v0.x += a0.x; v0.y += a0.y;
                v1.x += a1.x; v1.y += a1.y;
            }
            *(float2*)(C + (size_t)r0 * EMB + col) = v0;
            *(float2*)(C + (size_t)(r0 + 8) * EMB + col) = v1;
        }
    }
}

// ---------------- BD = (Q + r_r_bias) @ R^T, stored pre-shifted ----------------
__global__ __launch_bounds__(256) void bd_gemm(const float* __restrict__ rrb)
{
    const int pt = blockIdx.x, it = blockIdx.y, bh = blockIdx.z;
    const int i0 = it * 64, p0 = pt * 64;
    if (i0 + p0 + 126 < QL - 1) return;
    const int b = bh >> 4, h = bh & 15;

    __shared__ float Qs[64 * 65];
    __shared__ float Rs[64 * 65];
    const int tid = threadIdx.x;

#pragma unroll
    for (int u = 0; u < 4; u++) {
        int f4 = tid + 256 * u;
        int rw = f4 >> 4;
        int d4 = (f4 & 15) << 2;
        float4 q = *(const float4*)&g_Q[(((size_t)b * QL + i0 + rw) * NH + h) * DH + d4];
        float4 bi = *(const float4*)&rrb[h * DH + d4];
        Qs[rw * 65 + d4 + 0] = q.x + bi.x;
        Qs[rw * 65 + d4 + 1] = q.y + bi.y;
        Qs[rw * 65 + d4 + 2] = q.z + bi.z;
        Qs[rw * 65 + d4 + 3] = q.w + bi.w;
        float4 rv = *(const float4*)&g_R[((size_t)(p0 + rw) * NH + h) * DH + d4];
        Rs[rw * 65 + d4 + 0] = rv.x;
        Rs[rw * 65 + d4 + 1] = rv.y;
        Rs[rw * 65 + d4 + 2] = rv.z;
        Rs[rw * 65 + d4 + 3] = rv.w;
    }
    __syncthreads();

    const int tx = tid & 15, ty = tid >> 4;
    float acc[4][4];
#pragma unroll
    for (int r = 0; r < 4; r++)
#pragma unroll
        for (int c = 0; c < 4; c++) acc[r][c] = 0.f;

#pragma unroll 8
    for (int d = 0; d < 64; d++) {
        float a[4], bvv[4];
#pragma unroll
        for (int r = 0; r < 4; r++) a[r] = Qs[(ty * 4 + r) * 65 + d];
#pragma unroll
        for (int c = 0; c < 4; c++) bvv[c] = Rs[(tx * 4 + c) * 65 + d];
#pragma unroll
        for (int r = 0; r < 4; r++)
#pragma unroll
            for (int c = 0; c < 4; c++) acc[r][c] += a[r] * bvv[c];
    }

    float* bdb = g_BD + (size_t)(b * NH + h) * QL * KLEN;
#pragma unroll
    for (int r = 0; r < 4; r++) {
        int gi = i0 + ty * 4 + r;
#pragma unroll
        for (int c = 0; c < 4; c++) {
            int gp = p0 + tx * 4 + c;
            int j = gp - (QL - 1) + gi;
            if (j >= 0) bdb[(size_t)gi * KLEN + j] = acc[r][c];
        }
    }
}

// ---------------- flash attention (fp32, q-tile 64, k-tile 64) ----------------
__global__ __launch_bounds__(256) void flash_kernel(const float* __restrict__ rwb)
{
    extern __shared__ float smf[];
    float* Qw = smf;
    float* Ks = smf + 64 * 65;
    float* Vs = smf + 2 * 64 * 65;
    float* Ps = smf + 3 * 64 * 65;

    const int qt = blockIdx.x, h = blockIdx.y, b = blockIdx.z;
    const int qi0 = qt * 64;
    const int tid = threadIdx.x, tx = tid & 15, ty = tid >> 4;

#pragma unroll
    for (int u = 0; u < 4; u++) {
        int f4 = tid + 256 * u;
        int rw = f4 >> 4, d4 = (f4 & 15) << 2;
        float4 q = *(const float4*)&g_Q[(((size_t)b * QL + qi0 + rw) * NH + h) * DH + d4];
        float4 bi = *(const float4*)&rwb[h * DH + d4];
        Qw[rw * 65 + d4 + 0] = q.x + bi.x;
        Qw[rw * 65 + d4 + 1] = q.y + bi.y;
        Qw[rw * 65 + d4 + 2] = q.z + bi.z;
        Qw[rw * 65 + d4 + 3] = q.w + bi.w;
    }

    float o[4][4];
    float mr[4], lr[4];
#pragma unroll
    for (int r = 0; r < 4; r++) {
        mr[r] = -1e30f; lr[r] = 0.f;
#pragma unroll
        for (int c = 0; c < 4; c++) o[r][c] = 0.f;
    }

    const float* bdb = g_BD + (size_t)(b * NH + h) * QL * KLEN;
    const float LOG2E = 1.4426950408889634f;
    const float sc = 0.03125f;

    const int nkt = qt + 17;
    for (int kt = 0; kt < nkt; kt++) {
        const int kj0 = kt * 64;
        __syncthreads();
#pragma unroll
        for (int u = 0; u < 4; u++) {
            int f4 = tid + 256 * u;
            int rw = f4 >> 4, d4 = (f4 & 15) << 2;
            size_t go = (((size_t)b * KLEN + kj0 + rw) * NH + h) * DH + d4;
            float4 kv = *(const float4*)&g_K[go];
            Ks[rw * 65 + d4 + 0] = kv.x;
            Ks[rw * 65 + d4 + 1] = kv.y;
            Ks[rw * 65 + d4 + 2] = kv.z;
            Ks[rw * 65 + d4 + 3] = kv.w;
            float4 vv = *(const float4*)&g_V[go];
            Vs[rw * 65 + d4 + 0] = vv.x;
            Vs[rw * 65 + d4 + 1] = vv.y;
            Vs[rw * 65 + d4 + 2] = vv.z;
            Vs[rw * 65 + d4 + 3] = vv.w;
        }
        __syncthreads();

        float s[4][4];
#pragma unroll
        for (int r = 0; r < 4; r++)
#pragma unroll
            for (int c = 0; c < 4; c++) s[r][c] = 0.f;

#pragma unroll 8
        for (int d = 0; d < 64; d++) {
            float a[4], kk[4];
#pragma unroll
            for (int r = 0; r < 4; r++) a[r] = Qw[(ty * 4 + r) * 65 + d];
#pragma unroll
            for (int c = 0; c < 4; c++) kk[c] = Ks[(tx * 4 + c) * 65 + d];
#pragma unroll
            for (int r = 0; r < 4; r++)
#pragma unroll
                for (int c = 0; c < 4; c++) s[r][c] += a[r] * kk[c];
        }

#pragma unroll
        for (int r = 0; r < 4; r++) {
            int gi = qi0 + ty * 4 + r;
            float4 bd = *(const float4*)&bdb[(size_t)gi * KLEN + kj0 + tx * 4];
            float bda[4] = {bd.x, bd.y, bd.z, bd.w};
            int jlim = gi + ML - kj0;
#pragma unroll
            for (int c = 0; c < 4; c++) {
                int jl = tx * 4 + c;
                s[r][c] = (jl <= jlim) ? (s[r][c] + bda[c]) * sc : -1e30f;
            }
        }

#pragma unroll
        for (int r = 0; r < 4; r++) {
            float mx = fmaxf(fmaxf(s[r][0], s[r][1]), fmaxf(s[r][2], s[r][3]));
#pragma unroll
            for (int w = 1; w < 16; w <<= 1)
                mx = fmaxf(mx, __shfl_xor_sync(0xffffffff, mx, w));
            float mnew = fmaxf(mr[r], mx);
            float scal = exp2f((mr[r] - mnew) * LOG2E);
            mr[r] = mnew;
            lr[r] *= scal;
#pragma unroll
            for (int c = 0; c < 4; c++) o[r][c] *= scal;
            float ps = 0.f;
#pragma unroll
            for (int c = 0; c < 4; c++) {
                float p = exp2f((s[r][c] - mnew) * LOG2E);
                Ps[(ty * 4 + r) * 65 + tx * 4 + c] = p;
                ps += p;
            }
#pragma unroll
            for (int w = 1; w < 16; w <<= 1)
                ps += __shfl_xor_sync(0xffffffff, ps, w);
            lr[r] += ps;
        }
        __syncthreads();

#pragma unroll 8
        for (int j = 0; j < 64; j++) {
            float pv[4], vv[4];
#pragma unroll
            for (int r = 0; r < 4; r++) pv[r] = Ps[(ty * 4 + r) * 65 + j];
#pragma unroll
            for (int c = 0; c < 4; c++) vv[c] = Vs[j * 65 + tx * 4 + c];
#pragma unroll
            for (int r = 0; r < 4; r++)
#pragma unroll
                for (int c = 0; c < 4; c++) o[r][c] += pv[r] * vv[c];
        }
    }

    // epilogue: round to tf32 so the Wo GEMM's raw-bit MMA read is exact
#pragma unroll
    for (int r = 0; r < 4; r++) {
        int gi = qi0 + ty * 4 + r;
        float inv = 1.0f / lr[r];
        float4 ov;
        ov.x = rna_tf32(o[r][0] * inv);
        ov.y = rna_tf32(o[r][1] * inv);
        ov.z = rna_tf32(o[r][2] * inv);
        ov.w = rna_tf32(o[r][3] * inv);
        *(float4*)&g_AO[((size_t)b * QL + gi) * EMB + h * DH + tx * 4] = ov;
    }
}

// ---------------- layernorm over last dim (1024), eps=1e-3 ----------------
__global__ __launch_bounds__(256) void ln_kernel(
    const float* __restrict__ gamma, const float* __restrict__ beta,
    float* __restrict__ out)
{
    const int row = blockIdx.x;
    const int tid = threadIdx.x;
    const float* x = g_X + (size_t)row * EMB;
    float4 v = ((const float4*)x)[tid];
    float s = v.x + v.y + v.z + v.w;
    float s2 = v.x * v.x + v.y * v.y + v.z * v.z + v.w * v.w;
#pragma unroll
    for (int w = 1; w < 32; w <<= 1) {
        s += __shfl_xor_sync(0xffffffff, s, w);
        s2 += __shfl_xor_sync(0xffffffff, s2, w);
    }
    __shared__ float sh[16];
    __shared__ float red[2];
    int wid = tid >> 5, lid = tid & 31;
    if (lid == 0) { sh[wid] = s; sh[wid + 8] = s2; }
    __syncthreads();
    if (tid == 0) {
        float ts = 0.f, ts2 = 0.f;
#pragma unroll
        for (int i = 0; i < 8; i++) { ts += sh[i]; ts2 += sh[i + 8]; }
        red[0] = ts; red[1] = ts2;
    }
    __syncthreads();
    float mean = red[0] * (1.0f / EMB);
    float var = red[1] * (1.0f / EMB) - mean * mean;
    float rs = rsqrtf(var + 1e-3f);
    float4 g = ((const float4*)gamma)[tid];
    float4 bt = ((const float4*)beta)[tid];
    float4 ov;
    ov.x = (v.x - mean) * rs * g.x + bt.x;
    ov.y = (v.y - mean) * rs * g.y + bt.y;
    ov.z = (v.z - mean) * rs * g.z + bt.z;
    ov.w = (v.w - mean) * rs * g.w + bt.w;
    ((float4*)(out + (size_t)row * EMB))[tid] = ov;
}

// ---------------- launch ----------------
extern "C" void kernel_launch(void* const* d_in, const int* in_sizes, int n_in,
                              void* d_out, int out_size)
{
    const float* w      = (const float*)d_in[0];
    const float* r      = (const float*)d_in[1];
    const float* rwb    = (const float*)d_in[3];
    const float* rrb    = (const float*)d_in[4];
    const float* member = (const float*)d_in[5];
    const float* Wq     = (const float*)d_in[6];
    const float* Wk     = (const float*)d_in[7];
    const float* Wv     = (const float*)d_in[8];
    const float* Wr     = (const float*)d_in[9];
    const float* Wo     = (const float*)d_in[10];
    const float* gamma  = (const float*)d_in[11];
    const float* beta   = (const float*)d_in[12];
    float* out = (float*)d_out;

    float *gQ, *gK, *gV, *gR, *gAO, *gX, *gWT, *gcat, *grR;
    cudaGetSymbolAddress((void**)&gQ, g_Q);
    cudaGetSymbolAddress((void**)&gK, g_K);
    cudaGetSymbolAddress((void**)&gV, g_V);
    cudaGetSymbolAddress((void**)&gR, g_R);
    cudaGetSymbolAddress((void**)&gAO, g_AO);
    cudaGetSymbolAddress((void**)&gX, g_X);
    cudaGetSymbolAddress((void**)&gWT, g_WT);
    cudaGetSymbolAddress((void**)&gcat, g_cat);
    cudaGetSymbolAddress((void**)&grR, g_rR);

    dim3 blk(256);

    // 0) round inputs to tf32 + transpose/round weights
    prep_round<<<6144, blk>>>(w, member, r);
    transposeW<<<dim3(32, 32, 5), blk>>>(Wq, Wk, Wv, Wr, Wo);

    cudaFuncSetAttribute(mma_gemm, cudaFuncAttributeMaxDynamicSharedMemorySize, SMEM_GEMM);

    // 1) projections on tensor cores (tf32 mma.sync)
    mma_gemm<<<dim3(8, 16), blk, SMEM_GEMM>>>(gcat, gWT + 0ull * (1 << 20), gQ, nullptr, 1);
    mma_gemm<<<dim3(8, 32), blk, SMEM_GEMM>>>(gcat, gWT + 1ull * (1 << 20), gK, nullptr, 0);
    mma_gemm<<<dim3(8, 32), blk, SMEM_GEMM>>>(gcat, gWT + 2ull * (1 << 20), gV, nullptr, 0);
    mma_gemm<<<dim3(8, 16), blk, SMEM_GEMM>>>(grR, gWT + 3ull * (1 << 20), gR, nullptr, 0);

    // 2) BD with fused rel_shift
    bd_gemm<<<dim3(32, 16, 32), blk>>>(rrb);

    // 3) flash attention
    int smem = 4 * 64 * 65 * sizeof(float);
    cudaFuncSetAttribute(flash_kernel, cudaFuncAttributeMaxDynamicSharedMemorySize, smem);
    flash_kernel<<<dim3(16, NH, BB), blk, smem>>>(rwb);

    // 4) output projection + residual
    mma_gemm<<<dim3(8, 16), blk, SMEM_GEMM>>>(gAO, gWT + 4ull * (1 << 20), gX, w, 0);

    // 5) layernorm
    ln_kernel<<<BB * QL, blk>>>(gamma, beta, out);
}

// round 4
// speedup vs baseline: 1.7181x; 1.7181x over previous
#include <cuda_runtime.h>
#include <cuda_bf16.h>
#include <cstdint>

#define BB 2
#define QL 1024
#define ML 1024
#define KLEN 2048
#define EMB 1024
#define NH 16
#define DH 64

// ---------------- scratch (static device, allocation-free) ----------------
__device__ float g_Q[BB * QL * EMB];               // [b,q,h,d]
__device__ float g_K[BB * KLEN * EMB];             // [b,k,h,d]
__device__ float g_V[BB * KLEN * EMB];             // [b,k,h,d]
__device__ float g_R[KLEN * EMB];                  // [p,h,d]
__device__ float g_BD[(size_t)BB * NH * QL * KLEN];// pre-shifted BD [b,h,q,j]
__device__ float g_AO[BB * QL * EMB];              // attention out
__device__ float g_X[BB * QL * EMB];               // pre-LN residual sum
__device__ __nv_bfloat16 g_WTb[5ull * 1024 * 1024];// transposed bf16 weights [n][k]

__device__ __forceinline__ uint32_t bf16x2_of(float lo, float hi) {
    uint32_t o;
    asm("cvt.rn.bf16x2.f32 %0, %1, %2;" : "=r"(o) : "f"(hi), "f"(lo));
    return o;
}

// ---------------- weight transpose + bf16 convert: g_WTb[z][n][k] = bf16(W_z[k][n]) ----------------
__global__ __launch_bounds__(256) void transposeW(
    const float* __restrict__ w0, const float* __restrict__ w1,
    const float* __restrict__ w2, const float* __restrict__ w3,
    const float* __restrict__ w4)
{
    __shared__ float t[32][33];
    const float* src;
    switch (blockIdx.z) {
        case 0: src = w0; break;
        case 1: src = w1; break;
        case 2: src = w2; break;
        case 3: src = w3; break;
        default: src = w4; break;
    }
    __nv_bfloat16* dst = g_WTb + ((size_t)blockIdx.z << 20);
    int tx = threadIdx.x & 31, ty = threadIdx.x >> 5;
    int x = blockIdx.x * 32 + tx;
    int y = blockIdx.y * 32 + ty;
#pragma unroll
    for (int j = 0; j < 32; j += 8)
        t[ty + j][tx] = src[(size_t)(y + j) * EMB + x];
    __syncthreads();
    x = blockIdx.y * 32 + tx;
    y = blockIdx.x * 32 + ty;
#pragma unroll
    for (int j = 0; j < 32; j += 8)
        dst[(size_t)(y + j) * EMB + x] = __float2bfloat16(t[tx][ty + j]);
}

// ---------------- bf16 mma.sync GEMM: C[M,1024] = A[M,1024] @ W (WTb=[n][k] bf16) ----------------
// mode 0: A rows direct. mode 1: rows gathered from cat(member=A, w=A2).
// Tile 128x128, 8 warps (4m x 2n), warp tile 32x64, K-chunk 32, double-buffered smem.
// smem: per buf A[128][40w] + B[128][40w] words; 2 bufs = 10240 words = 40KB.
__global__ __launch_bounds__(256) void mma_gemm(
    const float* __restrict__ A, const float* __restrict__ A2,
    const __nv_bfloat16* __restrict__ WT,
    float* __restrict__ C, const float* __restrict__ resid, int mode)
{
    __shared__ uint32_t smw[10240];
    const int tid = threadIdx.x;
    const int lane = tid & 31, wid = tid >> 5;
    const int m0 = blockIdx.y * 128, n0 = blockIdx.x * 128;
    const int wm = wid >> 1, wn = wid & 1;
    const int g = lane >> 2, tig = lane & 3;

    // ---- global load geometry ----
    // A: 4 u-steps: f4 = tid + 256u -> row = f4>>3 (0..127), c4 = f4&7 (float4 within 32k)
    const float* ap[4];
    uint32_t swA[4];
#pragma unroll
    for (int u = 0; u < 4; u++) {
        int f4 = tid + 256 * u;
        int rr = f4 >> 3, c4 = f4 & 7;
        int m = m0 + rr;
        const float* arow;
        if (mode == 0) {
            arow = A + (size_t)m * EMB;
        } else {
            int b = m >> 11, t = m & 2047;
            arow = (t < ML) ? (A + ((size_t)b * ML + t) * EMB)
                            : (A2 + ((size_t)b * QL + (t - ML)) * EMB);
        }
        ap[u] = arow + c4 * 4;
        swA[u] = (uint32_t)(rr * 20 + c4 * 2);
    }
    // B: 2 u-steps: f16 = tid + 256u -> row = f16>>2 (0..127), c16 = f16&3 (16B chunk)
    const __nv_bfloat16* bp[2];
    uint32_t swB[2];
#pragma unroll
    for (int v = 0; v < 2; v++) {
        int f16 = tid + 256 * v;
        int rr = f16 >> 2, c16 = f16 & 3;
        bp[v] = WT + (size_t)(n0 + rr) * EMB + c16 * 8;
        swB[v] = (uint32_t)(rr * 20 + c16 * 4);
    }

    float4 ra[4];
    uint4 rb[2];
#define LDGC(k0) do { \
        _Pragma("unroll") for (int u = 0; u < 4; u++) ra[u] = *(const float4*)(ap[u] + (k0)); \
        _Pragma("unroll") for (int v = 0; v < 2; v++) rb[v] = *(const uint4*)(bp[v] + (k0)); \
    } while (0)

    float c[2][8][4];
#pragma unroll
    for (int mf = 0; mf < 2; mf++)
#pragma unroll
        for (int nf = 0; nf < 8; nf++)
#pragma unroll
            for (int e = 0; e < 4; e++) c[mf][nf][e] = 0.f;

    LDGC(0);

    for (int it = 0; it < 32; it++) {
        const int buf = it & 1;
        uint32_t* Aw = smw + buf * 5120;
        uint32_t* Bw = Aw + 2560;
#pragma unroll
        for (int u = 0; u < 4; u++) {
            Aw[swA[u]]     = bf16x2_of(ra[u].x, ra[u].y);
            Aw[swA[u] + 1] = bf16x2_of(ra[u].z, ra[u].w);
        }
#pragma unroll
        for (int v = 0; v < 2; v++)
            *(uint4*)&Bw[swB[v]] = rb[v];
        __syncthreads();

        if (it + 1 < 32) LDGC((it + 1) * 32);

        const uint32_t* Awr = Aw + (wm * 32) * 20;
        const uint32_t* Bwr = Bw + (wn * 64) * 20;
#pragma unroll
        for (int ks = 0; ks < 2; ks++) {
            uint32_t a[2][4];
#pragma unroll
            for (int mf = 0; mf < 2; mf++) {
                int idx = (mf * 16 + g) * 20 + ks * 8 + tig;
                a[mf][0] = Awr[idx];
                a[mf][1] = Awr[idx + 160];
                a[mf][2] = Awr[idx + 4];
                a[mf][3] = Awr[idx + 164];
            }
#pragma unroll
            for (int nf = 0; nf < 8; nf++) {
                int bidx = (nf * 8 + g) * 20 + ks * 8 + tig;
                uint32_t b0 = Bwr[bidx];
                uint32_t b1 = Bwr[bidx + 4];
#pragma unroll
                for (int mf = 0; mf < 2; mf++) {
                    asm volatile(
                        "mma.sync.aligned.m16n8k16.row.col.f32.bf16.bf16.f32 "
                        "{%0,%1,%2,%3}, {%4,%5,%6,%7}, {%8,%9}, {%0,%1,%2,%3};"
                        : "+f"(c[mf][nf][0]), "+f"(c[mf][nf][1]),
                          "+f"(c[mf][nf][2]), "+f"(c[mf][nf][3])
                        : "r"(a[mf][0]), "r"(a[mf][1]), "r"(a[mf][2]), "r"(a[mf][3]),
                          "r"(b0), "r"(b1));
                }
            }
        }
        __syncthreads();
    }

    // epilogue: rows m0+wm*32+mf*16+g(+8), cols n0+wn*64+nf*8+2*tig(+1)
#pragma unroll
    for (int mf = 0; mf < 2; mf++) {
        int r0 = m0 + wm * 32 + mf * 16 + g;
#pragma unroll
        for (int nf = 0; nf < 8; nf++) {
            int col = n0 + wn * 64 + nf * 8 + tig * 2;
            float2 v0 = make_float2(c[mf][nf][0], c[mf][nf][1]);
            float2 v1 = make_float2(c[mf][nf][2], c[mf][nf][3]);
            if (resid) {
                float2 a0 = *(const float2*)(resid + (size_t)r0 * EMB + col);
                float2 a1 = *(const float2*)(resid + (size_t)(r0 + 8) * EMB + col);
                v0.x += a0.x; v0.y += a0.y;
                v1.x += a1.x; v1.y += a1.y;
            }
            *(float2*)(C + (size_t)r0 * EMB + col) = v0;
            *(float2*)(C + (size_t)(r0 + 8) * EMB + col) = v1;
        }
    }
}

// ---------------- BD = (Q + r_r_bias) @ R^T, stored pre-shifted ----------------
__global__ __launch_bounds__(256) void bd_gemm(const float* __restrict__ rrb)
{
    const int pt = blockIdx.x, it = blockIdx.y, bh = blockIdx.z;
    const int i0 = it * 64, p0 = pt * 64;
    if (i0 + p0 + 126 < QL - 1) return;
    const int b = bh >> 4, h = bh & 15;

    __shared__ float Qs[64 * 65];
    __shared__ float Rs[64 * 65];
    const int tid = threadIdx.x;

#pragma unroll
    for (int u = 0; u < 4; u++) {
        int f4 = tid + 256 * u;
        int rw = f4 >> 4;
        int d4 = (f4 & 15) << 2;
        float4 q = *(const float4*)&g_Q[(((size_t)b * QL + i0 + rw) * NH + h) * DH + d4];
        float4 bi = *(const float4*)&rrb[h * DH + d4];
        Qs[rw * 65 + d4 + 0] = q.x + bi.x;
        Qs[rw * 65 + d4 + 1] = q.y + bi.y;
        Qs[rw * 65 + d4 + 2] = q.z + bi.z;
        Qs[rw * 65 + d4 + 3] = q.w + bi.w;
        float4 rv = *(const float4*)&g_R[((size_t)(p0 + rw) * NH + h) * DH + d4];
        Rs[rw * 65 + d4 + 0] = rv.x;
        Rs[rw * 65 + d4 + 1] = rv.y;
        Rs[rw * 65 + d4 + 2] = rv.z;
        Rs[rw * 65 + d4 + 3] = rv.w;
    }
    __syncthreads();

    const int tx = tid & 15, ty = tid >> 4;
    float acc[4][4];
#pragma unroll
    for (int r = 0; r < 4; r++)
#pragma unroll
        for (int c = 0; c < 4; c++) acc[r][c] = 0.f;

#pragma unroll 8
    for (int d = 0; d < 64; d++) {
        float a[4], bvv[4];
#pragma unroll
        for (int r = 0; r < 4; r++) a[r] = Qs[(ty * 4 + r) * 65 + d];
#pragma unroll
        for (int c = 0; c < 4; c++) bvv[c] = Rs[(tx * 4 + c) * 65 + d];
#pragma unroll
        for (int r = 0; r < 4; r++)
#pragma unroll
            for (int c = 0; c < 4; c++) acc[r][c] += a[r] * bvv[c];
    }

    float* bdb = g_BD + (size_t)(b * NH + h) * QL * KLEN;
#pragma unroll
    for (int r = 0; r < 4; r++) {
        int gi = i0 + ty * 4 + r;
#pragma unroll
        for (int c = 0; c < 4; c++) {
            int gp = p0 + tx * 4 + c;
            int j = gp - (QL - 1) + gi;
            if (j >= 0) bdb[(size_t)gi * KLEN + j] = acc[r][c];
        }
    }
}

// ---------------- flash attention (fp32, q-tile 64, k-tile 64) ----------------
__global__ __launch_bounds__(256) void flash_kernel(const float* __restrict__ rwb)
{
    extern __shared__ float smf[];
    float* Qw = smf;
    float* Ks = smf + 64 * 65;
    float* Vs = smf + 2 * 64 * 65;
    float* Ps = smf + 3 * 64 * 65;

    const int qt = blockIdx.x, h = blockIdx.y, b = blockIdx.z;
    const int qi0 = qt * 64;
    const int tid = threadIdx.x, tx = tid & 15, ty = tid >> 4;

#pragma unroll
    for (int u = 0; u < 4; u++) {
        int f4 = tid + 256 * u;
        int rw = f4 >> 4, d4 = (f4 & 15) << 2;
        float4 q = *(const float4*)&g_Q[(((size_t)b * QL + qi0 + rw) * NH + h) * DH + d4];
        float4 bi = *(const float4*)&rwb[h * DH + d4];
        Qw[rw * 65 + d4 + 0] = q.x + bi.x;
        Qw[rw * 65 + d4 + 1] = q.y + bi.y;
        Qw[rw * 65 + d4 + 2] = q.z + bi.z;
        Qw[rw * 65 + d4 + 3] = q.w + bi.w;
    }

    float o[4][4];
    float mr[4], lr[4];
#pragma unroll
    for (int r = 0; r < 4; r++) {
        mr[r] = -1e30f; lr[r] = 0.f;
#pragma unroll
        for (int c = 0; c < 4; c++) o[r][c] = 0.f;
    }

    const float* bdb = g_BD + (size_t)(b * NH + h) * QL * KLEN;
    const float LOG2E = 1.4426950408889634f;
    const float sc = 0.03125f;

    const int nkt = qt + 17;
    for (int kt = 0; kt < nkt; kt++) {
        const int kj0 = kt * 64;
        __syncthreads();
#pragma unroll
        for (int u = 0; u < 4; u++) {
            int f4 = tid + 256 * u;
            int rw = f4 >> 4, d4 = (f4 & 15) << 2;
            size_t go = (((size_t)b * KLEN + kj0 + rw) * NH + h) * DH + d4;
            float4 kv = *(const float4*)&g_K[go];
            Ks[rw * 65 + d4 + 0] = kv.x;
            Ks[rw * 65 + d4 + 1] = kv.y;
            Ks[rw * 65 + d4 + 2] = kv.z;
            Ks[rw * 65 + d4 + 3] = kv.w;
            float4 vv = *(const float4*)&g_V[go];
            Vs[rw * 65 + d4 + 0] = vv.x;
            Vs[rw * 65 + d4 + 1] = vv.y;
            Vs[rw * 65 + d4 + 2] = vv.z;
            Vs[rw * 65 + d4 + 3] = vv.w;
        }
        __syncthreads();

        float s[4][4];
#pragma unroll
        for (int r = 0; r < 4; r++)
#pragma unroll
            for (int c = 0; c < 4; c++) s[r][c] = 0.f;

#pragma unroll 8
        for (int d = 0; d < 64; d++) {
            float a[4], kk[4];
#pragma unroll
            for (int r = 0; r < 4; r++) a[r] = Qw[(ty * 4 + r) * 65 + d];
#pragma unroll
            for (int c = 0; c < 4; c++) kk[c] = Ks[(tx * 4 + c) * 65 + d];
#pragma unroll
            for (int r = 0; r < 4; r++)
#pragma unroll
                for (int c = 0; c < 4; c++) s[r][c] += a[r] * kk[c];
        }

#pragma unroll
        for (int r = 0; r < 4; r++) {
            int gi = qi0 + ty * 4 + r;
            float4 bd = *(const float4*)&bdb[(size_t)gi * KLEN + kj0 + tx * 4];
            float bda[4] = {bd.x, bd.y, bd.z, bd.w};
            int jlim = gi + ML - kj0;
#pragma unroll
            for (int c = 0; c < 4; c++) {
                int jl = tx * 4 + c;
                s[r][c] = (jl <= jlim) ? (s[r][c] + bda[c]) * sc : -1e30f;
            }
        }

#pragma unroll
        for (int r = 0; r < 4; r++) {
            float mx = fmaxf(fmaxf(s[r][0], s[r][1]), fmaxf(s[r][2], s[r][3]));
#pragma unroll
            for (int w = 1; w < 16; w <<= 1)
                mx = fmaxf(mx, __shfl_xor_sync(0xffffffff, mx, w));
            float mnew = fmaxf(mr[r], mx);
            float scal = exp2f((mr[r] - mnew) * LOG2E);
            mr[r] = mnew;
            lr[r] *= scal;
#pragma unroll
            for (int c = 0; c < 4; c++) o[r][c] *= scal;
            float ps = 0.f;
#pragma unroll
            for (int c = 0; c < 4; c++) {
                float p = exp2f((s[r][c] - mnew) * LOG2E);
                Ps[(ty * 4 + r) * 65 + tx * 4 + c] = p;
                ps += p;
            }
#pragma unroll
            for (int w = 1; w < 16; w <<= 1)
                ps += __shfl_xor_sync(0xffffffff, ps, w);
            lr[r] += ps;
        }
        __syncthreads();

#pragma unroll 8
        for (int j = 0; j < 64; j++) {
            float pv[4], vv[4];
#pragma unroll
            for (int r = 0; r < 4; r++) pv[r] = Ps[(ty * 4 + r) * 65 + j];
#pragma unroll
            for (int c = 0; c < 4; c++) vv[c] = Vs[j * 65 + tx * 4 + c];
#pragma unroll
            for (int r = 0; r < 4; r++)
#pragma unroll
                for (int c = 0; c < 4; c++) o[r][c] += pv[r] * vv[c];
        }
    }

#pragma unroll
    for (int r = 0; r < 4; r++) {
        int gi = qi0 + ty * 4 + r;
        float inv = 1.0f / lr[r];
        float4 ov;
        ov.x = o[r][0] * inv;
        ov.y = o[r][1] * inv;
        ov.z = o[r][2] * inv;
        ov.w = o[r][3] * inv;
        *(float4*)&g_AO[((size_t)b * QL + gi) * EMB + h * DH + tx * 4] = ov;
    }
}

// ---------------- layernorm over last dim (1024), eps=1e-3 ----------------
__global__ __launch_bounds__(256) void ln_kernel(
    const float* __restrict__ gamma, const float* __restrict__ beta,
    float* __restrict__ out)
{
    const int row = blockIdx.x;
    const int tid = threadIdx.x;
    const float* x = g_X + (size_t)row * EMB;
    float4 v = ((const float4*)x)[tid];
    float s = v.x + v.y + v.z + v.w;
    float s2 = v.x * v.x + v.y * v.y + v.z * v.z + v.w * v.w;
#pragma unroll
    for (int w = 1; w < 32; w <<= 1) {
        s += __shfl_xor_sync(0xffffffff, s, w);
        s2 += __shfl_xor_sync(0xffffffff, s2, w);
    }
    __shared__ float sh[16];
    __shared__ float red[2];
    int wid = tid >> 5, lid = tid & 31;
    if (lid == 0) { sh[wid] = s; sh[wid + 8] = s2; }
    __syncthreads();
    if (tid == 0) {
        float ts = 0.f, ts2 = 0.f;
#pragma unroll
        for (int i = 0; i < 8; i++) { ts += sh[i]; ts2 += sh[i + 8]; }
        red[0] = ts; red[1] = ts2;
    }
    __syncthreads();
    float mean = red[0] * (1.0f / EMB);
    float var = red[1] * (1.0f / EMB) - mean * mean;
    float rs = rsqrtf(var + 1e-3f);
    float4 g = ((const float4*)gamma)[tid];
    float4 bt = ((const float4*)beta)[tid];
    float4 ov;
    ov.x = (v.x - mean) * rs * g.x + bt.x;
    ov.y = (v.y - mean) * rs * g.y + bt.y;
    ov.z = (v.z - mean) * rs * g.z + bt.z;
    ov.w = (v.w - mean) * rs * g.w + bt.w;
    ((float4*)(out + (size_t)row * EMB))[tid] = ov;
}

// ---------------- launch ----------------
extern "C" void kernel_launch(void* const* d_in, const int* in_sizes, int n_in,
                              void* d_out, int out_size)
{
    const float* w      = (const float*)d_in[0];
    const float* r      = (const float*)d_in[1];
    const float* rwb    = (const float*)d_in[3];
    const float* rrb    = (const float*)d_in[4];
    const float* member = (const float*)d_in[5];
    const float* Wq     = (const float*)d_in[6];
    const float* Wk     = (const float*)d_in[7];
    const float* Wv     = (const float*)d_in[8];
    const float* Wr     = (const float*)d_in[9];
    const float* Wo     = (const float*)d_in[10];
    const float* gamma  = (const float*)d_in[11];
    const float* beta   = (const float*)d_in[12];
    float* out = (float*)d_out;

    float *gQ, *gK, *gV, *gR, *gAO, *gX;
    __nv_bfloat16* gWT;
    cudaGetSymbolAddress((void**)&gQ, g_Q);
    cudaGetSymbolAddress((void**)&gK, g_K);
    cudaGetSymbolAddress((void**)&gV, g_V);
    cudaGetSymbolAddress((void**)&gR, g_R);
    cudaGetSymbolAddress((void**)&gAO, g_AO);
    cudaGetSymbolAddress((void**)&gX, g_X);
    cudaGetSymbolAddress((void**)&gWT, g_WTb);

    dim3 blk(256);

    // 0) transpose + convert weights to bf16 [n][k]
    transposeW<<<dim3(32, 32, 5), blk>>>(Wq, Wk, Wv, Wr, Wo);

    // 1) projections on bf16 tensor cores
    mma_gemm<<<dim3(8, 16), blk>>>(w, nullptr, gWT + 0ull * (1 << 20), gQ, nullptr, 0);
    mma_gemm<<<dim3(8, 32), blk>>>(member, w, gWT + 1ull * (1 << 20), gK, nullptr, 1);
    mma_gemm<<<dim3(8, 32), blk>>>(member, w, gWT + 2ull * (1 << 20), gV, nullptr, 1);
    mma_gemm<<<dim3(8, 16), blk>>>(r, nullptr, gWT + 3ull * (1 << 20), gR, nullptr, 0);

    // 2) BD with fused rel_shift
    bd_gemm<<<dim3(32, 16, 32), blk>>>(rrb);

    // 3) flash attention
    int smem = 4 * 64 * 65 * sizeof(float);
    cudaFuncSetAttribute(flash_kernel, cudaFuncAttributeMaxDynamicSharedMemorySize, smem);
    flash_kernel<<<dim3(16, NH, BB), blk, smem>>>(rwb);

    // 4) output projection + residual
    mma_gemm<<<dim3(8, 16), blk>>>(gAO, nullptr, gWT + 4ull * (1 << 20), gX, w, 0);

    // 5) layernorm
    ln_kernel<<<BB * QL, blk>>>(gamma, beta, out);
}

// round 5
// speedup vs baseline: 3.5623x; 2.0734x over previous
#include <cuda_runtime.h>
#include <cuda_bf16.h>
#include <cstdint>

#define BB 2
#define QL 1024
#define ML 1024
#define KLEN 2048
#define EMB 1024
#define NH 16
#define DH 64

// ---------------- scratch (static device, allocation-free) ----------------
__device__ float g_Q[BB * QL * EMB];               // [b,q,h,d]
__device__ float g_K[BB * KLEN * EMB];             // [b,k,h,d]
__device__ float g_V[BB * KLEN * EMB];             // [b,k,h,d]
__device__ float g_R[KLEN * EMB];                  // [p,h,d]
__device__ float g_BD[(size_t)BB * NH * QL * KLEN];// pre-shifted BD [b,h,q,j]
__device__ float g_AO[BB * QL * EMB];              // attention out
__device__ float g_X[BB * QL * EMB];               // pre-LN residual sum
__device__ __nv_bfloat16 g_WTb[5ull * 1024 * 1024];// transposed bf16 weights [n][k]

__device__ __forceinline__ uint32_t bf16x2_of(float lo, float hi) {
    uint32_t o;
    asm("cvt.rn.bf16x2.f32 %0, %1, %2;" : "=r"(o) : "f"(hi), "f"(lo));
    return o;
}
__device__ __forceinline__ float ex2f(float x) {
    float y;
    asm("ex2.approx.f32 %0, %1;" : "=f"(y) : "f"(x));
    return y;
}
#define MMA16816(C, A0, A1, A2, A3, B0, B1) \
    asm volatile("mma.sync.aligned.m16n8k16.row.col.f32.bf16.bf16.f32 " \
        "{%0,%1,%2,%3}, {%4,%5,%6,%7}, {%8,%9}, {%0,%1,%2,%3};" \
        : "+f"((C)[0]), "+f"((C)[1]), "+f"((C)[2]), "+f"((C)[3]) \
        : "r"(A0), "r"(A1), "r"(A2), "r"(A3), "r"(B0), "r"(B1))

// ---------------- weight transpose + bf16 convert ----------------
__global__ __launch_bounds__(256) void transposeW(
    const float* __restrict__ w0, const float* __restrict__ w1,
    const float* __restrict__ w2, const float* __restrict__ w3,
    const float* __restrict__ w4)
{
    __shared__ float t[32][33];
    const float* src;
    switch (blockIdx.z) {
        case 0: src = w0; break;
        case 1: src = w1; break;
        case 2: src = w2; break;
        case 3: src = w3; break;
        default: src = w4; break;
    }
    __nv_bfloat16* dst = g_WTb + ((size_t)blockIdx.z << 20);
    int tx = threadIdx.x & 31, ty = threadIdx.x >> 5;
    int x = blockIdx.x * 32 + tx;
    int y = blockIdx.y * 32 + ty;
#pragma unroll
    for (int j = 0; j < 32; j += 8)
        t[ty + j][tx] = src[(size_t)(y + j) * EMB + x];
    __syncthreads();
    x = blockIdx.y * 32 + tx;
    y = blockIdx.x * 32 + ty;
#pragma unroll
    for (int j = 0; j < 32; j += 8)
        dst[(size_t)(y + j) * EMB + x] = __float2bfloat16(t[tx][ty + j]);
}

// ---------------- bf16 mma GEMM: projections (unchanged from R4) ----------------
__global__ __launch_bounds__(256) void mma_gemm(
    const float* __restrict__ A, const float* __restrict__ A2,
    const __nv_bfloat16* __restrict__ WT,
    float* __restrict__ C, const float* __restrict__ resid, int mode)
{
    __shared__ uint32_t smw[10240];
    const int tid = threadIdx.x;
    const int lane = tid & 31, wid = tid >> 5;
    const int m0 = blockIdx.y * 128, n0 = blockIdx.x * 128;
    const int wm = wid >> 1, wn = wid & 1;
    const int g = lane >> 2, tig = lane & 3;

    const float* ap[4];
    uint32_t swA[4];
#pragma unroll
    for (int u = 0; u < 4; u++) {
        int f4 = tid + 256 * u;
        int rr = f4 >> 3, c4 = f4 & 7;
        int m = m0 + rr;
        const float* arow;
        if (mode == 0) {
            arow = A + (size_t)m * EMB;
        } else {
            int b = m >> 11, t = m & 2047;
            arow = (t < ML) ? (A + ((size_t)b * ML + t) * EMB)
                            : (A2 + ((size_t)b * QL + (t - ML)) * EMB);
        }
        ap[u] = arow + c4 * 4;
        swA[u] = (uint32_t)(rr * 20 + c4 * 2);
    }
    const __nv_bfloat16* bp[2];
    uint32_t swB[2];
#pragma unroll
    for (int v = 0; v < 2; v++) {
        int f16 = tid + 256 * v;
        int rr = f16 >> 2, c16 = f16 & 3;
        bp[v] = WT + (size_t)(n0 + rr) * EMB + c16 * 8;
        swB[v] = (uint32_t)(rr * 20 + c16 * 4);
    }

    float4 ra[4];
    uint4 rb[2];
#define LDGC(k0) do { \
        _Pragma("unroll") for (int u = 0; u < 4; u++) ra[u] = *(const float4*)(ap[u] + (k0)); \
        _Pragma("unroll") for (int v = 0; v < 2; v++) rb[v] = *(const uint4*)(bp[v] + (k0)); \
    } while (0)

    float c[2][8][4];
#pragma unroll
    for (int mf = 0; mf < 2; mf++)
#pragma unroll
        for (int nf = 0; nf < 8; nf++)
#pragma unroll
            for (int e = 0; e < 4; e++) c[mf][nf][e] = 0.f;

    LDGC(0);

    for (int it = 0; it < 32; it++) {
        const int buf = it & 1;
        uint32_t* Aw = smw + buf * 5120;
        uint32_t* Bw = Aw + 2560;
#pragma unroll
        for (int u = 0; u < 4; u++) {
            Aw[swA[u]]     = bf16x2_of(ra[u].x, ra[u].y);
            Aw[swA[u] + 1] = bf16x2_of(ra[u].z, ra[u].w);
        }
#pragma unroll
        for (int v = 0; v < 2; v++)
            *(uint4*)&Bw[swB[v]] = rb[v];
        __syncthreads();

        if (it + 1 < 32) LDGC((it + 1) * 32);

        const uint32_t* Awr = Aw + (wm * 32) * 20;
        const uint32_t* Bwr = Bw + (wn * 64) * 20;
#pragma unroll
        for (int ks = 0; ks < 2; ks++) {
            uint32_t a[2][4];
#pragma unroll
            for (int mf = 0; mf < 2; mf++) {
                int idx = (mf * 16 + g) * 20 + ks * 8 + tig;
                a[mf][0] = Awr[idx];
                a[mf][1] = Awr[idx + 160];
                a[mf][2] = Awr[idx + 4];
                a[mf][3] = Awr[idx + 164];
            }
#pragma unroll
            for (int nf = 0; nf < 8; nf++) {
                int bidx = (nf * 8 + g) * 20 + ks * 8 + tig;
                uint32_t b0 = Bwr[bidx];
                uint32_t b1 = Bwr[bidx + 4];
#pragma unroll
                for (int mf = 0; mf < 2; mf++)
                    MMA16816(c[mf][nf], a[mf][0], a[mf][1], a[mf][2], a[mf][3], b0, b1);
            }
        }
        __syncthreads();
    }

#pragma unroll
    for (int mf = 0; mf < 2; mf++) {
        int r0 = m0 + wm * 32 + mf * 16 + g;
#pragma unroll
        for (int nf = 0; nf < 8; nf++) {
            int col = n0 + wn * 64 + nf * 8 + tig * 2;
            float2 v0 = make_float2(c[mf][nf][0], c[mf][nf][1]);
            float2 v1 = make_float2(c[mf][nf][2], c[mf][nf][3]);
            if (resid) {
                float2 a0 = *(const float2*)(resid + (size_t)r0 * EMB + col);
                float2 a1 = *(const float2*)(resid + (size_t)(r0 + 8) * EMB + col);
                v0.x += a0.x; v0.y += a0.y;
                v1.x += a1.x; v1.y += a1.y;
            }
            *(float2*)(C + (size_t)r0 * EMB + col) = v0;
            *(float2*)(C + (size_t)(r0 + 8) * EMB + col) = v1;
        }
    }
}

// ---------------- BD via bf16 mma: pre-shifted band write ----------------
// CTA: 128 i-rows x 64 p-cols, 8 warps (16 rows each), k=d=64.
__global__ __launch_bounds__(256) void bd_mma(const float* __restrict__ rrb)
{
    const int pt = blockIdx.x, it = blockIdx.y, bh = blockIdx.z;
    const int i0 = it * 128, p0 = pt * 64;
    if (i0 + p0 < 833) return;  // whole tile maps to j < 0
    const int b = bh >> 4, h = bh & 15;

    __shared__ uint32_t sm[6912];      // Qs 128*36 + Rs 64*36
    uint32_t* Qs = sm;
    uint32_t* Rs = sm + 4608;
    const int tid = threadIdx.x, lane = tid & 31, wm = tid >> 5;
    const int g = lane >> 2, tig = lane & 3;

#pragma unroll
    for (int u = 0; u < 8; u++) {
        int f4 = tid + 256 * u;
        int row = f4 >> 4, d4 = (f4 & 15) << 2;
        float4 q = *(const float4*)&g_Q[(((size_t)b * QL + i0 + row) * NH + h) * DH + d4];
        float4 bi = *(const float4*)&rrb[h * DH + d4];
        Qs[row * 36 + (d4 >> 1)]     = bf16x2_of(q.x + bi.x, q.y + bi.y);
        Qs[row * 36 + (d4 >> 1) + 1] = bf16x2_of(q.z + bi.z, q.w + bi.w);
    }
#pragma unroll
    for (int u = 0; u < 4; u++) {
        int f4 = tid + 256 * u;
        int row = f4 >> 4, d4 = (f4 & 15) << 2;
        float4 rv = *(const float4*)&g_R[((size_t)(p0 + row) * NH + h) * DH + d4];
        Rs[row * 36 + (d4 >> 1)]     = bf16x2_of(rv.x, rv.y);
        Rs[row * 36 + (d4 >> 1) + 1] = bf16x2_of(rv.z, rv.w);
    }
    __syncthreads();

    float s[8][4];
#pragma unroll
    for (int nf = 0; nf < 8; nf++)
#pragma unroll
        for (int e = 0; e < 4; e++) s[nf][e] = 0.f;

#pragma unroll
    for (int ks = 0; ks < 4; ks++) {
        int ai = (wm * 16 + g) * 36 + ks * 8 + tig;
        uint32_t a0 = Qs[ai], a1 = Qs[ai + 288], a2 = Qs[ai + 4], a3 = Qs[ai + 292];
#pragma unroll
        for (int nf = 0; nf < 8; nf++) {
            int bi = (nf * 8 + g) * 36 + ks * 8 + tig;
            MMA16816(s[nf], a0, a1, a2, a3, Rs[bi], Rs[bi + 4]);
        }
    }

    float* bdb = g_BD + (size_t)(b * NH + h) * QL * KLEN;
#pragma unroll
    for (int e = 0; e < 2; e++) {
        int i = i0 + wm * 16 + g + 8 * e;
#pragma unroll
        for (int nf = 0; nf < 8; nf++) {
#pragma unroll
            for (int c = 0; c < 2; c++) {
                int p = p0 + nf * 8 + 2 * tig + c;
                int j = p - (QL - 1) + i;
                if (j >= 0) bdb[(size_t)i * KLEN + j] = s[nf][2 * e + c];
            }
        }
    }
}

// ---------------- flash attention, bf16 mma, q-tile 128 / k-tile 64 ----------------
__global__ __launch_bounds__(256) void flash_mma(const float* __restrict__ rwb)
{
    __shared__ uint32_t sm[9216];      // Qs 128*36 | Ks 64*36 | Vt 64*36
    uint32_t* Qs = sm;
    uint32_t* Ks = sm + 4608;
    uint32_t* Vt = sm + 6912;          // [d][kv] bf16, 72 halves per d-row
    __nv_bfloat16* Vh = (__nv_bfloat16*)Vt;

    const int qt = blockIdx.x, h = blockIdx.y, b = blockIdx.z;
    const int qi0 = qt * 128;
    const int tid = threadIdx.x, lane = tid & 31, wm = tid >> 5;
    const int g = lane >> 2, tig = lane & 3;

    // Q tile + content bias, bf16
#pragma unroll
    for (int u = 0; u < 8; u++) {
        int f4 = tid + 256 * u;
        int row = f4 >> 4, d4 = (f4 & 15) << 2;
        float4 q = *(const float4*)&g_Q[(((size_t)b * QL + qi0 + row) * NH + h) * DH + d4];
        float4 bi = *(const float4*)&rwb[h * DH + d4];
        Qs[row * 36 + (d4 >> 1)]     = bf16x2_of(q.x + bi.x, q.y + bi.y);
        Qs[row * 36 + (d4 >> 1) + 1] = bf16x2_of(q.z + bi.z, q.w + bi.w);
    }

    float o[8][4];
#pragma unroll
    for (int nf = 0; nf < 8; nf++)
#pragma unroll
        for (int e = 0; e < 4; e++) o[nf][e] = 0.f;
    float mr[2] = {-1e30f, -1e30f}, lr[2] = {0.f, 0.f};

    const float* bdb = g_BD + (size_t)(b * NH + h) * QL * KLEN;
    const float scl2 = 0.03125f * 1.4426950408889634f;   // (1/sqrt(1024)) * log2(e)

    const int nkt = 2 * qt + 18;
    for (int kt = 0; kt < nkt; kt++) {
        const int kj0 = kt * 64;
        __syncthreads();
#pragma unroll
        for (int u = 0; u < 4; u++) {
            int f4 = tid + 256 * u;
            int row = f4 >> 4, d4 = (f4 & 15) << 2;
            size_t go = (((size_t)b * KLEN + kj0 + row) * NH + h) * DH + d4;
            float4 kv = *(const float4*)&g_K[go];
            Ks[row * 36 + (d4 >> 1)]     = bf16x2_of(kv.x, kv.y);
            Ks[row * 36 + (d4 >> 1) + 1] = bf16x2_of(kv.z, kv.w);
            float4 vv = *(const float4*)&g_V[go];
            Vh[(d4 + 0) * 72 + row] = __float2bfloat16(vv.x);
            Vh[(d4 + 1) * 72 + row] = __float2bfloat16(vv.y);
            Vh[(d4 + 2) * 72 + row] = __float2bfloat16(vv.z);
            Vh[(d4 + 3) * 72 + row] = __float2bfloat16(vv.w);
        }
        __syncthreads();

        // S = Q @ K^T  (warp: 16 rows x 64 cols)
        float s[8][4];
#pragma unroll
        for (int nf = 0; nf < 8; nf++)
#pragma unroll
            for (int e = 0; e < 4; e++) s[nf][e] = 0.f;
#pragma unroll
        for (int ks = 0; ks < 4; ks++) {
            int ai = (wm * 16 + g) * 36 + ks * 8 + tig;
            uint32_t a0 = Qs[ai], a1 = Qs[ai + 288], a2 = Qs[ai + 4], a3 = Qs[ai + 292];
#pragma unroll
            for (int nf = 0; nf < 8; nf++) {
                int bi = (nf * 8 + g) * 36 + ks * 8 + tig;
                MMA16816(s[nf], a0, a1, a2, a3, Ks[bi], Ks[bi + 4]);
            }
        }

        // BD add + scale + mask + online softmax (warp-local, per row e)
#pragma unroll
        for (int e = 0; e < 2; e++) {
            int i = qi0 + wm * 16 + g + 8 * e;
            int jb = kj0 + 2 * tig;
            int jlim = i + ML;
            float mx = -1e30f;
#pragma unroll
            for (int nf = 0; nf < 8; nf++) {
                float2 bd = *(const float2*)&bdb[(size_t)i * KLEN + jb + nf * 8];
                int j0 = jb + nf * 8;
                float v0 = (j0 <= jlim)     ? (s[nf][2 * e]     + bd.x) * scl2 : -1e30f;
                float v1 = (j0 + 1 <= jlim) ? (s[nf][2 * e + 1] + bd.y) * scl2 : -1e30f;
                s[nf][2 * e] = v0;
                s[nf][2 * e + 1] = v1;
                mx = fmaxf(mx, fmaxf(v0, v1));
            }
            mx = fmaxf(mx, __shfl_xor_sync(0xffffffff, mx, 1));
            mx = fmaxf(mx, __shfl_xor_sync(0xffffffff, mx, 2));
            float mnew = fmaxf(mr[e], mx);
            float scal = ex2f(mr[e] - mnew);
            mr[e] = mnew;
            float ps = 0.f;
#pragma unroll
            for (int nf = 0; nf < 8; nf++) {
                float p0 = ex2f(s[nf][2 * e] - mnew);
                float p1 = ex2f(s[nf][2 * e + 1] - mnew);
                s[nf][2 * e] = p0;
                s[nf][2 * e + 1] = p1;
                ps += p0 + p1;
            }
            ps += __shfl_xor_sync(0xffffffff, ps, 1);
            ps += __shfl_xor_sync(0xffffffff, ps, 2);
            lr[e] = lr[e] * scal + ps;
#pragma unroll
            for (int nf = 0; nf < 8; nf++) {
                o[nf][2 * e] *= scal;
                o[nf][2 * e + 1] *= scal;
            }
        }

        // pack P fragments (C-layout == A-layout trick)
        uint32_t pa[4][4];
#pragma unroll
        for (int t = 0; t < 4; t++) {
            pa[t][0] = bf16x2_of(s[2 * t][0], s[2 * t][1]);
            pa[t][1] = bf16x2_of(s[2 * t][2], s[2 * t][3]);
            pa[t][2] = bf16x2_of(s[2 * t + 1][0], s[2 * t + 1][1]);
            pa[t][3] = bf16x2_of(s[2 * t + 1][2], s[2 * t + 1][3]);
        }

        // O += P @ V   (V^T in smem: Vt[d][kv])
#pragma unroll
        for (int t = 0; t < 4; t++) {
#pragma unroll
            for (int nf = 0; nf < 8; nf++) {
                int bi = (nf * 8 + g) * 36 + 8 * t + tig;
                MMA16816(o[nf], pa[t][0], pa[t][1], pa[t][2], pa[t][3], Vt[bi], Vt[bi + 4]);
            }
        }
    }

    // write O / l
#pragma unroll
    for (int e = 0; e < 2; e++) {
        int i = qi0 + wm * 16 + g + 8 * e;
        float inv = 1.0f / lr[e];
#pragma unroll
        for (int nf = 0; nf < 8; nf++) {
            float2 v = make_float2(o[nf][2 * e] * inv, o[nf][2 * e + 1] * inv);
            *(float2*)&g_AO[((size_t)b * QL + i) * EMB + h * DH + nf * 8 + 2 * tig] = v;
        }
    }
}

// ---------------- layernorm over last dim (1024), eps=1e-3 ----------------
__global__ __launch_bounds__(256) void ln_kernel(
    const float* __restrict__ gamma, const float* __restrict__ beta,
    float* __restrict__ out)
{
    const int row = blockIdx.x;
    const int tid = threadIdx.x;
    const float* x = g_X + (size_t)row * EMB;
    float4 v = ((const float4*)x)[tid];
    float s = v.x + v.y + v.z + v.w;
    float s2 = v.x * v.x + v.y * v.y + v.z * v.z + v.w * v.w;
#pragma unroll
    for (int w = 1; w < 32; w <<= 1) {
        s += __shfl_xor_sync(0xffffffff, s, w);
        s2 += __shfl_xor_sync(0xffffffff, s2, w);
    }
    __shared__ float sh[16];
    __shared__ float red[2];
    int wid = tid >> 5, lid = tid & 31;
    if (lid == 0) { sh[wid] = s; sh[wid + 8] = s2; }
    __syncthreads();
    if (tid == 0) {
        float ts = 0.f, ts2 = 0.f;
#pragma unroll
        for (int i = 0; i < 8; i++) { ts += sh[i]; ts2 += sh[i + 8]; }
        red[0] = ts; red[1] = ts2;
    }
    __syncthreads();
    float mean = red[0] * (1.0f / EMB);
    float var = red[1] * (1.0f / EMB) - mean * mean;
    float rs = rsqrtf(var + 1e-3f);
    float4 g = ((const float4*)gamma)[tid];
    float4 bt = ((const float4*)beta)[tid];
    float4 ov;
    ov.x = (v.x - mean) * rs * g.x + bt.x;
    ov.y = (v.y - mean) * rs * g.y + bt.y;
    ov.z = (v.z - mean) * rs * g.z + bt.z;
    ov.w = (v.w - mean) * rs * g.w + bt.w;
    ((float4*)(out + (size_t)row * EMB))[tid] = ov;
}

// ---------------- launch ----------------
extern "C" void kernel_launch(void* const* d_in, const int* in_sizes, int n_in,
                              void* d_out, int out_size)
{
    const float* w      = (const float*)d_in[0];
    const float* r      = (const float*)d_in[1];
    const float* rwb    = (const float*)d_in[3];
    const float* rrb    = (const float*)d_in[4];
    const float* member = (const float*)d_in[5];
    const float* Wq     = (const float*)d_in[6];
    const float* Wk     = (const float*)d_in[7];
    const float* Wv     = (const float*)d_in[8];
    const float* Wr     = (const float*)d_in[9];
    const float* Wo     = (const float*)d_in[10];
    const float* gamma  = (const float*)d_in[11];
    const float* beta   = (const float*)d_in[12];
    float* out = (float*)d_out;

    float *gQ, *gK, *gV, *gR, *gAO, *gX;
    __nv_bfloat16* gWT;
    cudaGetSymbolAddress((void**)&gQ, g_Q);
    cudaGetSymbolAddress((void**)&gK, g_K);
    cudaGetSymbolAddress((void**)&gV, g_V);
    cudaGetSymbolAddress((void**)&gR, g_R);
    cudaGetSymbolAddress((void**)&gAO, g_AO);
    cudaGetSymbolAddress((void**)&gX, g_X);
    cudaGetSymbolAddress((void**)&gWT, g_WTb);

    dim3 blk(256);

    // 0) transpose + convert weights to bf16 [n][k]
    transposeW<<<dim3(32, 32, 5), blk>>>(Wq, Wk, Wv, Wr, Wo);

    // 1) projections on bf16 tensor cores
    mma_gemm<<<dim3(8, 16), blk>>>(w, nullptr, gWT + 0ull * (1 << 20), gQ, nullptr, 0);
    mma_gemm<<<dim3(8, 32), blk>>>(member, w, gWT + 1ull * (1 << 20), gK, nullptr, 1);
    mma_gemm<<<dim3(8, 32), blk>>>(member, w, gWT + 2ull * (1 << 20), gV, nullptr, 1);
    mma_gemm<<<dim3(8, 16), blk>>>(r, nullptr, gWT + 3ull * (1 << 20), gR, nullptr, 0);

    // 2) BD with fused rel_shift (bf16 mma)
    bd_mma<<<dim3(32, 8, 32), blk>>>(rrb);

    // 3) flash attention (bf16 mma)
    flash_mma<<<dim3(8, NH, BB), blk>>>(rwb);

    // 4) output projection + residual
    mma_gemm<<<dim3(8, 16), blk>>>(gAO, nullptr, gWT + 4ull * (1 << 20), gX, w, 0);

    // 5) layernorm
    ln_kernel<<<BB * QL, blk>>>(gamma, beta, out);
}

// round 6
// speedup vs baseline: 3.7632x; 1.0564x over previous
#include <cuda_runtime.h>
#include <cuda_bf16.h>
#include <cstdint>

#define BB 2
#define QL 1024
#define ML 1024
#define KLEN 2048
#define EMB 1024
#define NH 16
#define DH 64

typedef __nv_bfloat16 bf16;
typedef __nv_bfloat162 bf162;

// ---------------- scratch (static device, allocation-free) ----------------
__device__ bf16 g_Qh[BB * QL * EMB];                 // [b*q][h*d] bf16
__device__ bf16 g_Kh[BB * KLEN * EMB];               // [b*k][h*d] bf16
__device__ bf16 g_Vh[BB * KLEN * EMB];               // [b*k][h*d] bf16
__device__ bf16 g_Rh[KLEN * EMB];                    // [p][h*d] bf16
__device__ bf16 g_BDh[(size_t)BB * NH * QL * KLEN];  // pre-shifted BD, bf16
__device__ float g_AO[BB * QL * EMB];                // attention out fp32
__device__ float g_X[BB * QL * EMB];                 // pre-LN residual sum
__device__ bf16 g_WTb[5ull * 1024 * 1024];           // transposed bf16 weights [n][k]

__device__ __forceinline__ uint32_t bf16x2_of(float lo, float hi) {
    uint32_t o;
    asm("cvt.rn.bf16x2.f32 %0, %1, %2;" : "=r"(o) : "f"(hi), "f"(lo));
    return o;
}
__device__ __forceinline__ float2 f2_of_bf16x2(uint32_t w) {
    bf162 t = *reinterpret_cast<bf162*>(&w);
    return __bfloat1622float2(t);
}
__device__ __forceinline__ float ex2f(float x) {
    float y;
    asm("ex2.approx.f32 %0, %1;" : "=f"(y) : "f"(x));
    return y;
}
#define MMA16816(C, A0, A1, A2, A3, B0, B1) \
    asm volatile("mma.sync.aligned.m16n8k16.row.col.f32.bf16.bf16.f32 " \
        "{%0,%1,%2,%3}, {%4,%5,%6,%7}, {%8,%9}, {%0,%1,%2,%3};" \
        : "+f"((C)[0]), "+f"((C)[1]), "+f"((C)[2]), "+f"((C)[3]) \
        : "r"(A0), "r"(A1), "r"(A2), "r"(A3), "r"(B0), "r"(B1))

// ---------------- weight transpose + bf16 convert ----------------
__global__ __launch_bounds__(256) void transposeW(
    const float* __restrict__ w0, const float* __restrict__ w1,
    const float* __restrict__ w2, const float* __restrict__ w3,
    const float* __restrict__ w4)
{
    __shared__ float t[32][33];
    const float* src;
    switch (blockIdx.z) {
        case 0: src = w0; break;
        case 1: src = w1; break;
        case 2: src = w2; break;
        case 3: src = w3; break;
        default: src = w4; break;
    }
    bf16* dst = g_WTb + ((size_t)blockIdx.z << 20);
    int tx = threadIdx.x & 31, ty = threadIdx.x >> 5;
    int x = blockIdx.x * 32 + tx;
    int y = blockIdx.y * 32 + ty;
#pragma unroll
    for (int j = 0; j < 32; j += 8)
        t[ty + j][tx] = src[(size_t)(y + j) * EMB + x];
    __syncthreads();
    x = blockIdx.y * 32 + tx;
    y = blockIdx.x * 32 + ty;
#pragma unroll
    for (int j = 0; j < 32; j += 8)
        dst[(size_t)(y + j) * EMB + x] = __float2bfloat16(t[tx][ty + j]);
}

// ---------------- bf16 mma GEMM ----------------
// A fp32 [M][1024] (mode 1: row gather from cat(member=A, w=A2)).
// WT bf16 [n][k], n may span up to 2048 (fused KV: n<1024 -> C0, else C1).
// OBF: bf16 output (no resid), else fp32 output (+optional resid).
// Tile 128x128, 8 warps (4m x 2n), K-chunk 32, double-buffered, 1 sync/iter.
template <bool OBF>
__global__ __launch_bounds__(256) void mma_gemm(
    const float* __restrict__ A, const float* __restrict__ A2,
    const bf16* __restrict__ WT,
    void* C0v, void* C1v, const float* __restrict__ resid, int mode)
{
    __shared__ uint32_t smw[10240];
    const int tid = threadIdx.x;
    const int lane = tid & 31, wid = tid >> 5;
    const int m0 = blockIdx.y * 128, n0 = blockIdx.x * 128;
    const int wm = wid >> 1, wn = wid & 1;
    const int g = lane >> 2, tig = lane & 3;

    const float* ap[4];
    uint32_t swA[4];
#pragma unroll
    for (int u = 0; u < 4; u++) {
        int f4 = tid + 256 * u;
        int rr = f4 >> 3, c4 = f4 & 7;
        int m = m0 + rr;
        const float* arow;
        if (mode == 0) {
            arow = A + (size_t)m * EMB;
        } else {
            int b = m >> 11, t = m & 2047;
            arow = (t < ML) ? (A + ((size_t)b * ML + t) * EMB)
                            : (A2 + ((size_t)b * QL + (t - ML)) * EMB);
        }
        ap[u] = arow + c4 * 4;
        swA[u] = (uint32_t)(rr * 20 + c4 * 2);
    }
    const bf16* bp[2];
    uint32_t swB[2];
#pragma unroll
    for (int v = 0; v < 2; v++) {
        int f16 = tid + 256 * v;
        int rr = f16 >> 2, c16 = f16 & 3;
        bp[v] = WT + (size_t)(n0 + rr) * EMB + c16 * 8;
        swB[v] = (uint32_t)(rr * 20 + c16 * 4);
    }

    float4 ra[4];
    uint4 rb[2];
#define LDGC(k0) do { \
        _Pragma("unroll") for (int u = 0; u < 4; u++) ra[u] = *(const float4*)(ap[u] + (k0)); \
        _Pragma("unroll") for (int v = 0; v < 2; v++) rb[v] = *(const uint4*)(bp[v] + (k0)); \
    } while (0)
#define STSC(buf) do { \
        uint32_t* Aw_ = smw + (buf) * 5120; \
        uint32_t* Bw_ = Aw_ + 2560; \
        _Pragma("unroll") for (int u = 0; u < 4; u++) { \
            Aw_[swA[u]]     = bf16x2_of(ra[u].x, ra[u].y); \
            Aw_[swA[u] + 1] = bf16x2_of(ra[u].z, ra[u].w); \
        } \
        _Pragma("unroll") for (int v = 0; v < 2; v++) \
            *(uint4*)&Bw_[swB[v]] = rb[v]; \
    } while (0)

    float c[2][8][4];
#pragma unroll
    for (int mf = 0; mf < 2; mf++)
#pragma unroll
        for (int nf = 0; nf < 8; nf++)
#pragma unroll
            for (int e = 0; e < 4; e++) c[mf][nf][e] = 0.f;

    LDGC(0);
    STSC(0);
    __syncthreads();

    for (int it = 0; it < 32; it++) {
        if (it + 1 < 32) LDGC((it + 1) * 32);

        const uint32_t* Awr = smw + (it & 1) * 5120 + (wm * 32) * 20;
        const uint32_t* Bwr = smw + (it & 1) * 5120 + 2560 + (wn * 64) * 20;
#pragma unroll
        for (int ks = 0; ks < 2; ks++) {
            uint32_t a[2][4];
#pragma unroll
            for (int mf = 0; mf < 2; mf++) {
                int idx = (mf * 16 + g) * 20 + ks * 8 + tig;
                a[mf][0] = Awr[idx];
                a[mf][1] = Awr[idx + 160];
                a[mf][2] = Awr[idx + 4];
                a[mf][3] = Awr[idx + 164];
            }
#pragma unroll
            for (int nf = 0; nf < 8; nf++) {
                int bidx = (nf * 8 + g) * 20 + ks * 8 + tig;
                uint32_t b0 = Bwr[bidx];
                uint32_t b1 = Bwr[bidx + 4];
#pragma unroll
                for (int mf = 0; mf < 2; mf++)
                    MMA16816(c[mf][nf], a[mf][0], a[mf][1], a[mf][2], a[mf][3], b0, b1);
            }
        }
        if (it + 1 < 32) STSC((it + 1) & 1);
        __syncthreads();
    }

    if (OBF) {
        bf16* C = (bf16*)((n0 < 1024) ? C0v : C1v);
        int col0 = (n0 & 1023) + wn * 64;
#pragma unroll
        for (int mf = 0; mf < 2; mf++) {
            int r0 = m0 + wm * 32 + mf * 16 + g;
#pragma unroll
            for (int nf = 0; nf < 8; nf++) {
                int col = col0 + nf * 8 + tig * 2;
                *(uint32_t*)&C[(size_t)r0 * EMB + col] = bf16x2_of(c[mf][nf][0], c[mf][nf][1]);
                *(uint32_t*)&C[(size_t)(r0 + 8) * EMB + col] = bf16x2_of(c[mf][nf][2], c[mf][nf][3]);
            }
        }
    } else {
        float* C = (float*)C0v;
#pragma unroll
        for (int mf = 0; mf < 2; mf++) {
            int r0 = m0 + wm * 32 + mf * 16 + g;
#pragma unroll
            for (int nf = 0; nf < 8; nf++) {
                int col = n0 + wn * 64 + nf * 8 + tig * 2;
                float2 v0 = make_float2(c[mf][nf][0], c[mf][nf][1]);
                float2 v1 = make_float2(c[mf][nf][2], c[mf][nf][3]);
                if (resid) {
                    float2 a0 = *(const float2*)(resid + (size_t)r0 * EMB + col);
                    float2 a1 = *(const float2*)(resid + (size_t)(r0 + 8) * EMB + col);
                    v0.x += a0.x; v0.y += a0.y;
                    v1.x += a1.x; v1.y += a1.y;
                }
                *(float2*)(C + (size_t)r0 * EMB + col) = v0;
                *(float2*)(C + (size_t)(r0 + 8) * EMB + col) = v1;
            }
        }
    }
}

// ---------------- BD via bf16 mma: pre-shifted band write (bf16) ----------------
__global__ __launch_bounds__(256) void bd_mma(const float* __restrict__ rrb)
{
    const int pt = blockIdx.x, it = blockIdx.y, bh = blockIdx.z;
    const int i0 = it * 128, p0 = pt * 64;
    if (i0 + p0 < 833) return;  // whole tile maps to j < 0
    const int b = bh >> 4, h = bh & 15;

    __shared__ uint32_t sm[6912];      // Qs 128*36 + Rs 64*36
    uint32_t* Qs = sm;
    uint32_t* Rs = sm + 4608;
    const int tid = threadIdx.x, lane = tid & 31, wm = tid >> 5;
    const int g = lane >> 2, tig = lane & 3;

    const float2* bias2 = (const float2*)&rrb[h * DH];
#pragma unroll
    for (int u = 0; u < 4; u++) {
        int f = tid + 256 * u;
        int row = f >> 3, d8 = (f & 7) * 8;
        uint4 qv = *(const uint4*)&g_Qh[((size_t)(b * QL + i0 + row)) * EMB + h * DH + d8];
        const uint32_t* qw = (const uint32_t*)&qv;
#pragma unroll
        for (int j = 0; j < 4; j++) {
            float2 qf = f2_of_bf16x2(qw[j]);
            float2 bb = bias2[(d8 >> 1) + j];
            Qs[row * 36 + (d8 >> 1) + j] = bf16x2_of(qf.x + bb.x, qf.y + bb.y);
        }
    }
#pragma unroll
    for (int u = 0; u < 2; u++) {
        int f = tid + 256 * u;
        int row = f >> 3, d8 = (f & 7) * 8;
        uint4 rv = *(const uint4*)&g_Rh[((size_t)(p0 + row)) * EMB + h * DH + d8];
        *(uint4*)&Rs[row * 36 + (d8 >> 1)] = rv;
    }
    __syncthreads();

    float s[8][4];
#pragma unroll
    for (int nf = 0; nf < 8; nf++)
#pragma unroll
        for (int e = 0; e < 4; e++) s[nf][e] = 0.f;

#pragma unroll
    for (int ks = 0; ks < 4; ks++) {
        int ai = (wm * 16 + g) * 36 + ks * 8 + tig;
        uint32_t a0 = Qs[ai], a1 = Qs[ai + 288], a2 = Qs[ai + 4], a3 = Qs[ai + 292];
#pragma unroll
        for (int nf = 0; nf < 8; nf++) {
            int bi = (nf * 8 + g) * 36 + ks * 8 + tig;
            MMA16816(s[nf], a0, a1, a2, a3, Rs[bi], Rs[bi + 4]);
        }
    }

    bf16* bdb = g_BDh + (size_t)(b * NH + h) * QL * KLEN;
#pragma unroll
    for (int e = 0; e < 2; e++) {
        int i = i0 + wm * 16 + g + 8 * e;
#pragma unroll
        for (int nf = 0; nf < 8; nf++) {
            int p = p0 + nf * 8 + 2 * tig;
            int j0 = p - (QL - 1) + i;
            if (j0 >= 0)     bdb[(size_t)i * KLEN + j0]     = __float2bfloat16(s[nf][2 * e]);
            if (j0 + 1 >= 0) bdb[(size_t)i * KLEN + j0 + 1] = __float2bfloat16(s[nf][2 * e + 1]);
        }
    }
}

// ---------------- flash attention, bf16 mma, q-tile 128 / k-tile 64 ----------------
__global__ __launch_bounds__(256) void flash_mma(const float* __restrict__ rwb)
{
    __shared__ uint32_t sm[9216];      // Qs 128*36 | Ks 64*36 | Vt 64*36
    uint32_t* Qs = sm;
    uint32_t* Ks = sm + 4608;
    uint32_t* Vt = sm + 6912;          // [d][kv] bf16, 72 halves per d-row
    bf16* Vh = (bf16*)Vt;

    const int qt = blockIdx.x, h = blockIdx.y, b = blockIdx.z;
    const int qi0 = qt * 128;
    const int tid = threadIdx.x, lane = tid & 31, wm = tid >> 5;
    const int g = lane >> 2, tig = lane & 3;

    // Q tile + content bias
    const float2* bias2 = (const float2*)&rwb[h * DH];
#pragma unroll
    for (int u = 0; u < 4; u++) {
        int f = tid + 256 * u;
        int row = f >> 3, d8 = (f & 7) * 8;
        uint4 qv = *(const uint4*)&g_Qh[((size_t)(b * QL + qi0 + row)) * EMB + h * DH + d8];
        const uint32_t* qw = (const uint32_t*)&qv;
#pragma unroll
        for (int j = 0; j < 4; j++) {
            float2 qf = f2_of_bf16x2(qw[j]);
            float2 bb = bias2[(d8 >> 1) + j];
            Qs[row * 36 + (d8 >> 1) + j] = bf16x2_of(qf.x + bb.x, qf.y + bb.y);
        }
    }

    float o[8][4];
#pragma unroll
    for (int nf = 0; nf < 8; nf++)
#pragma unroll
        for (int e = 0; e < 4; e++) o[nf][e] = 0.f;
    float mr[2] = {-1e30f, -1e30f}, lr[2] = {0.f, 0.f};

    const bf16* bdb = g_BDh + (size_t)(b * NH + h) * QL * KLEN;
    const float scl2 = 0.03125f * 1.4426950408889634f;

    const int nkt = 2 * qt + 18;
    for (int kt = 0; kt < nkt; kt++) {
        const int kj0 = kt * 64;
        __syncthreads();
#pragma unroll
        for (int u = 0; u < 2; u++) {
            int f = tid + 256 * u;
            int row = f >> 3, d8 = (f & 7) * 8;
            size_t go = ((size_t)(b * KLEN + kj0 + row)) * EMB + h * DH + d8;
            uint4 kv = *(const uint4*)&g_Kh[go];
            *(uint4*)&Ks[row * 36 + (d8 >> 1)] = kv;
            uint4 vv = *(const uint4*)&g_Vh[go];
            const bf16* vh = (const bf16*)&vv;
#pragma unroll
            for (int j = 0; j < 8; j++)
                Vh[(d8 + j) * 72 + row] = vh[j];
        }
        __syncthreads();

        // S = Q @ K^T
        float s[8][4];
#pragma unroll
        for (int nf = 0; nf < 8; nf++)
#pragma unroll
            for (int e = 0; e < 4; e++) s[nf][e] = 0.f;
#pragma unroll
        for (int ks = 0; ks < 4; ks++) {
            int ai = (wm * 16 + g) * 36 + ks * 8 + tig;
            uint32_t a0 = Qs[ai], a1 = Qs[ai + 288], a2 = Qs[ai + 4], a3 = Qs[ai + 292];
#pragma unroll
            for (int nf = 0; nf < 8; nf++) {
                int bi = (nf * 8 + g) * 36 + ks * 8 + tig;
                MMA16816(s[nf], a0, a1, a2, a3, Ks[bi], Ks[bi + 4]);
            }
        }

        // BD add + scale + mask + online softmax
#pragma unroll
        for (int e = 0; e < 2; e++) {
            int i = qi0 + wm * 16 + g + 8 * e;
            int jb = kj0 + 2 * tig;
            int jlim = i + ML;
            float mx = -1e30f;
#pragma unroll
            for (int nf = 0; nf < 8; nf++) {
                uint32_t bdw = *(const uint32_t*)&bdb[(size_t)i * KLEN + jb + nf * 8];
                float2 bd = f2_of_bf16x2(bdw);
                int j0 = jb + nf * 8;
                float v0 = (j0 <= jlim)     ? (s[nf][2 * e]     + bd.x) * scl2 : -1e30f;
                float v1 = (j0 + 1 <= jlim) ? (s[nf][2 * e + 1] + bd.y) * scl2 : -1e30f;
                s[nf][2 * e] = v0;
                s[nf][2 * e + 1] = v1;
                mx = fmaxf(mx, fmaxf(v0, v1));
            }
            mx = fmaxf(mx, __shfl_xor_sync(0xffffffff, mx, 1));
            mx = fmaxf(mx, __shfl_xor_sync(0xffffffff, mx, 2));
            float mnew = fmaxf(mr[e], mx);
            float scal = ex2f(mr[e] - mnew);
            mr[e] = mnew;
            float ps = 0.f;
#pragma unroll
            for (int nf = 0; nf < 8; nf++) {
                float p0 = ex2f(s[nf][2 * e] - mnew);
                float p1 = ex2f(s[nf][2 * e + 1] - mnew);
                s[nf][2 * e] = p0;
                s[nf][2 * e + 1] = p1;
                ps += p0 + p1;
            }
            ps += __shfl_xor_sync(0xffffffff, ps, 1);
            ps += __shfl_xor_sync(0xffffffff, ps, 2);
            lr[e] = lr[e] * scal + ps;
#pragma unroll
            for (int nf = 0; nf < 8; nf++) {
                o[nf][2 * e] *= scal;
                o[nf][2 * e + 1] *= scal;
            }
        }

        // pack P fragments (C-layout == A-layout)
        uint32_t pa[4][4];
#pragma unroll
        for (int t = 0; t < 4; t++) {
            pa[t][0] = bf16x2_of(s[2 * t][0], s[2 * t][1]);
            pa[t][1] = bf16x2_of(s[2 * t][2], s[2 * t][3]);
            pa[t][2] = bf16x2_of(s[2 * t + 1][0], s[2 * t + 1][1]);
            pa[t][3] = bf16x2_of(s[2 * t + 1][2], s[2 * t + 1][3]);
        }

        // O += P @ V
#pragma unroll
        for (int t = 0; t < 4; t++) {
#pragma unroll
            for (int nf = 0; nf < 8; nf++) {
                int bi = (nf * 8 + g) * 36 + 8 * t + tig;
                MMA16816(o[nf], pa[t][0], pa[t][1], pa[t][2], pa[t][3], Vt[bi], Vt[bi + 4]);
            }
        }
    }

#pragma unroll
    for (int e = 0; e < 2; e++) {
        int i = qi0 + wm * 16 + g + 8 * e;
        float inv = 1.0f / lr[e];
#pragma unroll
        for (int nf = 0; nf < 8; nf++) {
            float2 v = make_float2(o[nf][2 * e] * inv, o[nf][2 * e + 1] * inv);
            *(float2*)&g_AO[((size_t)b * QL + i) * EMB + h * DH + nf * 8 + 2 * tig] = v;
        }
    }
}

// ---------------- layernorm over last dim (1024), eps=1e-3 ----------------
__global__ __launch_bounds__(256) void ln_kernel(
    const float* __restrict__ gamma, const float* __restrict__ beta,
    float* __restrict__ out)
{
    const int row = blockIdx.x;
    const int tid = threadIdx.x;
    const float* x = g_X + (size_t)row * EMB;
    float4 v = ((const float4*)x)[tid];
    float s = v.x + v.y + v.z + v.w;
    float s2 = v.x * v.x + v.y * v.y + v.z * v.z + v.w * v.w;
#pragma unroll
    for (int w = 1; w < 32; w <<= 1) {
        s += __shfl_xor_sync(0xffffffff, s, w);
        s2 += __shfl_xor_sync(0xffffffff, s2, w);
    }
    __shared__ float sh[16];
    __shared__ float red[2];
    int wid = tid >> 5, lid = tid & 31;
    if (lid == 0) { sh[wid] = s; sh[wid + 8] = s2; }
    __syncthreads();
    if (tid == 0) {
        float ts = 0.f, ts2 = 0.f;
#pragma unroll
        for (int i = 0; i < 8; i++) { ts += sh[i]; ts2 += sh[i + 8]; }
        red[0] = ts; red[1] = ts2;
    }
    __syncthreads();
    float mean = red[0] * (1.0f / EMB);
    float var = red[1] * (1.0f / EMB) - mean * mean;
    float rs = rsqrtf(var + 1e-3f);
    float4 g = ((const float4*)gamma)[tid];
    float4 bt = ((const float4*)beta)[tid];
    float4 ov;
    ov.x = (v.x - mean) * rs * g.x + bt.x;
    ov.y = (v.y - mean) * rs * g.y + bt.y;
    ov.z = (v.z - mean) * rs * g.z + bt.z;
    ov.w = (v.w - mean) * rs * g.w + bt.w;
    ((float4*)(out + (size_t)row * EMB))[tid] = ov;
}

// ---------------- launch ----------------
extern "C" void kernel_launch(void* const* d_in, const int* in_sizes, int n_in,
                              void* d_out, int out_size)
{
    const float* w      = (const float*)d_in[0];
    const float* r      = (const float*)d_in[1];
    const float* rwb    = (const float*)d_in[3];
    const float* rrb    = (const float*)d_in[4];
    const float* member = (const float*)d_in[5];
    const float* Wq     = (const float*)d_in[6];
    const float* Wk     = (const float*)d_in[7];
    const float* Wv     = (const float*)d_in[8];
    const float* Wr     = (const float*)d_in[9];
    const float* Wo     = (const float*)d_in[10];
    const float* gamma  = (const float*)d_in[11];
    const float* beta   = (const float*)d_in[12];
    float* out = (float*)d_out;

    bf16 *gQh, *gKh, *gVh, *gRh, *gWT;
    float *gAO, *gX;
    cudaGetSymbolAddress((void**)&gQh, g_Qh);
    cudaGetSymbolAddress((void**)&gKh, g_Kh);
    cudaGetSymbolAddress((void**)&gVh, g_Vh);
    cudaGetSymbolAddress((void**)&gRh, g_Rh);
    cudaGetSymbolAddress((void**)&gAO, g_AO);
    cudaGetSymbolAddress((void**)&gX, g_X);
    cudaGetSymbolAddress((void**)&gWT, g_WTb);

    dim3 blk(256);

    // 0) transpose + convert weights to bf16 [n][k]
    transposeW<<<dim3(32, 32, 5), blk>>>(Wq, Wk, Wv, Wr, Wo);

    // 1) projections on bf16 tensor cores (bf16 outputs)
    mma_gemm<true><<<dim3(8, 16), blk>>>(w, nullptr, gWT + 0ull * (1 << 20),
                                         gQh, nullptr, nullptr, 0);
    // fused K+V: WT rows 0..2047 = [Wk^T; Wv^T], N=2048, M=4096
    mma_gemm<true><<<dim3(16, 32), blk>>>(member, w, gWT + 1ull * (1 << 20),
                                          gKh, gVh, nullptr, 1);
    mma_gemm<true><<<dim3(8, 16), blk>>>(r, nullptr, gWT + 3ull * (1 << 20),
                                         gRh, nullptr, nullptr, 0);

    // 2) BD with fused rel_shift (bf16 out)
    bd_mma<<<dim3(32, 8, 32), blk>>>(rrb);

    // 3) flash attention (bf16 mma, bf16 inputs)
    flash_mma<<<dim3(8, NH, BB), blk>>>(rwb);

    // 4) output projection + residual (fp32 out)
    mma_gemm<false><<<dim3(8, 16), blk>>>(gAO, nullptr, gWT + 4ull * (1 << 20),
                                          gX, nullptr, w, 0);

    // 5) layernorm
    ln_kernel<<<BB * QL, blk>>>(gamma, beta, out);
}

// round 8
// speedup vs baseline: 4.4846x; 1.1917x over previous
#include <cuda_runtime.h>
#include <cuda_bf16.h>
#include <cstdint>

#define BB 2
#define QL 1024
#define ML 1024
#define KLEN 2048
#define EMB 1024
#define NH 16
#define DH 64

typedef __nv_bfloat16 bf16;
typedef __nv_bfloat162 bf162;

// ---------------- scratch (static device, allocation-free) ----------------
__device__ bf16 g_Qh[BB * QL * EMB];
__device__ bf16 g_Kh[BB * KLEN * EMB];
__device__ bf16 g_Vh[BB * KLEN * EMB];
__device__ bf16 g_Rh[KLEN * EMB];
__device__ bf16 g_BDh[(size_t)BB * NH * QL * KLEN];
__device__ float g_AO[BB * QL * EMB];
__device__ float g_X[BB * QL * EMB];
__device__ bf16 g_WTb[5ull * 1024 * 1024];

__device__ __forceinline__ uint32_t smem_u32(const void* p) {
    uint32_t a;
    asm("{ .reg .u64 t; cvta.to.shared.u64 t, %1; cvt.u32.u64 %0, t; }" : "=r"(a) : "l"(p));
    return a;
}
__device__ __forceinline__ uint32_t bf16x2_of(float lo, float hi) {
    uint32_t o;
    asm("cvt.rn.bf16x2.f32 %0, %1, %2;" : "=r"(o) : "f"(hi), "f"(lo));
    return o;
}
__device__ __forceinline__ float2 f2_of_bf16x2(uint32_t w) {
    bf162 t = *reinterpret_cast<bf162*>(&w);
    return __bfloat1622float2(t);
}
__device__ __forceinline__ float ex2f(float x) {
    float y;
    asm("ex2.approx.f32 %0, %1;" : "=f"(y) : "f"(x));
    return y;
}
#define MMA16816(C, A0, A1, A2, A3, B0, B1) \
    asm volatile("mma.sync.aligned.m16n8k16.row.col.f32.bf16.bf16.f32 " \
        "{%0,%1,%2,%3}, {%4,%5,%6,%7}, {%8,%9}, {%0,%1,%2,%3};" \
        : "+f"((C)[0]), "+f"((C)[1]), "+f"((C)[2]), "+f"((C)[3]) \
        : "r"(A0), "r"(A1), "r"(A2), "r"(A3), "r"(B0), "r"(B1))
#define LDSM_X4(d0, d1, d2, d3, addr) \
    asm volatile("ldmatrix.sync.aligned.m8n8.x4.shared.b16 {%0,%1,%2,%3}, [%4];" \
        : "=r"(d0), "=r"(d1), "=r"(d2), "=r"(d3) : "r"(addr))
#define LDSM_X4_T(d0, d1, d2, d3, addr) \
    asm volatile("ldmatrix.sync.aligned.m8n8.x4.trans.shared.b16 {%0,%1,%2,%3}, [%4];" \
        : "=r"(d0), "=r"(d1), "=r"(d2), "=r"(d3) : "r"(addr))
#define CPA16(dst, src) \
    asm volatile("cp.async.cg.shared.global [%0], [%1], 16;" :: "r"(dst), "l"(src) : "memory")
#define CP_COMMIT() asm volatile("cp.async.commit_group;" ::: "memory")
#define CP_WAIT0()  asm volatile("cp.async.wait_group 0;" ::: "memory")
#define CP_WAIT1()  asm volatile("cp.async.wait_group 1;" ::: "memory")

// ---------------- weight transpose + bf16 convert ----------------
__global__ __launch_bounds__(256) void transposeW(
    const float* __restrict__ w0, const float* __restrict__ w1,
    const float* __restrict__ w2, const float* __restrict__ w3,
    const float* __restrict__ w4)
{
    __shared__ float t[32][33];
    const float* src;
    switch (blockIdx.z) {
        case 0: src = w0; break;
        case 1: src = w1; break;
        case 2: src = w2; break;
        case 3: src = w3; break;
        default: src = w4; break;
    }
    bf16* dst = g_WTb + ((size_t)blockIdx.z << 20);
    int tx = threadIdx.x & 31, ty = threadIdx.x >> 5;
    int x = blockIdx.x * 32 + tx;
    int y = blockIdx.y * 32 + ty;
#pragma unroll
    for (int j = 0; j < 32; j += 8)
        t[ty + j][tx] = src[(size_t)(y + j) * EMB + x];
    __syncthreads();
    x = blockIdx.y * 32 + tx;
    y = blockIdx.x * 32 + ty;
#pragma unroll
    for (int j = 0; j < 32; j += 8)
        dst[(size_t)(y + j) * EMB + x] = __float2bfloat16(t[tx][ty + j]);
}

// ---------------- bf16 mma GEMM (ldmatrix + cp.async) ----------------
// smem bytes: A buf b at b*20480 (128 rows x 80B), B buf b at 10240 + b*20480.
template <bool OBF>
__global__ __launch_bounds__(256, 2) void mma_gemm(
    const float* __restrict__ A, const float* __restrict__ A2,
    const bf16* __restrict__ WT,
    void* C0v, void* C1v, const float* __restrict__ resid, int mode)
{
    __shared__ uint32_t smw[10240];
    const uint32_t sbase = smem_u32(smw);
    const int tid = threadIdx.x;
    const int lane = tid & 31, wid = tid >> 5;
    const int m0 = blockIdx.y * 128, n0 = blockIdx.x * 128;
    const int wm = wid >> 1, wn = wid & 1;
    const int g = lane >> 2, tig = lane & 3;

    const float* ap[4];
    uint32_t swA[4];
#pragma unroll
    for (int u = 0; u < 4; u++) {
        int f4 = tid + 256 * u;
        int rr = f4 >> 3, c4 = f4 & 7;
        int m = m0 + rr;
        const float* arow;
        if (mode == 0) {
            arow = A + (size_t)m * EMB;
        } else {
            int b = m >> 11, t = m & 2047;
            arow = (t < ML) ? (A + ((size_t)b * ML + t) * EMB)
                            : (A2 + ((size_t)b * QL + (t - ML)) * EMB);
        }
        ap[u] = arow + c4 * 4;
        swA[u] = (uint32_t)(rr * 20 + c4 * 2);
    }
    const bf16* bp[2];
    uint32_t dstB[2];
#pragma unroll
    for (int v = 0; v < 2; v++) {
        int f16 = tid + 256 * v;
        int rr = f16 >> 2, c16 = f16 & 3;
        bp[v] = WT + (size_t)(n0 + rr) * EMB + c16 * 8;
        dstB[v] = sbase + 10240 + (uint32_t)(rr * 80 + c16 * 16);
    }

    float4 ra[4];
#define LDGA(k0) do { \
        _Pragma("unroll") for (int u = 0; u < 4; u++) ra[u] = *(const float4*)(ap[u] + (k0)); \
    } while (0)
#define STSA(buf) do { \
        uint32_t* Aw_ = smw + (buf) * 5120; \
        _Pragma("unroll") for (int u = 0; u < 4; u++) { \
            Aw_[swA[u]]     = bf16x2_of(ra[u].x, ra[u].y); \
            Aw_[swA[u] + 1] = bf16x2_of(ra[u].z, ra[u].w); \
        } \
    } while (0)
#define CPB(buf, k0) do { \
        _Pragma("unroll") for (int v = 0; v < 2; v++) \
            CPA16(dstB[v] + (buf) * 20480, bp[v] + (k0)); \
        CP_COMMIT(); \
    } while (0)

    const uint32_t aLd = sbase + (uint32_t)((wm * 32 + (lane & 15)) * 80 + (lane & 16));
    const uint32_t bLd = sbase + 10240 + (uint32_t)((wn * 64 + (lane & 15)) * 80 + (lane & 16));

    float c[2][8][4];
#pragma unroll
    for (int mf = 0; mf < 2; mf++)
#pragma unroll
        for (int nf = 0; nf < 8; nf++)
#pragma unroll
            for (int e = 0; e < 4; e++) c[mf][nf][e] = 0.f;

    LDGA(0);
    CPB(0, 0);
    STSA(0);
    CP_WAIT0();
    __syncthreads();

    for (int it = 0; it < 32; it++) {
        if (it + 1 < 32) {
            LDGA((it + 1) * 32);
            CPB((it + 1) & 1, (it + 1) * 32);
        }
        const uint32_t bufB = (uint32_t)(it & 1) * 20480;
#pragma unroll
        for (int ks = 0; ks < 2; ks++) {
            uint32_t a0, a1, a2, a3, a4, a5, a6, a7;
            LDSM_X4(a0, a1, a2, a3, aLd + bufB + ks * 32);
            LDSM_X4(a4, a5, a6, a7, aLd + bufB + 1280 + ks * 32);
#pragma unroll
            for (int nf2 = 0; nf2 < 4; nf2++) {
                uint32_t b0, b1, b2, b3;
                LDSM_X4(b0, b1, b2, b3, bLd + bufB + nf2 * 1280 + ks * 32);
                MMA16816(c[0][2 * nf2],     a0, a1, a2, a3, b0, b2);
                MMA16816(c[0][2 * nf2 + 1], a0, a1, a2, a3, b1, b3);
                MMA16816(c[1][2 * nf2],     a4, a5, a6, a7, b0, b2);
                MMA16816(c[1][2 * nf2 + 1], a4, a5, a6, a7, b1, b3);
            }
        }
        if (it + 1 < 32) STSA((it + 1) & 1);
        CP_WAIT0();
        __syncthreads();
    }

    if (OBF) {
        bf16* C = (bf16*)((n0 < 1024) ? C0v : C1v);
        int col0 = (n0 & 1023) + wn * 64;
#pragma unroll
        for (int mf = 0; mf < 2; mf++) {
            int r0 = m0 + wm * 32 + mf * 16 + g;
#pragma unroll
            for (int nf = 0; nf < 8; nf++) {
                int col = col0 + nf * 8 + tig * 2;
                *(uint32_t*)&C[(size_t)r0 * EMB + col] = bf16x2_of(c[mf][nf][0], c[mf][nf][1]);
                *(uint32_t*)&C[(size_t)(r0 + 8) * EMB + col] = bf16x2_of(c[mf][nf][2], c[mf][nf][3]);
            }
        }
    } else {
        float* C = (float*)C0v;
#pragma unroll
        for (int mf = 0; mf < 2; mf++) {
            int r0 = m0 + wm * 32 + mf * 16 + g;
#pragma unroll
            for (int nf = 0; nf < 8; nf++) {
                int col = n0 + wn * 64 + nf * 8 + tig * 2;
                float2 v0 = make_float2(c[mf][nf][0], c[mf][nf][1]);
                float2 v1 = make_float2(c[mf][nf][2], c[mf][nf][3]);
                if (resid) {
                    float2 a0 = *(const float2*)(resid + (size_t)r0 * EMB + col);
                    float2 a1 = *(const float2*)(resid + (size_t)(r0 + 8) * EMB + col);
                    v0.x += a0.x; v0.y += a0.y;
                    v1.x += a1.x; v1.y += a1.y;
                }
                *(float2*)(C + (size_t)r0 * EMB + col) = v0;
                *(float2*)(C + (size_t)(r0 + 8) * EMB + col) = v1;
            }
        }
    }
}

// ---------------- BD via bf16 mma (ldmatrix), pre-shifted band write ----------------
// smem bytes: Q 128 rows x 144B (0..18431), R 64 rows x 144B (18432..27647).
__global__ __launch_bounds__(256, 2) void bd_mma(const float* __restrict__ rrb)
{
    const int pt = blockIdx.x, it = blockIdx.y, bh = blockIdx.z;
    const int i0 = it * 128, p0 = pt * 64;
    if (i0 + p0 < 833) return;
    const int b = bh >> 4, h = bh & 15;

    __shared__ uint32_t sm[6912];
    const uint32_t sbase = smem_u32(sm);
    const uint32_t Rb = sbase + 18432;
    const int tid = threadIdx.x, lane = tid & 31, wm = tid >> 5;
    const int g = lane >> 2, tig = lane & 3;

    // R via cp.async
#pragma unroll
    for (int u = 0; u < 2; u++) {
        int f = tid + 256 * u;
        int row = f >> 3, c16 = f & 7;
        CPA16(Rb + row * 144 + c16 * 16,
              g_Rh + ((size_t)(p0 + row)) * EMB + h * DH + c16 * 8);
    }
    CP_COMMIT();

    // Q + bias via registers
    const float2* bias2 = (const float2*)&rrb[h * DH];
#pragma unroll
    for (int u = 0; u < 4; u++) {
        int f = tid + 256 * u;
        int row = f >> 3, d8 = (f & 7) * 8;
        uint4 qv = *(const uint4*)&g_Qh[((size_t)(b * QL + i0 + row)) * EMB + h * DH + d8];
        const uint32_t* qw = (const uint32_t*)&qv;
#pragma unroll
        for (int j = 0; j < 4; j++) {
            float2 qf = f2_of_bf16x2(qw[j]);
            float2 bbv = bias2[(d8 >> 1) + j];
            sm[row * 36 + (d8 >> 1) + j] = bf16x2_of(qf.x + bbv.x, qf.y + bbv.y);
        }
    }
    CP_WAIT0();
    __syncthreads();

    const uint32_t aLd = sbase + (uint32_t)((wm * 16 + (lane & 15)) * 144 + (lane & 16));
    const uint32_t bLd = Rb + (uint32_t)((lane & 15) * 144 + (lane & 16));

    float s[8][4];
#pragma unroll
    for (int nf = 0; nf < 8; nf++)
#pragma unroll
        for (int e = 0; e < 4; e++) s[nf][e] = 0.f;

#pragma unroll
    for (int ks = 0; ks < 4; ks++) {
        uint32_t a0, a1, a2, a3;
        LDSM_X4(a0, a1, a2, a3, aLd + ks * 32);
#pragma unroll
        for (int nf2 = 0; nf2 < 4; nf2++) {
            uint32_t b0, b1, b2, b3;
            LDSM_X4(b0, b1, b2, b3, bLd + nf2 * 2304 + ks * 32);
            MMA16816(s[2 * nf2],     a0, a1, a2, a3, b0, b2);
            MMA16816(s[2 * nf2 + 1], a0, a1, a2, a3, b1, b3);
        }
    }

    bf16* bdb = g_BDh + (size_t)(b * NH + h) * QL * KLEN;
#pragma unroll
    for (int e = 0; e < 2; e++) {
        int i = i0 + wm * 16 + g + 8 * e;
#pragma unroll
        for (int nf = 0; nf < 8; nf++) {
            int p = p0 + nf * 8 + 2 * tig;
            int j0 = p - (QL - 1) + i;
            if (j0 >= 0)     bdb[(size_t)i * KLEN + j0]     = __float2bfloat16(s[nf][2 * e]);
            if (j0 + 1 >= 0) bdb[(size_t)i * KLEN + j0 + 1] = __float2bfloat16(s[nf][2 * e + 1]);
        }
    }
}

// ---------------- flash attention: ldmatrix + cp.async double-buffered K/V ----------------
// smem bytes: Q 0..18431; buf b: K at 18432 + b*18432, V at K+9216. total 55296B.
__global__ __launch_bounds__(256) void flash_mma(const float* __restrict__ rwb)
{
    extern __shared__ uint32_t smd[];
    const uint32_t sbase = smem_u32(smd);

    const int qt = 7 - blockIdx.x, h = blockIdx.y, b = blockIdx.z;
    const int qi0 = qt * 128;
    const int tid = threadIdx.x, lane = tid & 31, wm = tid >> 5;
    const int g = lane >> 2, tig = lane & 3;

#define CPKV(kt, buf) do { \
        const int kj0_ = (kt) * 64; \
        uint32_t kb_ = sbase + 18432 + (uint32_t)(buf) * 18432; \
        _Pragma("unroll") for (int u = 0; u < 2; u++) { \
            int f_ = tid + 256 * u; \
            int row_ = f_ >> 3, c16_ = f_ & 7; \
            size_t go_ = ((size_t)(b * KLEN + kj0_ + row_)) * EMB + h * DH + c16_ * 8; \
            CPA16(kb_ + row_ * 144 + c16_ * 16, g_Kh + go_); \
            CPA16(kb_ + 9216 + row_ * 144 + c16_ * 16, g_Vh + go_); \
        } \
        CP_COMMIT(); \
    } while (0)

    CPKV(0, 0);
    const float2* bias2 = (const float2*)&rwb[h * DH];
#pragma unroll
    for (int u = 0; u < 4; u++) {
        int f = tid + 256 * u;
        int row = f >> 3, d8 = (f & 7) * 8;
        uint4 qv = *(const uint4*)&g_Qh[((size_t)(b * QL + qi0 + row)) * EMB + h * DH + d8];
        const uint32_t* qw = (const uint32_t*)&qv;
#pragma unroll
        for (int j = 0; j < 4; j++) {
            float2 qf = f2_of_bf16x2(qw[j]);
            float2 bbv = bias2[(d8 >> 1) + j];
            smd[row * 36 + (d8 >> 1) + j] = bf16x2_of(qf.x + bbv.x, qf.y + bbv.y);
        }
    }

    float o[8][4];
#pragma unroll
    for (int nf = 0; nf < 8; nf++)
#pragma unroll
        for (int e = 0; e < 4; e++) o[nf][e] = 0.f;
    float mr[2] = {-1e30f, -1e30f}, lr[2] = {0.f, 0.f};

    const bf16* bdb = g_BDh + (size_t)(b * NH + h) * QL * KLEN;
    const float scl2 = 0.03125f * 1.4426950408889634f;

    const uint32_t qLd = sbase + (uint32_t)((wm * 16 + (lane & 15)) * 144 + (lane & 16));
    const uint32_t kLdOff = (uint32_t)((lane & 15) * 144 + (lane & 16));
    const uint32_t vLdOff = (uint32_t)(((lane & 7) + ((lane & 16) >> 1)) * 144 + (lane & 8) * 2);

    const int nkt = 2 * qt + 18;
    for (int kt = 0; kt < nkt; kt++) {
        if (kt + 1 < nkt) {
            CPKV(kt + 1, (kt + 1) & 1);
            CP_WAIT1();
        } else {
            CP_WAIT0();
        }
        __syncthreads();

        const uint32_t Kb = sbase + 18432 + (uint32_t)(kt & 1) * 18432;
        const uint32_t kLd = Kb + kLdOff;
        const uint32_t vLd = Kb + 9216 + vLdOff;
        const int kj0 = kt * 64;

        // S = Q @ K^T
        float s[8][4];
#pragma unroll
        for (int nf = 0; nf < 8; nf++)
#pragma unroll
            for (int e = 0; e < 4; e++) s[nf][e] = 0.f;
#pragma unroll
        for (int ks = 0; ks < 4; ks++) {
            uint32_t a0, a1, a2, a3;
            LDSM_X4(a0, a1, a2, a3, qLd + ks * 32);
#pragma unroll
            for (int nf2 = 0; nf2 < 4; nf2++) {
                uint32_t b0, b1, b2, b3;
                LDSM_X4(b0, b1, b2, b3, kLd + nf2 * 2304 + ks * 32);
                MMA16816(s[2 * nf2],     a0, a1, a2, a3, b0, b2);
                MMA16816(s[2 * nf2 + 1], a0, a1, a2, a3, b1, b3);
            }
        }

        // BD add + scale + mask + online softmax
#pragma unroll
        for (int e = 0; e < 2; e++) {
            int i = qi0 + wm * 16 + g + 8 * e;
            int jb = kj0 + 2 * tig;
            int jlim = i + ML;
            float mx = -1e30f;
#pragma unroll
            for (int nf = 0; nf < 8; nf++) {
                uint32_t bdw = *(const uint32_t*)&bdb[(size_t)i * KLEN + jb + nf * 8];
                float2 bd = f2_of_bf16x2(bdw);
                int j0 = jb + nf * 8;
                float v0 = (j0 <= jlim)     ? (s[nf][2 * e]     + bd.x) * scl2 : -1e30f;
                float v1 = (j0 + 1 <= jlim) ? (s[nf][2 * e + 1] + bd.y) * scl2 : -1e30f;
                s[nf][2 * e] = v0;
                s[nf][2 * e + 1] = v1;
                mx = fmaxf(mx, fmaxf(v0, v1));
            }
            mx = fmaxf(mx, __shfl_xor_sync(0xffffffff, mx, 1));
            mx = fmaxf(mx, __shfl_xor_sync(0xffffffff, mx, 2));
            float mnew = fmaxf(mr[e], mx);
            float scal = ex2f(mr[e] - mnew);
            mr[e] = mnew;
            float ps = 0.f;
#pragma unroll
            for (int nf = 0; nf < 8; nf++) {
                float p0 = ex2f(s[nf][2 * e] - mnew);
                float p1 = ex2f(s[nf][2 * e + 1] - mnew);
                s[nf][2 * e] = p0;
                s[nf][2 * e + 1] = p1;
                ps += p0 + p1;
            }
            ps += __shfl_xor_sync(0xffffffff, ps, 1);
            ps += __shfl_xor_sync(0xffffffff, ps, 2);
            lr[e] = lr[e] * scal + ps;
#pragma unroll
            for (int nf = 0; nf < 8; nf++) {
                o[nf][2 * e] *= scal;
                o[nf][2 * e + 1] *= scal;
            }
        }

        // pack P fragments
        uint32_t pa[4][4];
#pragma unroll
        for (int t = 0; t < 4; t++) {
            pa[t][0] = bf16x2_of(s[2 * t][0], s[2 * t][1]);
            pa[t][1] = bf16x2_of(s[2 * t][2], s[2 * t][3]);
            pa[t][2] = bf16x2_of(s[2 * t + 1][0], s[2 * t + 1][1]);
            pa[t][3] = bf16x2_of(s[2 * t + 1][2], s[2 * t + 1][3]);
        }

        // O += P @ V (V^T via ldmatrix.trans)
#pragma unroll
        for (int t = 0; t < 4; t++) {
#pragma unroll
            for (int nf2 = 0; nf2 < 4; nf2++) {
                uint32_t b0, b1, b2, b3;
                LDSM_X4_T(b0, b1, b2, b3, vLd + t * 2304 + nf2 * 32);
                MMA16816(o[2 * nf2],     pa[t][0], pa[t][1], pa[t][2], pa[t][3], b0, b2);
                MMA16816(o[2 * nf2 + 1], pa[t][0], pa[t][1], pa[t][2], pa[t][3], b1, b3);
            }
        }
        __syncthreads();
    }

#pragma unroll
    for (int e = 0; e < 2; e++) {
        int i = qi0 + wm * 16 + g + 8 * e;
        float inv = 1.0f / lr[e];
#pragma unroll
        for (int nf = 0; nf < 8; nf++) {
            float2 v = make_float2(o[nf][2 * e] * inv, o[nf][2 * e + 1] * inv);
            *(float2*)&g_AO[((size_t)b * QL + i) * EMB + h * DH + nf * 8 + 2 * tig] = v;
        }
    }
}

// ---------------- layernorm ----------------
__global__ __launch_bounds__(256) void ln_kernel(
    const float* __restrict__ gamma, const float* __restrict__ beta,
    float* __restrict__ out)
{
    const int row = blockIdx.x;
    const int tid = threadIdx.x;
    const float* x = g_X + (size_t)row * EMB;
    float4 v = ((const float4*)x)[tid];
    float s = v.x + v.y + v.z + v.w;
    float s2 = v.x * v.x + v.y * v.y + v.z * v.z + v.w * v.w;
#pragma unroll
    for (int w = 1; w < 32; w <<= 1) {
        s += __shfl_xor_sync(0xffffffff, s, w);
        s2 += __shfl_xor_sync(0xffffffff, s2, w);
    }
    __shared__ float sh[16];
    __shared__ float red[2];
    int wid = tid >> 5, lid = tid & 31;
    if (lid == 0) { sh[wid] = s; sh[wid + 8] = s2; }
    __syncthreads();
    if (tid == 0) {
        float ts = 0.f, ts2 = 0.f;
#pragma unroll
        for (int i = 0; i < 8; i++) { ts += sh[i]; ts2 += sh[i + 8]; }
        red[0] = ts; red[1] = ts2;
    }
    __syncthreads();
    float mean = red[0] * (1.0f / EMB);
    float var = red[1] * (1.0f / EMB) - mean * mean;
    float rs = rsqrtf(var + 1e-3f);
    float4 gg = ((const float4*)gamma)[tid];
    float4 bt = ((const float4*)beta)[tid];
    float4 ov;
    ov.x = (v.x - mean) * rs * gg.x + bt.x;
    ov.y = (v.y - mean) * rs * gg.y + bt.y;
    ov.z = (v.z - mean) * rs * gg.z + bt.z;
    ov.w = (v.w - mean) * rs * gg.w + bt.w;
    ((float4*)(out + (size_t)row * EMB))[tid] = ov;
}

// ---------------- launch ----------------
extern "C" void kernel_launch(void* const* d_in, const int* in_sizes, int n_in,
                              void* d_out, int out_size)
{
    const float* w      = (const float*)d_in[0];
    const float* r      = (const float*)d_in[1];
    const float* rwb    = (const float*)d_in[3];
    const float* rrb    = (const float*)d_in[4];
    const float* member = (const float*)d_in[5];
    const float* Wq     = (const float*)d_in[6];
    const float* Wk     = (const float*)d_in[7];
    const float* Wv     = (const float*)d_in[8];
    const float* Wr     = (const float*)d_in[9];
    const float* Wo     = (const float*)d_in[10];
    const float* gamma  = (const float*)d_in[11];
    const float* beta   = (const float*)d_in[12];
    float* out = (float*)d_out;

    bf16 *gQh, *gKh, *gVh, *gRh, *gWT;
    float *gAO, *gX;
    cudaGetSymbolAddress((void**)&gQh, g_Qh);
    cudaGetSymbolAddress((void**)&gKh, g_Kh);
    cudaGetSymbolAddress((void**)&gVh, g_Vh);
    cudaGetSymbolAddress((void**)&gRh, g_Rh);
    cudaGetSymbolAddress((void**)&gAO, g_AO);
    cudaGetSymbolAddress((void**)&gX, g_X);
    cudaGetSymbolAddress((void**)&gWT, g_WTb);

    dim3 blk(256);

    // 0) transpose + convert weights to bf16 [n][k]
    transposeW<<<dim3(32, 32, 5), blk>>>(Wq, Wk, Wv, Wr, Wo);

    // 1) projections on bf16 tensor cores (bf16 outputs)
    mma_gemm<true><<<dim3(8, 16), blk>>>(w, nullptr, gWT + 0ull * (1 << 20),
                                         gQh, nullptr, nullptr, 0);
    mma_gemm<true><<<dim3(16, 32), blk>>>(member, w, gWT + 1ull * (1 << 20),
                                          gKh, gVh, nullptr, 1);
    mma_gemm<true><<<dim3(8, 16), blk>>>(r, nullptr, gWT + 3ull * (1 << 20),
                                         gRh, nullptr, nullptr, 0);

    // 2) BD with fused rel_shift
    bd_mma<<<dim3(32, 8, 32), blk>>>(rrb);

    // 3) flash attention (dyn smem 55296B)
    static const int FLASH_SMEM = 55296;
    cudaFuncSetAttribute(flash_mma, cudaFuncAttributeMaxDynamicSharedMemorySize, FLASH_SMEM);
    flash_mma<<<dim3(8, NH, BB), blk, FLASH_SMEM>>>(rwb);

    // 4) output projection + residual (fp32 out)
    mma_gemm<false><<<dim3(8, 16), blk>>>(gAO, nullptr, gWT + 4ull * (1 << 20),
                                          gX, nullptr, w, 0);

    // 5) layernorm
    ln_kernel<<<BB * QL, blk>>>(gamma, beta, out);
}

// round 9
// speedup vs baseline: 4.7242x; 1.0534x over previous
#include <cuda_runtime.h>
#include <cuda_bf16.h>
#include <cstdint>

#define BB 2
#define QL 1024
#define ML 1024
#define KLEN 2048
#define EMB 1024
#define NH 16
#define DH 64

typedef __nv_bfloat16 bf16;
typedef __nv_bfloat162 bf162;

// ---------------- scratch (static device, allocation-free) ----------------
__device__ bf16 g_Qh[BB * QL * EMB];
__device__ bf16 g_Kh[BB * KLEN * EMB];
__device__ bf16 g_Vh[BB * KLEN * EMB];
__device__ bf16 g_Rh[KLEN * EMB];
__device__ bf16 g_BDh[(size_t)BB * NH * QL * KLEN];
__device__ float g_AO[BB * QL * EMB];
__device__ float g_X[BB * QL * EMB];
__device__ bf16 g_WTb[5ull * 1024 * 1024];

__device__ __forceinline__ uint32_t smem_u32(const void* p) {
    uint32_t a;
    asm("{ .reg .u64 t; cvta.to.shared.u64 t, %1; cvt.u32.u64 %0, t; }" : "=r"(a) : "l"(p));
    return a;
}
__device__ __forceinline__ uint32_t bf16x2_of(float lo, float hi) {
    uint32_t o;
    asm("cvt.rn.bf16x2.f32 %0, %1, %2;" : "=r"(o) : "f"(hi), "f"(lo));
    return o;
}
__device__ __forceinline__ float2 f2_of_bf16x2(uint32_t w) {
    bf162 t = *reinterpret_cast<bf162*>(&w);
    return __bfloat1622float2(t);
}
__device__ __forceinline__ float ex2f(float x) {
    float y;
    asm("ex2.approx.f32 %0, %1;" : "=f"(y) : "f"(x));
    return y;
}
#define MMA16816(C, A0, A1, A2, A3, B0, B1) \
    asm volatile("mma.sync.aligned.m16n8k16.row.col.f32.bf16.bf16.f32 " \
        "{%0,%1,%2,%3}, {%4,%5,%6,%7}, {%8,%9}, {%0,%1,%2,%3};" \
        : "+f"((C)[0]), "+f"((C)[1]), "+f"((C)[2]), "+f"((C)[3]) \
        : "r"(A0), "r"(A1), "r"(A2), "r"(A3), "r"(B0), "r"(B1))
#define LDSM_X4(d0, d1, d2, d3, addr) \
    asm volatile("ldmatrix.sync.aligned.m8n8.x4.shared.b16 {%0,%1,%2,%3}, [%4];" \
        : "=r"(d0), "=r"(d1), "=r"(d2), "=r"(d3) : "r"(addr))
#define LDSM_X4_T(d0, d1, d2, d3, addr) \
    asm volatile("ldmatrix.sync.aligned.m8n8.x4.trans.shared.b16 {%0,%1,%2,%3}, [%4];" \
        : "=r"(d0), "=r"(d1), "=r"(d2), "=r"(d3) : "r"(addr))
#define CPA16(dst, src) \
    asm volatile("cp.async.cg.shared.global [%0], [%1], 16;" :: "r"(dst), "l"(src) : "memory")
#define CP_COMMIT() asm volatile("cp.async.commit_group;" ::: "memory")
#define CP_WAIT0()  asm volatile("cp.async.wait_group 0;" ::: "memory")
#define CP_WAIT1()  asm volatile("cp.async.wait_group 1;" ::: "memory")

// ---------------- weight transpose + bf16 convert ----------------
__global__ __launch_bounds__(256) void transposeW(
    const float* __restrict__ w0, const float* __restrict__ w1,
    const float* __restrict__ w2, const float* __restrict__ w3,
    const float* __restrict__ w4)
{
    __shared__ float t[32][33];
    const float* src;
    switch (blockIdx.z) {
        case 0: src = w0; break;
        case 1: src = w1; break;
        case 2: src = w2; break;
        case 3: src = w3; break;
        default: src = w4; break;
    }
    bf16* dst = g_WTb + ((size_t)blockIdx.z << 20);
    int tx = threadIdx.x & 31, ty = threadIdx.x >> 5;
    int x = blockIdx.x * 32 + tx;
    int y = blockIdx.y * 32 + ty;
#pragma unroll
    for (int j = 0; j < 32; j += 8)
        t[ty + j][tx] = src[(size_t)(y + j) * EMB + x];
    __syncthreads();
    x = blockIdx.y * 32 + tx;
    y = blockIdx.x * 32 + ty;
#pragma unroll
    for (int j = 0; j < 32; j += 8)
        dst[(size_t)(y + j) * EMB + x] = __float2bfloat16(t[tx][ty + j]);
}

// ================= shared GEMM body (128x128 tile, ldmatrix, cp.async) =================
// A fp32 (mode1: gather cat(member,w)); B = WT[n][k] bf16. Writes bf16 (C0/C1
// split at n=1024) or fp32 (+resid).
template <bool OBF>
__device__ __forceinline__ void gemm_tile_body(
    const float* __restrict__ A, const float* __restrict__ A2,
    const bf16* __restrict__ WT,
    void* C0v, void* C1v, const float* __restrict__ resid,
    int mode, int m0, int n0, uint32_t* smw)
{
    const uint32_t sbase = smem_u32(smw);
    const int tid = threadIdx.x;
    const int lane = tid & 31, wid = tid >> 5;
    const int wm = wid >> 1, wn = wid & 1;
    const int g = lane >> 2, tig = lane & 3;

    const float* ap[4];
    uint32_t swA[4];
#pragma unroll
    for (int u = 0; u < 4; u++) {
        int f4 = tid + 256 * u;
        int rr = f4 >> 3, c4 = f4 & 7;
        int m = m0 + rr;
        const float* arow;
        if (mode == 0) {
            arow = A + (size_t)m * EMB;
        } else {
            int b = m >> 11, t = m & 2047;
            arow = (t < ML) ? (A + ((size_t)b * ML + t) * EMB)
                            : (A2 + ((size_t)b * QL + (t - ML)) * EMB);
        }
        ap[u] = arow + c4 * 4;
        swA[u] = (uint32_t)(rr * 20 + c4 * 2);
    }
    const bf16* bp[2];
    uint32_t dstB[2];
#pragma unroll
    for (int v = 0; v < 2; v++) {
        int f16 = tid + 256 * v;
        int rr = f16 >> 2, c16 = f16 & 3;
        bp[v] = WT + (size_t)(n0 + rr) * EMB + c16 * 8;
        dstB[v] = sbase + 10240 + (uint32_t)(rr * 80 + c16 * 16);
    }

    float4 ra[4];
#define LDGA(k0) do { \
        _Pragma("unroll") for (int u = 0; u < 4; u++) ra[u] = *(const float4*)(ap[u] + (k0)); \
    } while (0)
#define STSA(buf) do { \
        uint32_t* Aw_ = smw + (buf) * 5120; \
        _Pragma("unroll") for (int u = 0; u < 4; u++) { \
            Aw_[swA[u]]     = bf16x2_of(ra[u].x, ra[u].y); \
            Aw_[swA[u] + 1] = bf16x2_of(ra[u].z, ra[u].w); \
        } \
    } while (0)
#define CPB(buf, k0) do { \
        _Pragma("unroll") for (int v = 0; v < 2; v++) \
            CPA16(dstB[v] + (buf) * 20480, bp[v] + (k0)); \
        CP_COMMIT(); \
    } while (0)

    const uint32_t aLd = sbase + (uint32_t)((wm * 32 + (lane & 15)) * 80 + (lane & 16));
    const uint32_t bLd = sbase + 10240 + (uint32_t)((wn * 64 + (lane & 15)) * 80 + (lane & 16));

    float c[2][8][4];
#pragma unroll
    for (int mf = 0; mf < 2; mf++)
#pragma unroll
        for (int nf = 0; nf < 8; nf++)
#pragma unroll
            for (int e = 0; e < 4; e++) c[mf][nf][e] = 0.f;

    LDGA(0);
    CPB(0, 0);
    STSA(0);
    CP_WAIT0();
    __syncthreads();

    for (int it = 0; it < 32; it++) {
        if (it + 1 < 32) {
            LDGA((it + 1) * 32);
            CPB((it + 1) & 1, (it + 1) * 32);
        }
        const uint32_t bufB = (uint32_t)(it & 1) * 20480;
#pragma unroll
        for (int ks = 0; ks < 2; ks++) {
            uint32_t a0, a1, a2, a3, a4, a5, a6, a7;
            LDSM_X4(a0, a1, a2, a3, aLd + bufB + ks * 32);
            LDSM_X4(a4, a5, a6, a7, aLd + bufB + 1280 + ks * 32);
#pragma unroll
            for (int nf2 = 0; nf2 < 4; nf2++) {
                uint32_t b0, b1, b2, b3;
                LDSM_X4(b0, b1, b2, b3, bLd + bufB + nf2 * 1280 + ks * 32);
                MMA16816(c[0][2 * nf2],     a0, a1, a2, a3, b0, b2);
                MMA16816(c[0][2 * nf2 + 1], a0, a1, a2, a3, b1, b3);
                MMA16816(c[1][2 * nf2],     a4, a5, a6, a7, b0, b2);
                MMA16816(c[1][2 * nf2 + 1], a4, a5, a6, a7, b1, b3);
            }
        }
        if (it + 1 < 32) STSA((it + 1) & 1);
        CP_WAIT0();
        __syncthreads();
    }

    if (OBF) {
        bf16* C = (bf16*)((n0 < 1024) ? C0v : C1v);
        int col0 = (n0 & 1023) + wn * 64;
#pragma unroll
        for (int mf = 0; mf < 2; mf++) {
            int r0 = m0 + wm * 32 + mf * 16 + g;
#pragma unroll
            for (int nf = 0; nf < 8; nf++) {
                int col = col0 + nf * 8 + tig * 2;
                *(uint32_t*)&C[(size_t)r0 * EMB + col] = bf16x2_of(c[mf][nf][0], c[mf][nf][1]);
                *(uint32_t*)&C[(size_t)(r0 + 8) * EMB + col] = bf16x2_of(c[mf][nf][2], c[mf][nf][3]);
            }
        }
    } else {
        float* C = (float*)C0v;
#pragma unroll
        for (int mf = 0; mf < 2; mf++) {
            int r0 = m0 + wm * 32 + mf * 16 + g;
#pragma unroll
            for (int nf = 0; nf < 8; nf++) {
                int col = n0 + wn * 64 + nf * 8 + tig * 2;
                float2 v0 = make_float2(c[mf][nf][0], c[mf][nf][1]);
                float2 v1 = make_float2(c[mf][nf][2], c[mf][nf][3]);
                if (resid) {
                    float2 a0 = *(const float2*)(resid + (size_t)r0 * EMB + col);
                    float2 a1 = *(const float2*)(resid + (size_t)(r0 + 8) * EMB + col);
                    v0.x += a0.x; v0.y += a0.y;
                    v1.x += a1.x; v1.y += a1.y;
                }
                *(float2*)(C + (size_t)r0 * EMB + col) = v0;
                *(float2*)(C + (size_t)(r0 + 8) * EMB + col) = v1;
            }
        }
    }
#undef LDGA
#undef STSA
#undef CPB
}

// ---------------- fused projection GEMM: Q + KV + R in one launch ----------------
// tiles: [0,128) Q (M=2048,N=1024); [128,640) KV (M=4096,N=2048, gather);
//        [640,768) R (M=2048,N=1024)
__global__ __launch_bounds__(256, 2) void proj_gemm(
    const float* __restrict__ w, const float* __restrict__ member,
    const float* __restrict__ r)
{
    __shared__ uint32_t smw[10240];
    const int t = blockIdx.x;
    const float *A, *A2 = nullptr;
    const bf16* WT;
    void *C0, *C1 = nullptr;
    int mode, m0, n0;
    if (t < 128) {
        A = w; WT = g_WTb; C0 = g_Qh; mode = 0;
        m0 = (t >> 3) * 128; n0 = (t & 7) * 128;
    } else if (t < 640) {
        int u = t - 128;
        A = member; A2 = w; WT = g_WTb + (1u << 20); C0 = g_Kh; C1 = g_Vh; mode = 1;
        m0 = (u >> 4) * 128; n0 = (u & 15) * 128;
    } else {
        int u = t - 640;
        A = r; WT = g_WTb + (3u << 20); C0 = g_Rh; mode = 0;
        m0 = (u >> 3) * 128; n0 = (u & 7) * 128;
    }
    gemm_tile_body<true>(A, A2, WT, C0, C1, nullptr, mode, m0, n0, smw);
}

// ---------------- Wo GEMM + residual (fp32 out) ----------------
__global__ __launch_bounds__(256, 2) void wo_gemm(const float* __restrict__ resid)
{
    __shared__ uint32_t smw[10240];
    const int m0 = blockIdx.y * 128, n0 = blockIdx.x * 128;
    gemm_tile_body<false>(g_AO, nullptr, g_WTb + (4u << 20), g_X, nullptr,
                          resid, 0, m0, n0, smw);
}

// NOTE: Wo's A operand is fp32 g_AO — gemm_tile_body expects fp32 A. OK.

// ---------------- BD via bf16 mma (ldmatrix), pre-shifted band write ----------------
__global__ __launch_bounds__(256, 2) void bd_mma(const float* __restrict__ rrb)
{
    const int pt = blockIdx.x, it = blockIdx.y, bh = blockIdx.z;
    const int i0 = it * 128, p0 = pt * 64;
    if (i0 + p0 < 833) return;
    const int b = bh >> 4, h = bh & 15;

    __shared__ uint32_t sm[6912];
    const uint32_t sbase = smem_u32(sm);
    const uint32_t Rb = sbase + 18432;
    const int tid = threadIdx.x, lane = tid & 31, wm = tid >> 5;
    const int g = lane >> 2, tig = lane & 3;

#pragma unroll
    for (int u = 0; u < 2; u++) {
        int f = tid + 256 * u;
        int row = f >> 3, c16 = f & 7;
        CPA16(Rb + row * 144 + c16 * 16,
              g_Rh + ((size_t)(p0 + row)) * EMB + h * DH + c16 * 8);
    }
    CP_COMMIT();

    const float2* bias2 = (const float2*)&rrb[h * DH];
#pragma unroll
    for (int u = 0; u < 4; u++) {
        int f = tid + 256 * u;
        int row = f >> 3, d8 = (f & 7) * 8;
        uint4 qv = *(const uint4*)&g_Qh[((size_t)(b * QL + i0 + row)) * EMB + h * DH + d8];
        const uint32_t* qw = (const uint32_t*)&qv;
#pragma unroll
        for (int j = 0; j < 4; j++) {
            float2 qf = f2_of_bf16x2(qw[j]);
            float2 bbv = bias2[(d8 >> 1) + j];
            sm[row * 36 + (d8 >> 1) + j] = bf16x2_of(qf.x + bbv.x, qf.y + bbv.y);
        }
    }
    CP_WAIT0();
    __syncthreads();

    const uint32_t aLd = sbase + (uint32_t)((wm * 16 + (lane & 15)) * 144 + (lane & 16));
    const uint32_t bLd = Rb + (uint32_t)((lane & 15) * 144 + (lane & 16));

    float s[8][4];
#pragma unroll
    for (int nf = 0; nf < 8; nf++)
#pragma unroll
        for (int e = 0; e < 4; e++) s[nf][e] = 0.f;

#pragma unroll
    for (int ks = 0; ks < 4; ks++) {
        uint32_t a0, a1, a2, a3;
        LDSM_X4(a0, a1, a2, a3, aLd + ks * 32);
#pragma unroll
        for (int nf2 = 0; nf2 < 4; nf2++) {
            uint32_t b0, b1, b2, b3;
            LDSM_X4(b0, b1, b2, b3, bLd + nf2 * 2304 + ks * 32);
            MMA16816(s[2 * nf2],     a0, a1, a2, a3, b0, b2);
            MMA16816(s[2 * nf2 + 1], a0, a1, a2, a3, b1, b3);
        }
    }

    bf16* bdb = g_BDh + (size_t)(b * NH + h) * QL * KLEN;
#pragma unroll
    for (int e = 0; e < 2; e++) {
        int i = i0 + wm * 16 + g + 8 * e;
#pragma unroll
        for (int nf = 0; nf < 8; nf++) {
            int p = p0 + nf * 8 + 2 * tig;
            int j0 = p - (QL - 1) + i;
            if (j0 >= 0)     bdb[(size_t)i * KLEN + j0]     = __float2bfloat16(s[nf][2 * e]);
            if (j0 + 1 >= 0) bdb[(size_t)i * KLEN + j0 + 1] = __float2bfloat16(s[nf][2 * e + 1]);
        }
    }
}

// ---------------- flash attention: ldmatrix + cp.async double-buffered K/V ----------------
__global__ __launch_bounds__(256) void flash_mma(const float* __restrict__ rwb)
{
    extern __shared__ uint32_t smd[];
    const uint32_t sbase = smem_u32(smd);

    const int qt = 7 - blockIdx.x, h = blockIdx.y, b = blockIdx.z;
    const int qi0 = qt * 128;
    const int tid = threadIdx.x, lane = tid & 31, wm = tid >> 5;
    const int g = lane >> 2, tig = lane & 3;

#define CPKV(kt, buf) do { \
        const int kj0_ = (kt) * 64; \
        uint32_t kb_ = sbase + 18432 + (uint32_t)(buf) * 18432; \
        _Pragma("unroll") for (int u = 0; u < 2; u++) { \
            int f_ = tid + 256 * u; \
            int row_ = f_ >> 3, c16_ = f_ & 7; \
            size_t go_ = ((size_t)(b * KLEN + kj0_ + row_)) * EMB + h * DH + c16_ * 8; \
            CPA16(kb_ + row_ * 144 + c16_ * 16, g_Kh + go_); \
            CPA16(kb_ + 9216 + row_ * 144 + c16_ * 16, g_Vh + go_); \
        } \
        CP_COMMIT(); \
    } while (0)

    CPKV(0, 0);
    const float2* bias2 = (const float2*)&rwb[h * DH];
#pragma unroll
    for (int u = 0; u < 4; u++) {
        int f = tid + 256 * u;
        int row = f >> 3, d8 = (f & 7) * 8;
        uint4 qv = *(const uint4*)&g_Qh[((size_t)(b * QL + qi0 + row)) * EMB + h * DH + d8];
        const uint32_t* qw = (const uint32_t*)&qv;
#pragma unroll
        for (int j = 0; j < 4; j++) {
            float2 qf = f2_of_bf16x2(qw[j]);
            float2 bbv = bias2[(d8 >> 1) + j];
            smd[row * 36 + (d8 >> 1) + j] = bf16x2_of(qf.x + bbv.x, qf.y + bbv.y);
        }
    }

    float o[8][4];
#pragma unroll
    for (int nf = 0; nf < 8; nf++)
#pragma unroll
        for (int e = 0; e < 4; e++) o[nf][e] = 0.f;
    float mr[2] = {-1e30f, -1e30f}, lr[2] = {0.f, 0.f};

    const bf16* bdb = g_BDh + (size_t)(b * NH + h) * QL * KLEN;
    const float scl2 = 0.03125f * 1.4426950408889634f;

    const uint32_t qLd = sbase + (uint32_t)((wm * 16 + (lane & 15)) * 144 + (lane & 16));
    const uint32_t kLdOff = (uint32_t)((lane & 15) * 144 + (lane & 16));
    const uint32_t vLdOff = (uint32_t)(((lane & 7) + ((lane & 16) >> 1)) * 144 + (lane & 8) * 2);

    const int nkt = 2 * qt + 18;
    for (int kt = 0; kt < nkt; kt++) {
        if (kt + 1 < nkt) {
            CPKV(kt + 1, (kt + 1) & 1);
            CP_WAIT1();
        } else {
            CP_WAIT0();
        }
        __syncthreads();

        const uint32_t Kb = sbase + 18432 + (uint32_t)(kt & 1) * 18432;
        const uint32_t kLd = Kb + kLdOff;
        const uint32_t vLd = Kb + 9216 + vLdOff;
        const int kj0 = kt * 64;

        float s[8][4];
#pragma unroll
        for (int nf = 0; nf < 8; nf++)
#pragma unroll
            for (int e = 0; e < 4; e++) s[nf][e] = 0.f;
#pragma unroll
        for (int ks = 0; ks < 4; ks++) {
            uint32_t a0, a1, a2, a3;
            LDSM_X4(a0, a1, a2, a3, qLd + ks * 32);
#pragma unroll
            for (int nf2 = 0; nf2 < 4; nf2++) {
                uint32_t b0, b1, b2, b3;
                LDSM_X4(b0, b1, b2, b3, kLd + nf2 * 2304 + ks * 32);
                MMA16816(s[2 * nf2],     a0, a1, a2, a3, b0, b2);
                MMA16816(s[2 * nf2 + 1], a0, a1, a2, a3, b1, b3);
            }
        }

#pragma unroll
        for (int e = 0; e < 2; e++) {
            int i = qi0 + wm * 16 + g + 8 * e;
            int jb = kj0 + 2 * tig;
            int jlim = i + ML;
            float mx = -1e30f;
#pragma unroll
            for (int nf = 0; nf < 8; nf++) {
                uint32_t bdw = *(const uint32_t*)&bdb[(size_t)i * KLEN + jb + nf * 8];
                float2 bd = f2_of_bf16x2(bdw);
                int j0 = jb + nf * 8;
                float v0 = (j0 <= jlim)     ? (s[nf][2 * e]     + bd.x) * scl2 : -1e30f;
                float v1 = (j0 + 1 <= jlim) ? (s[nf][2 * e + 1] + bd.y) * scl2 : -1e30f;
                s[nf][2 * e] = v0;
                s[nf][2 * e + 1] = v1;
                mx = fmaxf(mx, fmaxf(v0, v1));
            }
            mx = fmaxf(mx, __shfl_xor_sync(0xffffffff, mx, 1));
            mx = fmaxf(mx, __shfl_xor_sync(0xffffffff, mx, 2));
            float mnew = fmaxf(mr[e], mx);
            float scal = ex2f(mr[e] - mnew);
            mr[e] = mnew;
            float ps = 0.f;
#pragma unroll
            for (int nf = 0; nf < 8; nf++) {
                float p0 = ex2f(s[nf][2 * e] - mnew);
                float p1 = ex2f(s[nf][2 * e + 1] - mnew);
                s[nf][2 * e] = p0;
                s[nf][2 * e + 1] = p1;
                ps += p0 + p1;
            }
            ps += __shfl_xor_sync(0xffffffff, ps, 1);
            ps += __shfl_xor_sync(0xffffffff, ps, 2);
            lr[e] = lr[e] * scal + ps;
#pragma unroll
            for (int nf = 0; nf < 8; nf++) {
                o[nf][2 * e] *= scal;
                o[nf][2 * e + 1] *= scal;
            }
        }

        uint32_t pa[4][4];
#pragma unroll
        for (int t = 0; t < 4; t++) {
            pa[t][0] = bf16x2_of(s[2 * t][0], s[2 * t][1]);
            pa[t][1] = bf16x2_of(s[2 * t][2], s[2 * t][3]);
            pa[t][2] = bf16x2_of(s[2 * t + 1][0], s[2 * t + 1][1]);
            pa[t][3] = bf16x2_of(s[2 * t + 1][2], s[2 * t + 1][3]);
        }

#pragma unroll
        for (int t = 0; t < 4; t++) {
#pragma unroll
            for (int nf2 = 0; nf2 < 4; nf2++) {
                uint32_t b0, b1, b2, b3;
                LDSM_X4_T(b0, b1, b2, b3, vLd + t * 2304 + nf2 * 32);
                MMA16816(o[2 * nf2],     pa[t][0], pa[t][1], pa[t][2], pa[t][3], b0, b2);
                MMA16816(o[2 * nf2 + 1], pa[t][0], pa[t][1], pa[t][2], pa[t][3], b1, b3);
            }
        }
        __syncthreads();
    }

#pragma unroll
    for (int e = 0; e < 2; e++) {
        int i = qi0 + wm * 16 + g + 8 * e;
        float inv = 1.0f / lr[e];
#pragma unroll
        for (int nf = 0; nf < 8; nf++) {
            float2 v = make_float2(o[nf][2 * e] * inv, o[nf][2 * e + 1] * inv);
            *(float2*)&g_AO[((size_t)b * QL + i) * EMB + h * DH + nf * 8 + 2 * tig] = v;
        }
    }
}

// ---------------- layernorm ----------------
__global__ __launch_bounds__(256) void ln_kernel(
    const float* __restrict__ gamma, const float* __restrict__ beta,
    float* __restrict__ out)
{
    const int row = blockIdx.x;
    const int tid = threadIdx.x;
    const float* x = g_X + (size_t)row * EMB;
    float4 v = ((const float4*)x)[tid];
    float s = v.x + v.y + v.z + v.w;
    float s2 = v.x * v.x + v.y * v.y + v.z * v.z + v.w * v.w;
#pragma unroll
    for (int w = 1; w < 32; w <<= 1) {
        s += __shfl_xor_sync(0xffffffff, s, w);
        s2 += __shfl_xor_sync(0xffffffff, s2, w);
    }
    __shared__ float sh[16];
    __shared__ float red[2];
    int wid = tid >> 5, lid = tid & 31;
    if (lid == 0) { sh[wid] = s; sh[wid + 8] = s2; }
    __syncthreads();
    if (tid == 0) {
        float ts = 0.f, ts2 = 0.f;
#pragma unroll
        for (int i = 0; i < 8; i++) { ts += sh[i]; ts2 += sh[i + 8]; }
        red[0] = ts; red[1] = ts2;
    }
    __syncthreads();
    float mean = red[0] * (1.0f / EMB);
    float var = red[1] * (1.0f / EMB) - mean * mean;
    float rs = rsqrtf(var + 1e-3f);
    float4 gg = ((const float4*)gamma)[tid];
    float4 bt = ((const float4*)beta)[tid];
    float4 ov;
    ov.x = (v.x - mean) * rs * gg.x + bt.x;
    ov.y = (v.y - mean) * rs * gg.y + bt.y;
    ov.z = (v.z - mean) * rs * gg.z + bt.z;
    ov.w = (v.w - mean) * rs * gg.w + bt.w;
    ((float4*)(out + (size_t)row * EMB))[tid] = ov;
}

// ---------------- launch ----------------
extern "C" void kernel_launch(void* const* d_in, const int* in_sizes, int n_in,
                              void* d_out, int out_size)
{
    const float* w      = (const float*)d_in[0];
    const float* r      = (const float*)d_in[1];
    const float* rwb    = (const float*)d_in[3];
    const float* rrb    = (const float*)d_in[4];
    const float* member = (const float*)d_in[5];
    const float* Wq     = (const float*)d_in[6];
    const float* Wk     = (const float*)d_in[7];
    const float* Wv     = (const float*)d_in[8];
    const float* Wr     = (const float*)d_in[9];
    const float* Wo     = (const float*)d_in[10];
    const float* gamma  = (const float*)d_in[11];
    const float* beta   = (const float*)d_in[12];
    float* out = (float*)d_out;

    dim3 blk(256);

    // 0) transpose + convert weights to bf16 [n][k]
    transposeW<<<dim3(32, 32, 5), blk>>>(Wq, Wk, Wv, Wr, Wo);

    // 1) ALL projections (Q, fused KV, R) in one launch: 768 tiles
    proj_gemm<<<768, blk>>>(w, member, r);

    // 2) BD with fused rel_shift
    bd_mma<<<dim3(32, 8, 32), blk>>>(rrb);

    // 3) flash attention (dyn smem 55296B)
    static const int FLASH_SMEM = 55296;
    cudaFuncSetAttribute(flash_mma, cudaFuncAttributeMaxDynamicSharedMemorySize, FLASH_SMEM);
    flash_mma<<<dim3(8, NH, BB), blk, FLASH_SMEM>>>(rwb);

    // 4) output projection + residual (fp32 out)
    wo_gemm<<<dim3(8, 16), blk>>>(w);

    // 5) layernorm
    ln_kernel<<<BB * QL, blk>>>(gamma, beta, out);
}

// round 10
// speedup vs baseline: 4.8069x; 1.0175x over previous
#include <cuda_runtime.h>
#include <cuda_bf16.h>
#include <cstdint>

#define BB 2
#define QL 1024
#define ML 1024
#define KLEN 2048
#define EMB 1024
#define NH 16
#define DH 64

typedef __nv_bfloat16 bf16;
typedef __nv_bfloat162 bf162;

// ---------------- scratch (static device, allocation-free) ----------------
__device__ bf16 g_Qh[BB * QL * EMB];
__device__ bf16 g_Kh[BB * KLEN * EMB];
__device__ bf16 g_Vh[BB * KLEN * EMB];
__device__ bf16 g_Rh[KLEN * EMB];
__device__ bf16 g_BDh[(size_t)BB * NH * QL * KLEN];
__device__ float g_AO[BB * QL * EMB];
__device__ float g_X[BB * QL * EMB];
__device__ bf16 g_WTb[5ull * 1024 * 1024];

__device__ __forceinline__ uint32_t smem_u32(const void* p) {
    uint32_t a;
    asm("{ .reg .u64 t; cvta.to.shared.u64 t, %1; cvt.u32.u64 %0, t; }" : "=r"(a) : "l"(p));
    return a;
}
__device__ __forceinline__ uint32_t bf16x2_of(float lo, float hi) {
    uint32_t o;
    asm("cvt.rn.bf16x2.f32 %0, %1, %2;" : "=r"(o) : "f"(hi), "f"(lo));
    return o;
}
__device__ __forceinline__ float2 f2_of_bf16x2(uint32_t w) {
    bf162 t = *reinterpret_cast<bf162*>(&w);
    return __bfloat1622float2(t);
}
__device__ __forceinline__ float ex2f(float x) {
    float y;
    asm("ex2.approx.f32 %0, %1;" : "=f"(y) : "f"(x));
    return y;
}
#define MMA16816(C, A0, A1, A2, A3, B0, B1) \
    asm volatile("mma.sync.aligned.m16n8k16.row.col.f32.bf16.bf16.f32 " \
        "{%0,%1,%2,%3}, {%4,%5,%6,%7}, {%8,%9}, {%0,%1,%2,%3};" \
        : "+f"((C)[0]), "+f"((C)[1]), "+f"((C)[2]), "+f"((C)[3]) \
        : "r"(A0), "r"(A1), "r"(A2), "r"(A3), "r"(B0), "r"(B1))
#define LDSM_X4(d0, d1, d2, d3, addr) \
    asm volatile("ldmatrix.sync.aligned.m8n8.x4.shared.b16 {%0,%1,%2,%3}, [%4];" \
        : "=r"(d0), "=r"(d1), "=r"(d2), "=r"(d3) : "r"(addr))
#define LDSM_X4_T(d0, d1, d2, d3, addr) \
    asm volatile("ldmatrix.sync.aligned.m8n8.x4.trans.shared.b16 {%0,%1,%2,%3}, [%4];" \
        : "=r"(d0), "=r"(d1), "=r"(d2), "=r"(d3) : "r"(addr))
#define CPA16(dst, src) \
    asm volatile("cp.async.cg.shared.global [%0], [%1], 16;" :: "r"(dst), "l"(src) : "memory")
#define CP_COMMIT() asm volatile("cp.async.commit_group;" ::: "memory")
#define CP_WAIT0()  asm volatile("cp.async.wait_group 0;" ::: "memory")
#define CP_WAIT1()  asm volatile("cp.async.wait_group 1;" ::: "memory")

// ---------------- weight transpose + bf16 convert ----------------
__global__ __launch_bounds__(256) void transposeW(
    const float* __restrict__ w0, const float* __restrict__ w1,
    const float* __restrict__ w2, const float* __restrict__ w3,
    const float* __restrict__ w4)
{
    __shared__ float t[32][33];
    const float* src;
    switch (blockIdx.z) {
        case 0: src = w0; break;
        case 1: src = w1; break;
        case 2: src = w2; break;
        case 3: src = w3; break;
        default: src = w4; break;
    }
    bf16* dst = g_WTb + ((size_t)blockIdx.z << 20);
    int tx = threadIdx.x & 31, ty = threadIdx.x >> 5;
    int x = blockIdx.x * 32 + tx;
    int y = blockIdx.y * 32 + ty;
#pragma unroll
    for (int j = 0; j < 32; j += 8)
        t[ty + j][tx] = src[(size_t)(y + j) * EMB + x];
    __syncthreads();
    x = blockIdx.y * 32 + tx;
    y = blockIdx.x * 32 + ty;
#pragma unroll
    for (int j = 0; j < 32; j += 8)
        dst[(size_t)(y + j) * EMB + x] = __float2bfloat16(t[tx][ty + j]);
}

// ================= shared GEMM body (128x128 tile, ldmatrix, cp.async) =================
template <bool OBF>
__device__ __forceinline__ void gemm_tile_body(
    const float* __restrict__ A, const float* __restrict__ A2,
    const bf16* __restrict__ WT,
    void* C0v, void* C1v, const float* __restrict__ resid,
    int mode, int m0, int n0, uint32_t* smw)
{
    const uint32_t sbase = smem_u32(smw);
    const int tid = threadIdx.x;
    const int lane = tid & 31, wid = tid >> 5;
    const int wm = wid >> 1, wn = wid & 1;
    const int g = lane >> 2, tig = lane & 3;

    const float* ap[4];
    uint32_t swA[4];
#pragma unroll
    for (int u = 0; u < 4; u++) {
        int f4 = tid + 256 * u;
        int rr = f4 >> 3, c4 = f4 & 7;
        int m = m0 + rr;
        const float* arow;
        if (mode == 0) {
            arow = A + (size_t)m * EMB;
        } else {
            int b = m >> 11, t = m & 2047;
            arow = (t < ML) ? (A + ((size_t)b * ML + t) * EMB)
                            : (A2 + ((size_t)b * QL + (t - ML)) * EMB);
        }
        ap[u] = arow + c4 * 4;
        swA[u] = (uint32_t)(rr * 20 + c4 * 2);
    }
    const bf16* bp[2];
    uint32_t dstB[2];
#pragma unroll
    for (int v = 0; v < 2; v++) {
        int f16 = tid + 256 * v;
        int rr = f16 >> 2, c16 = f16 & 3;
        bp[v] = WT + (size_t)(n0 + rr) * EMB + c16 * 8;
        dstB[v] = sbase + 10240 + (uint32_t)(rr * 80 + c16 * 16);
    }

    float4 ra[4];
#define LDGA(k0) do { \
        _Pragma("unroll") for (int u = 0; u < 4; u++) ra[u] = *(const float4*)(ap[u] + (k0)); \
    } while (0)
#define STSA(buf) do { \
        uint32_t* Aw_ = smw + (buf) * 5120; \
        _Pragma("unroll") for (int u = 0; u < 4; u++) { \
            Aw_[swA[u]]     = bf16x2_of(ra[u].x, ra[u].y); \
            Aw_[swA[u] + 1] = bf16x2_of(ra[u].z, ra[u].w); \
        } \
    } while (0)
#define CPB(buf, k0) do { \
        _Pragma("unroll") for (int v = 0; v < 2; v++) \
            CPA16(dstB[v] + (buf) * 20480, bp[v] + (k0)); \
        CP_COMMIT(); \
    } while (0)

    const uint32_t aLd = sbase + (uint32_t)((wm * 32 + (lane & 15)) * 80 + (lane & 16));
    const uint32_t bLd = sbase + 10240 + (uint32_t)((wn * 64 + (lane & 15)) * 80 + (lane & 16));

    float c[2][8][4];
#pragma unroll
    for (int mf = 0; mf < 2; mf++)
#pragma unroll
        for (int nf = 0; nf < 8; nf++)
#pragma unroll
            for (int e = 0; e < 4; e++) c[mf][nf][e] = 0.f;

    LDGA(0);
    CPB(0, 0);
    STSA(0);
    CP_WAIT0();
    __syncthreads();

    for (int it = 0; it < 32; it++) {
        if (it + 1 < 32) {
            LDGA((it + 1) * 32);
            CPB((it + 1) & 1, (it + 1) * 32);
        }
        const uint32_t bufB = (uint32_t)(it & 1) * 20480;
#pragma unroll
        for (int ks = 0; ks < 2; ks++) {
            uint32_t a0, a1, a2, a3, a4, a5, a6, a7;
            LDSM_X4(a0, a1, a2, a3, aLd + bufB + ks * 32);
            LDSM_X4(a4, a5, a6, a7, aLd + bufB + 1280 + ks * 32);
#pragma unroll
            for (int nf2 = 0; nf2 < 4; nf2++) {
                uint32_t b0, b1, b2, b3;
                LDSM_X4(b0, b1, b2, b3, bLd + bufB + nf2 * 1280 + ks * 32);
                MMA16816(c[0][2 * nf2],     a0, a1, a2, a3, b0, b2);
                MMA16816(c[0][2 * nf2 + 1], a0, a1, a2, a3, b1, b3);
                MMA16816(c[1][2 * nf2],     a4, a5, a6, a7, b0, b2);
                MMA16816(c[1][2 * nf2 + 1], a4, a5, a6, a7, b1, b3);
            }
        }
        if (it + 1 < 32) STSA((it + 1) & 1);
        CP_WAIT0();
        __syncthreads();
    }

    if (OBF) {
        bf16* C = (bf16*)((n0 < 1024) ? C0v : C1v);
        int col0 = (n0 & 1023) + wn * 64;
#pragma unroll
        for (int mf = 0; mf < 2; mf++) {
            int r0 = m0 + wm * 32 + mf * 16 + g;
#pragma unroll
            for (int nf = 0; nf < 8; nf++) {
                int col = col0 + nf * 8 + tig * 2;
                *(uint32_t*)&C[(size_t)r0 * EMB + col] = bf16x2_of(c[mf][nf][0], c[mf][nf][1]);
                *(uint32_t*)&C[(size_t)(r0 + 8) * EMB + col] = bf16x2_of(c[mf][nf][2], c[mf][nf][3]);
            }
        }
    } else {
        float* C = (float*)C0v;
#pragma unroll
        for (int mf = 0; mf < 2; mf++) {
            int r0 = m0 + wm * 32 + mf * 16 + g;
#pragma unroll
            for (int nf = 0; nf < 8; nf++) {
                int col = n0 + wn * 64 + nf * 8 + tig * 2;
                float2 v0 = make_float2(c[mf][nf][0], c[mf][nf][1]);
                float2 v1 = make_float2(c[mf][nf][2], c[mf][nf][3]);
                if (resid) {
                    float2 a0 = *(const float2*)(resid + (size_t)r0 * EMB + col);
                    float2 a1 = *(const float2*)(resid + (size_t)(r0 + 8) * EMB + col);
                    v0.x += a0.x; v0.y += a0.y;
                    v1.x += a1.x; v1.y += a1.y;
                }
                *(float2*)(C + (size_t)r0 * EMB + col) = v0;
                *(float2*)(C + (size_t)(r0 + 8) * EMB + col) = v1;
            }
        }
    }
#undef LDGA
#undef STSA
#undef CPB
}

// ---------------- fused projection GEMM: Q + KV + R in one launch ----------------
__global__ __launch_bounds__(256, 2) void proj_gemm(
    const float* __restrict__ w, const float* __restrict__ member,
    const float* __restrict__ r)
{
    __shared__ uint32_t smw[10240];
    const int t = blockIdx.x;
    const float *A, *A2 = nullptr;
    const bf16* WT;
    void *C0, *C1 = nullptr;
    int mode, m0, n0;
    if (t < 128) {
        A = w; WT = g_WTb; C0 = g_Qh; mode = 0;
        m0 = (t >> 3) * 128; n0 = (t & 7) * 128;
    } else if (t < 640) {
        int u = t - 128;
        A = member; A2 = w; WT = g_WTb + (1u << 20); C0 = g_Kh; C1 = g_Vh; mode = 1;
        m0 = (u >> 4) * 128; n0 = (u & 15) * 128;
    } else {
        int u = t - 640;
        A = r; WT = g_WTb + (3u << 20); C0 = g_Rh; mode = 0;
        m0 = (u >> 3) * 128; n0 = (u & 7) * 128;
    }
    gemm_tile_body<true>(A, A2, WT, C0, C1, nullptr, mode, m0, n0, smw);
}

// ---------------- Wo GEMM + residual (fp32 out) ----------------
__global__ __launch_bounds__(256, 2) void wo_gemm(const float* __restrict__ resid)
{
    __shared__ uint32_t smw[10240];
    const int m0 = blockIdx.y * 128, n0 = blockIdx.x * 128;
    gemm_tile_body<false>(g_AO, nullptr, g_WTb + (4u << 20), g_X, nullptr,
                          resid, 0, m0, n0, smw);
}

// ---------------- BD via bf16 mma (ldmatrix), pre-shifted band write ----------------
__global__ __launch_bounds__(256, 2) void bd_mma(const float* __restrict__ rrb)
{
    const int pt = blockIdx.x, it = blockIdx.y, bh = blockIdx.z;
    const int i0 = it * 128, p0 = pt * 64;
    if (i0 + p0 < 833) return;
    const int b = bh >> 4, h = bh & 15;

    __shared__ uint32_t sm[6912];
    const uint32_t sbase = smem_u32(sm);
    const uint32_t Rb = sbase + 18432;
    const int tid = threadIdx.x, lane = tid & 31, wm = tid >> 5;
    const int g = lane >> 2, tig = lane & 3;

#pragma unroll
    for (int u = 0; u < 2; u++) {
        int f = tid + 256 * u;
        int row = f >> 3, c16 = f & 7;
        CPA16(Rb + row * 144 + c16 * 16,
              g_Rh + ((size_t)(p0 + row)) * EMB + h * DH + c16 * 8);
    }
    CP_COMMIT();

    const float2* bias2 = (const float2*)&rrb[h * DH];
#pragma unroll
    for (int u = 0; u < 4; u++) {
        int f = tid + 256 * u;
        int row = f >> 3, d8 = (f & 7) * 8;
        uint4 qv = *(const uint4*)&g_Qh[((size_t)(b * QL + i0 + row)) * EMB + h * DH + d8];
        const uint32_t* qw = (const uint32_t*)&qv;
#pragma unroll
        for (int j = 0; j < 4; j++) {
            float2 qf = f2_of_bf16x2(qw[j]);
            float2 bbv = bias2[(d8 >> 1) + j];
            sm[row * 36 + (d8 >> 1) + j] = bf16x2_of(qf.x + bbv.x, qf.y + bbv.y);
        }
    }
    CP_WAIT0();
    __syncthreads();

    const uint32_t aLd = sbase + (uint32_t)((wm * 16 + (lane & 15)) * 144 + (lane & 16));
    const uint32_t bLd = Rb + (uint32_t)((lane & 15) * 144 + (lane & 16));

    float s[8][4];
#pragma unroll
    for (int nf = 0; nf < 8; nf++)
#pragma unroll
        for (int e = 0; e < 4; e++) s[nf][e] = 0.f;

#pragma unroll
    for (int ks = 0; ks < 4; ks++) {
        uint32_t a0, a1, a2, a3;
        LDSM_X4(a0, a1, a2, a3, aLd + ks * 32);
#pragma unroll
        for (int nf2 = 0; nf2 < 4; nf2++) {
            uint32_t b0, b1, b2, b3;
            LDSM_X4(b0, b1, b2, b3, bLd + nf2 * 2304 + ks * 32);
            MMA16816(s[2 * nf2],     a0, a1, a2, a3, b0, b2);
            MMA16816(s[2 * nf2 + 1], a0, a1, a2, a3, b1, b3);
        }
    }

    bf16* bdb = g_BDh + (size_t)(b * NH + h) * QL * KLEN;
#pragma unroll
    for (int e = 0; e < 2; e++) {
        int i = i0 + wm * 16 + g + 8 * e;
#pragma unroll
        for (int nf = 0; nf < 8; nf++) {
            int p = p0 + nf * 8 + 2 * tig;
            int j0 = p - (QL - 1) + i;
            if (j0 >= 0)     bdb[(size_t)i * KLEN + j0]     = __float2bfloat16(s[nf][2 * e]);
            if (j0 + 1 >= 0) bdb[(size_t)i * KLEN + j0 + 1] = __float2bfloat16(s[nf][2 * e + 1]);
        }
    }
}

// ---------------- flash attention: ldmatrix + cp.async K/V/BD double-buffered ----------------
// smem bytes: Q [0,18432); buf b at 18432 + b*36864: K 9216 | V 9216 | BD 18432.
// total = 18432 + 2*36864 = 92160.
__global__ __launch_bounds__(256) void flash_mma(const float* __restrict__ rwb)
{
    extern __shared__ uint32_t smd[];
    const uint32_t sbase = smem_u32(smd);

    const int qt = 7 - blockIdx.x, h = blockIdx.y, b = blockIdx.z;
    const int qi0 = qt * 128;
    const int tid = threadIdx.x, lane = tid & 31, wm = tid >> 5;
    const int g = lane >> 2, tig = lane & 3;

    const bf16* bdb = g_BDh + (size_t)(b * NH + h) * QL * KLEN + (size_t)qi0 * KLEN;

#define CPKV(kt, buf) do { \
        const int kj0_ = (kt) * 64; \
        uint32_t kb_ = sbase + 18432 + (uint32_t)(buf) * 36864; \
        _Pragma("unroll") for (int u = 0; u < 2; u++) { \
            int f_ = tid + 256 * u; \
            int row_ = f_ >> 3, c16_ = f_ & 7; \
            size_t go_ = ((size_t)(b * KLEN + kj0_ + row_)) * EMB + h * DH + c16_ * 8; \
            CPA16(kb_ + row_ * 144 + c16_ * 16, g_Kh + go_); \
            CPA16(kb_ + 9216 + row_ * 144 + c16_ * 16, g_Vh + go_); \
        } \
        _Pragma("unroll") for (int u = 0; u < 4; u++) { \
            int f_ = tid + 256 * u; \
            int row_ = f_ >> 3, c16_ = f_ & 7; \
            CPA16(kb_ + 18432 + row_ * 144 + c16_ * 16, \
                  bdb + (size_t)row_ * KLEN + kj0_ + c16_ * 8); \
        } \
        CP_COMMIT(); \
    } while (0)

    CPKV(0, 0);
    const float2* bias2 = (const float2*)&rwb[h * DH];
#pragma unroll
    for (int u = 0; u < 4; u++) {
        int f = tid + 256 * u;
        int row = f >> 3, d8 = (f & 7) * 8;
        uint4 qv = *(const uint4*)&g_Qh[((size_t)(b * QL + qi0 + row)) * EMB + h * DH + d8];
        const uint32_t* qw = (const uint32_t*)&qv;
#pragma unroll
        for (int j = 0; j < 4; j++) {
            float2 qf = f2_of_bf16x2(qw[j]);
            float2 bbv = bias2[(d8 >> 1) + j];
            smd[row * 36 + (d8 >> 1) + j] = bf16x2_of(qf.x + bbv.x, qf.y + bbv.y);
        }
    }

    float o[8][4];
#pragma unroll
    for (int nf = 0; nf < 8; nf++)
#pragma unroll
        for (int e = 0; e < 4; e++) o[nf][e] = 0.f;
    float mr[2] = {-1e30f, -1e30f}, lr[2] = {0.f, 0.f};

    const float scl2 = 0.03125f * 1.4426950408889634f;

    const uint32_t qLd = sbase + (uint32_t)((wm * 16 + (lane & 15)) * 144 + (lane & 16));
    const uint32_t kLdOff = (uint32_t)((lane & 15) * 144 + (lane & 16));
    const uint32_t vLdOff = (uint32_t)(((lane & 7) + ((lane & 16) >> 1)) * 144 + (lane & 8) * 2);

    const int nkt = 2 * qt + 18;
    for (int kt = 0; kt < nkt; kt++) {
        const int buf = kt & 1;
        if (kt + 1 < nkt) {
            CPKV(kt + 1, (kt + 1) & 1);
            CP_WAIT1();
        } else {
            CP_WAIT0();
        }
        __syncthreads();

        const uint32_t Kb = sbase + 18432 + (uint32_t)buf * 36864;
        const uint32_t kLd = Kb + kLdOff;
        const uint32_t vLd = Kb + 9216 + vLdOff;
        const int kj0 = kt * 64;
        const bool edge = (kt >= nkt - 2);

        // S = Q @ K^T
        float s[8][4];
#pragma unroll
        for (int nf = 0; nf < 8; nf++)
#pragma unroll
            for (int e = 0; e < 4; e++) s[nf][e] = 0.f;
#pragma unroll
        for (int ks = 0; ks < 4; ks++) {
            uint32_t a0, a1, a2, a3;
            LDSM_X4(a0, a1, a2, a3, qLd + ks * 32);
#pragma unroll
            for (int nf2 = 0; nf2 < 4; nf2++) {
                uint32_t b0, b1, b2, b3;
                LDSM_X4(b0, b1, b2, b3, kLd + nf2 * 2304 + ks * 32);
                MMA16816(s[2 * nf2],     a0, a1, a2, a3, b0, b2);
                MMA16816(s[2 * nf2 + 1], a0, a1, a2, a3, b1, b3);
            }
        }

        // BD add (from smem) + scale (+ mask on edge tiles) + online softmax
#pragma unroll
        for (int e = 0; e < 2; e++) {
            const int iloc = wm * 16 + g + 8 * e;
            const uint32_t* bdp = smd + 9216 * (buf + 1) + iloc * 36 + tig;
            float mx = -1e30f;
            if (!edge) {
#pragma unroll
                for (int nf = 0; nf < 8; nf++) {
                    float2 bd = f2_of_bf16x2(bdp[nf * 4]);
                    float v0 = (s[nf][2 * e]     + bd.x) * scl2;
                    float v1 = (s[nf][2 * e + 1] + bd.y) * scl2;
                    s[nf][2 * e] = v0;
                    s[nf][2 * e + 1] = v1;
                    mx = fmaxf(mx, fmaxf(v0, v1));
                }
            } else {
                const int i = qi0 + iloc;
                const int jb = kj0 + 2 * tig;
                const int jlim = i + ML;
#pragma unroll
                for (int nf = 0; nf < 8; nf++) {
                    float2 bd = f2_of_bf16x2(bdp[nf * 4]);
                    int j0 = jb + nf * 8;
                    float v0 = (j0 <= jlim)     ? (s[nf][2 * e]     + bd.x) * scl2 : -1e30f;
                    float v1 = (j0 + 1 <= jlim) ? (s[nf][2 * e + 1] + bd.y) * scl2 : -1e30f;
                    s[nf][2 * e] = v0;
                    s[nf][2 * e + 1] = v1;
                    mx = fmaxf(mx, fmaxf(v0, v1));
                }
            }
            mx = fmaxf(mx, __shfl_xor_sync(0xffffffff, mx, 1));
            mx = fmaxf(mx, __shfl_xor_sync(0xffffffff, mx, 2));
            float mnew = fmaxf(mr[e], mx);
            float scal = ex2f(mr[e] - mnew);
            mr[e] = mnew;
            float ps = 0.f;
#pragma unroll
            for (int nf = 0; nf < 8; nf++) {
                float p0 = ex2f(s[nf][2 * e] - mnew);
                float p1 = ex2f(s[nf][2 * e + 1] - mnew);
                s[nf][2 * e] = p0;
                s[nf][2 * e + 1] = p1;
                ps += p0 + p1;
            }
            ps += __shfl_xor_sync(0xffffffff, ps, 1);
            ps += __shfl_xor_sync(0xffffffff, ps, 2);
            lr[e] = lr[e] * scal + ps;
#pragma unroll
            for (int nf = 0; nf < 8; nf++) {
                o[nf][2 * e] *= scal;
                o[nf][2 * e + 1] *= scal;
            }
        }

        // pack P fragments (C-layout == A-layout)
        uint32_t pa[4][4];
#pragma unroll
        for (int t = 0; t < 4; t++) {
            pa[t][0] = bf16x2_of(s[2 * t][0], s[2 * t][1]);
            pa[t][1] = bf16x2_of(s[2 * t][2], s[2 * t][3]);
            pa[t][2] = bf16x2_of(s[2 * t + 1][0], s[2 * t + 1][1]);
            pa[t][3] = bf16x2_of(s[2 * t + 1][2], s[2 * t + 1][3]);
        }

        // O += P @ V (V^T via ldmatrix.trans)
#pragma unroll
        for (int t = 0; t < 4; t++) {
#pragma unroll
            for (int nf2 = 0; nf2 < 4; nf2++) {
                uint32_t b0, b1, b2, b3;
                LDSM_X4_T(b0, b1, b2, b3, vLd + t * 2304 + nf2 * 32);
                MMA16816(o[2 * nf2],     pa[t][0], pa[t][1], pa[t][2], pa[t][3], b0, b2);
                MMA16816(o[2 * nf2 + 1], pa[t][0], pa[t][1], pa[t][2], pa[t][3], b1, b3);
            }
        }
        __syncthreads();
    }

#pragma unroll
    for (int e = 0; e < 2; e++) {
        int i = qi0 + wm * 16 + g + 8 * e;
        float inv = 1.0f / lr[e];
#pragma unroll
        for (int nf = 0; nf < 8; nf++) {
            float2 v = make_float2(o[nf][2 * e] * inv, o[nf][2 * e + 1] * inv);
            *(float2*)&g_AO[((size_t)b * QL + i) * EMB + h * DH + nf * 8 + 2 * tig] = v;
        }
    }
}

// ---------------- layernorm ----------------
__global__ __launch_bounds__(256) void ln_kernel(
    const float* __restrict__ gamma, const float* __restrict__ beta,
    float* __restrict__ out)
{
    const int row = blockIdx.x;
    const int tid = threadIdx.x;
    const float* x = g_X + (size_t)row * EMB;
    float4 v = ((const float4*)x)[tid];
    float s = v.x + v.y + v.z + v.w;
    float s2 = v.x * v.x + v.y * v.y + v.z * v.z + v.w * v.w;
#pragma unroll
    for (int w = 1; w < 32; w <<= 1) {
        s += __shfl_xor_sync(0xffffffff, s, w);
        s2 += __shfl_xor_sync(0xffffffff, s2, w);
    }
    __shared__ float sh[16];
    __shared__ float red[2];
    int wid = tid >> 5, lid = tid & 31;
    if (lid == 0) { sh[wid] = s; sh[wid + 8] = s2; }
    __syncthreads();
    if (tid == 0) {
        float ts = 0.f, ts2 = 0.f;
#pragma unroll
        for (int i = 0; i < 8; i++) { ts += sh[i]; ts2 += sh[i + 8]; }
        red[0] = ts; red[1] = ts2;
    }
    __syncthreads();
    float mean = red[0] * (1.0f / EMB);
    float var = red[1] * (1.0f / EMB) - mean * mean;
    float rs = rsqrtf(var + 1e-3f);
    float4 gg = ((const float4*)gamma)[tid];
    float4 bt = ((const float4*)beta)[tid];
    float4 ov;
    ov.x = (v.x - mean) * rs * gg.x + bt.x;
    ov.y = (v.y - mean) * rs * gg.y + bt.y;
    ov.z = (v.z - mean) * rs * gg.z + bt.z;
    ov.w = (v.w - mean) * rs * gg.w + bt.w;
    ((float4*)(out + (size_t)row * EMB))[tid] = ov;
}

// ---------------- launch ----------------
extern "C" void kernel_launch(void* const* d_in, const int* in_sizes, int n_in,
                              void* d_out, int out_size)
{
    const float* w      = (const float*)d_in[0];
    const float* r      = (const float*)d_in[1];
    const float* rwb    = (const float*)d_in[3];
    const float* rrb    = (const float*)d_in[4];
    const float* member = (const float*)d_in[5];
    const float* Wq     = (const float*)d_in[6];
    const float* Wk     = (const float*)d_in[7];
    const float* Wv     = (const float*)d_in[8];
    const float* Wr     = (const float*)d_in[9];
    const float* Wo     = (const float*)d_in[10];
    const float* gamma  = (const float*)d_in[11];
    const float* beta   = (const float*)d_in[12];
    float* out = (float*)d_out;

    dim3 blk(256);

    // 0) transpose + convert weights to bf16 [n][k]
    transposeW<<<dim3(32, 32, 5), blk>>>(Wq, Wk, Wv, Wr, Wo);

    // 1) ALL projections (Q, fused KV, R) in one launch: 768 tiles
    proj_gemm<<<768, blk>>>(w, member, r);

    // 2) BD with fused rel_shift
    bd_mma<<<dim3(32, 8, 32), blk>>>(rrb);

    // 3) flash attention (dyn smem 92160B: Q + 2x(K|V|BD))
    static const int FLASH_SMEM = 92160;
    cudaFuncSetAttribute(flash_mma, cudaFuncAttributeMaxDynamicSharedMemorySize, FLASH_SMEM);
    flash_mma<<<dim3(8, NH, BB), blk, FLASH_SMEM>>>(rwb);

    // 4) output projection + residual (fp32 out)
    wo_gemm<<<dim3(8, 16), blk>>>(w);

    // 5) layernorm
    ln_kernel<<<BB * QL, blk>>>(gamma, beta, out);
}

// round 11
// speedup vs baseline: 5.0462x; 1.0498x over previous
#include <cuda_runtime.h>
#include <cuda_bf16.h>
#include <cstdint>

#define BB 2
#define QL 1024
#define ML 1024
#define KLEN 2048
#define EMB 1024
#define NH 16
#define DH 64

typedef __nv_bfloat16 bf16;
typedef __nv_bfloat162 bf162;

// scale folded into Q and BD: (1/sqrt(1024)) * log2(e)
#define SCL2 (0.03125f * 1.4426950408889634f)

// ---------------- scratch (static device, allocation-free) ----------------
__device__ bf16 g_Qh[BB * QL * EMB];
__device__ bf16 g_Kh[BB * KLEN * EMB];
__device__ bf16 g_Vh[BB * KLEN * EMB];
__device__ bf16 g_Rh[KLEN * EMB];
__device__ bf16 g_BDh[(size_t)BB * NH * QL * KLEN];
__device__ float g_AO[BB * QL * EMB];
__device__ float g_X[BB * QL * EMB];
__device__ bf16 g_WTb[5ull * 1024 * 1024];

__device__ __forceinline__ uint32_t smem_u32(const void* p) {
    uint32_t a;
    asm("{ .reg .u64 t; cvta.to.shared.u64 t, %1; cvt.u32.u64 %0, t; }" : "=r"(a) : "l"(p));
    return a;
}
__device__ __forceinline__ uint32_t bf16x2_of(float lo, float hi) {
    uint32_t o;
    asm("cvt.rn.bf16x2.f32 %0, %1, %2;" : "=r"(o) : "f"(hi), "f"(lo));
    return o;
}
__device__ __forceinline__ float2 f2_of_bf16x2(uint32_t w) {
    bf162 t = *reinterpret_cast<bf162*>(&w);
    return __bfloat1622float2(t);
}
__device__ __forceinline__ float ex2f(float x) {
    float y;
    asm("ex2.approx.f32 %0, %1;" : "=f"(y) : "f"(x));
    return y;
}
#define MMA16816(C, A0, A1, A2, A3, B0, B1) \
    asm volatile("mma.sync.aligned.m16n8k16.row.col.f32.bf16.bf16.f32 " \
        "{%0,%1,%2,%3}, {%4,%5,%6,%7}, {%8,%9}, {%0,%1,%2,%3};" \
        : "+f"((C)[0]), "+f"((C)[1]), "+f"((C)[2]), "+f"((C)[3]) \
        : "r"(A0), "r"(A1), "r"(A2), "r"(A3), "r"(B0), "r"(B1))
#define LDSM_X4(d0, d1, d2, d3, addr) \
    asm volatile("ldmatrix.sync.aligned.m8n8.x4.shared.b16 {%0,%1,%2,%3}, [%4];" \
        : "=r"(d0), "=r"(d1), "=r"(d2), "=r"(d3) : "r"(addr))
#define LDSM_X4_T(d0, d1, d2, d3, addr) \
    asm volatile("ldmatrix.sync.aligned.m8n8.x4.trans.shared.b16 {%0,%1,%2,%3}, [%4];" \
        : "=r"(d0), "=r"(d1), "=r"(d2), "=r"(d3) : "r"(addr))
#define CPA16(dst, src) \
    asm volatile("cp.async.cg.shared.global [%0], [%1], 16;" :: "r"(dst), "l"(src) : "memory")
#define CP_COMMIT() asm volatile("cp.async.commit_group;" ::: "memory")
#define CP_WAIT0()  asm volatile("cp.async.wait_group 0;" ::: "memory")
#define CP_WAIT1()  asm volatile("cp.async.wait_group 1;" ::: "memory")

// ---------------- weight transpose + bf16 convert ----------------
__global__ __launch_bounds__(256) void transposeW(
    const float* __restrict__ w0, const float* __restrict__ w1,
    const float* __restrict__ w2, const float* __restrict__ w3,
    const float* __restrict__ w4)
{
    __shared__ float t[32][33];
    const float* src;
    switch (blockIdx.z) {
        case 0: src = w0; break;
        case 1: src = w1; break;
        case 2: src = w2; break;
        case 3: src = w3; break;
        default: src = w4; break;
    }
    bf16* dst = g_WTb + ((size_t)blockIdx.z << 20);
    int tx = threadIdx.x & 31, ty = threadIdx.x >> 5;
    int x = blockIdx.x * 32 + tx;
    int y = blockIdx.y * 32 + ty;
#pragma unroll
    for (int j = 0; j < 32; j += 8)
        t[ty + j][tx] = src[(size_t)(y + j) * EMB + x];
    __syncthreads();
    x = blockIdx.y * 32 + tx;
    y = blockIdx.x * 32 + ty;
#pragma unroll
    for (int j = 0; j < 32; j += 8)
        dst[(size_t)(y + j) * EMB + x] = __float2bfloat16(t[tx][ty + j]);
}

// ================= shared GEMM body (128x128 tile, ldmatrix, cp.async) =================
template <bool OBF>
__device__ __forceinline__ void gemm_tile_body(
    const float* __restrict__ A, const float* __restrict__ A2,
    const bf16* __restrict__ WT,
    void* C0v, void* C1v, const float* __restrict__ resid,
    int mode, int m0, int n0, uint32_t* smw)
{
    const uint32_t sbase = smem_u32(smw);
    const int tid = threadIdx.x;
    const int lane = tid & 31, wid = tid >> 5;
    const int wm = wid >> 1, wn = wid & 1;
    const int g = lane >> 2, tig = lane & 3;

    const float* ap[4];
    uint32_t swA[4];
#pragma unroll
    for (int u = 0; u < 4; u++) {
        int f4 = tid + 256 * u;
        int rr = f4 >> 3, c4 = f4 & 7;
        int m = m0 + rr;
        const float* arow;
        if (mode == 0) {
            arow = A + (size_t)m * EMB;
        } else {
            int b = m >> 11, t = m & 2047;
            arow = (t < ML) ? (A + ((size_t)b * ML + t) * EMB)
                            : (A2 + ((size_t)b * QL + (t - ML)) * EMB);
        }
        ap[u] = arow + c4 * 4;
        swA[u] = (uint32_t)(rr * 20 + c4 * 2);
    }
    const bf16* bp[2];
    uint32_t dstB[2];
#pragma unroll
    for (int v = 0; v < 2; v++) {
        int f16 = tid + 256 * v;
        int rr = f16 >> 2, c16 = f16 & 3;
        bp[v] = WT + (size_t)(n0 + rr) * EMB + c16 * 8;
        dstB[v] = sbase + 10240 + (uint32_t)(rr * 80 + c16 * 16);
    }

    float4 ra[4];
#define LDGA(k0) do { \
        _Pragma("unroll") for (int u = 0; u < 4; u++) ra[u] = *(const float4*)(ap[u] + (k0)); \
    } while (0)
#define STSA(buf) do { \
        uint32_t* Aw_ = smw + (buf) * 5120; \
        _Pragma("unroll") for (int u = 0; u < 4; u++) { \
            Aw_[swA[u]]     = bf16x2_of(ra[u].x, ra[u].y); \
            Aw_[swA[u] + 1] = bf16x2_of(ra[u].z, ra[u].w); \
        } \
    } while (0)
#define CPB(buf, k0) do { \
        _Pragma("unroll") for (int v = 0; v < 2; v++) \
            CPA16(dstB[v] + (buf) * 20480, bp[v] + (k0)); \
        CP_COMMIT(); \
    } while (0)

    const uint32_t aLd = sbase + (uint32_t)((wm * 32 + (lane & 15)) * 80 + (lane & 16));
    const uint32_t bLd = sbase + 10240 + (uint32_t)((wn * 64 + (lane & 15)) * 80 + (lane & 16));

    float c[2][8][4];
#pragma unroll
    for (int mf = 0; mf < 2; mf++)
#pragma unroll
        for (int nf = 0; nf < 8; nf++)
#pragma unroll
            for (int e = 0; e < 4; e++) c[mf][nf][e] = 0.f;

    LDGA(0);
    CPB(0, 0);
    STSA(0);
    CP_WAIT0();
    __syncthreads();

    for (int it = 0; it < 32; it++) {
        if (it + 1 < 32) {
            LDGA((it + 1) * 32);
            CPB((it + 1) & 1, (it + 1) * 32);
        }
        const uint32_t bufB = (uint32_t)(it & 1) * 20480;
#pragma unroll
        for (int ks = 0; ks < 2; ks++) {
            uint32_t a0, a1, a2, a3, a4, a5, a6, a7;
            LDSM_X4(a0, a1, a2, a3, aLd + bufB + ks * 32);
            LDSM_X4(a4, a5, a6, a7, aLd + bufB + 1280 + ks * 32);
#pragma unroll
            for (int nf2 = 0; nf2 < 4; nf2++) {
                uint32_t b0, b1, b2, b3;
                LDSM_X4(b0, b1, b2, b3, bLd + bufB + nf2 * 1280 + ks * 32);
                MMA16816(c[0][2 * nf2],     a0, a1, a2, a3, b0, b2);
                MMA16816(c[0][2 * nf2 + 1], a0, a1, a2, a3, b1, b3);
                MMA16816(c[1][2 * nf2],     a4, a5, a6, a7, b0, b2);
                MMA16816(c[1][2 * nf2 + 1], a4, a5, a6, a7, b1, b3);
            }
        }
        if (it + 1 < 32) STSA((it + 1) & 1);
        CP_WAIT0();
        __syncthreads();
    }

    if (OBF) {
        bf16* C = (bf16*)((n0 < 1024) ? C0v : C1v);
        int col0 = (n0 & 1023) + wn * 64;
#pragma unroll
        for (int mf = 0; mf < 2; mf++) {
            int r0 = m0 + wm * 32 + mf * 16 + g;
#pragma unroll
            for (int nf = 0; nf < 8; nf++) {
                int col = col0 + nf * 8 + tig * 2;
                *(uint32_t*)&C[(size_t)r0 * EMB + col] = bf16x2_of(c[mf][nf][0], c[mf][nf][1]);
                *(uint32_t*)&C[(size_t)(r0 + 8) * EMB + col] = bf16x2_of(c[mf][nf][2], c[mf][nf][3]);
            }
        }
    } else {
        float* C = (float*)C0v;
#pragma unroll
        for (int mf = 0; mf < 2; mf++) {
            int r0 = m0 + wm * 32 + mf * 16 + g;
#pragma unroll
            for (int nf = 0; nf < 8; nf++) {
                int col = n0 + wn * 64 + nf * 8 + tig * 2;
                float2 v0 = make_float2(c[mf][nf][0], c[mf][nf][1]);
                float2 v1 = make_float2(c[mf][nf][2], c[mf][nf][3]);
                if (resid) {
                    float2 a0 = *(const float2*)(resid + (size_t)r0 * EMB + col);
                    float2 a1 = *(const float2*)(resid + (size_t)(r0 + 8) * EMB + col);
                    v0.x += a0.x; v0.y += a0.y;
                    v1.x += a1.x; v1.y += a1.y;
                }
                *(float2*)(C + (size_t)r0 * EMB + col) = v0;
                *(float2*)(C + (size_t)(r0 + 8) * EMB + col) = v1;
            }
        }
    }
#undef LDGA
#undef STSA
#undef CPB
}

// ---------------- fused projection GEMM: Q + KV + R in one launch ----------------
__global__ __launch_bounds__(256, 2) void proj_gemm(
    const float* __restrict__ w, const float* __restrict__ member,
    const float* __restrict__ r)
{
    __shared__ uint32_t smw[10240];
    const int t = blockIdx.x;
    const float *A, *A2 = nullptr;
    const bf16* WT;
    void *C0, *C1 = nullptr;
    int mode, m0, n0;
    if (t < 128) {
        A = w; WT = g_WTb; C0 = g_Qh; mode = 0;
        m0 = (t >> 3) * 128; n0 = (t & 7) * 128;
    } else if (t < 640) {
        int u = t - 128;
        A = member; A2 = w; WT = g_WTb + (1u << 20); C0 = g_Kh; C1 = g_Vh; mode = 1;
        m0 = (u >> 4) * 128; n0 = (u & 15) * 128;
    } else {
        int u = t - 640;
        A = r; WT = g_WTb + (3u << 20); C0 = g_Rh; mode = 0;
        m0 = (u >> 3) * 128; n0 = (u & 7) * 128;
    }
    gemm_tile_body<true>(A, A2, WT, C0, C1, nullptr, mode, m0, n0, smw);
}

// ---------------- Wo GEMM + residual (fp32 out) ----------------
__global__ __launch_bounds__(256, 2) void wo_gemm(const float* __restrict__ resid)
{
    __shared__ uint32_t smw[10240];
    const int m0 = blockIdx.y * 128, n0 = blockIdx.x * 128;
    gemm_tile_body<false>(g_AO, nullptr, g_WTb + (4u << 20), g_X, nullptr,
                          resid, 0, m0, n0, smw);
}

// ---------------- BD via bf16 mma (ldmatrix), pre-shifted band write (x SCL2) ----------------
__global__ __launch_bounds__(256, 2) void bd_mma(const float* __restrict__ rrb)
{
    const int pt = blockIdx.x, it = blockIdx.y, bh = blockIdx.z;
    const int i0 = it * 128, p0 = pt * 64;
    if (i0 + p0 < 833) return;
    const int b = bh >> 4, h = bh & 15;

    __shared__ uint32_t sm[6912];
    const uint32_t sbase = smem_u32(sm);
    const uint32_t Rb = sbase + 18432;
    const int tid = threadIdx.x, lane = tid & 31, wm = tid >> 5;
    const int g = lane >> 2, tig = lane & 3;

#pragma unroll
    for (int u = 0; u < 2; u++) {
        int f = tid + 256 * u;
        int row = f >> 3, c16 = f & 7;
        CPA16(Rb + row * 144 + c16 * 16,
              g_Rh + ((size_t)(p0 + row)) * EMB + h * DH + c16 * 8);
    }
    CP_COMMIT();

    const float2* bias2 = (const float2*)&rrb[h * DH];
#pragma unroll
    for (int u = 0; u < 4; u++) {
        int f = tid + 256 * u;
        int row = f >> 3, d8 = (f & 7) * 8;
        uint4 qv = *(const uint4*)&g_Qh[((size_t)(b * QL + i0 + row)) * EMB + h * DH + d8];
        const uint32_t* qw = (const uint32_t*)&qv;
#pragma unroll
        for (int j = 0; j < 4; j++) {
            float2 qf = f2_of_bf16x2(qw[j]);
            float2 bbv = bias2[(d8 >> 1) + j];
            sm[row * 36 + (d8 >> 1) + j] = bf16x2_of(qf.x + bbv.x, qf.y + bbv.y);
        }
    }
    CP_WAIT0();
    __syncthreads();

    const uint32_t aLd = sbase + (uint32_t)((wm * 16 + (lane & 15)) * 144 + (lane & 16));
    const uint32_t bLd = Rb + (uint32_t)((lane & 15) * 144 + (lane & 16));

    float s[8][4];
#pragma unroll
    for (int nf = 0; nf < 8; nf++)
#pragma unroll
        for (int e = 0; e < 4; e++) s[nf][e] = 0.f;

#pragma unroll
    for (int ks = 0; ks < 4; ks++) {
        uint32_t a0, a1, a2, a3;
        LDSM_X4(a0, a1, a2, a3, aLd + ks * 32);
#pragma unroll
        for (int nf2 = 0; nf2 < 4; nf2++) {
            uint32_t b0, b1, b2, b3;
            LDSM_X4(b0, b1, b2, b3, bLd + nf2 * 2304 + ks * 32);
            MMA16816(s[2 * nf2],     a0, a1, a2, a3, b0, b2);
            MMA16816(s[2 * nf2 + 1], a0, a1, a2, a3, b1, b3);
        }
    }

    bf16* bdb = g_BDh + (size_t)(b * NH + h) * QL * KLEN;
#pragma unroll
    for (int e = 0; e < 2; e++) {
        int i = i0 + wm * 16 + g + 8 * e;
#pragma unroll
        for (int nf = 0; nf < 8; nf++) {
            int p = p0 + nf * 8 + 2 * tig;
            int j0 = p - (QL - 1) + i;
            if (j0 >= 0)     bdb[(size_t)i * KLEN + j0]     = __float2bfloat16(s[nf][2 * e] * SCL2);
            if (j0 + 1 >= 0) bdb[(size_t)i * KLEN + j0 + 1] = __float2bfloat16(s[nf][2 * e + 1] * SCL2);
        }
    }
}

// ---------------- flash attention: streaming softmax (no running max) ----------------
// Q prescaled by SCL2, BD prescaled by SCL2 -> S accum = log2-domain scores.
// smem bytes: Q [0,18432); buf b at 18432 + b*36864: K 9216 | V 9216 | BD 18432.
__global__ __launch_bounds__(256) void flash_mma(const float* __restrict__ rwb)
{
    extern __shared__ uint32_t smd[];
    const uint32_t sbase = smem_u32(smd);

    const int qt = 7 - blockIdx.x, h = blockIdx.y, b = blockIdx.z;
    const int qi0 = qt * 128;
    const int tid = threadIdx.x, lane = tid & 31, wm = tid >> 5;
    const int g = lane >> 2, tig = lane & 3;

    const bf16* bdb = g_BDh + (size_t)(b * NH + h) * QL * KLEN + (size_t)qi0 * KLEN;

#define CPKV(kt, buf) do { \
        const int kj0_ = (kt) * 64; \
        uint32_t kb_ = sbase + 18432 + (uint32_t)(buf) * 36864; \
        _Pragma("unroll") for (int u = 0; u < 2; u++) { \
            int f_ = tid + 256 * u; \
            int row_ = f_ >> 3, c16_ = f_ & 7; \
            size_t go_ = ((size_t)(b * KLEN + kj0_ + row_)) * EMB + h * DH + c16_ * 8; \
            CPA16(kb_ + row_ * 144 + c16_ * 16, g_Kh + go_); \
            CPA16(kb_ + 9216 + row_ * 144 + c16_ * 16, g_Vh + go_); \
        } \
        _Pragma("unroll") for (int u = 0; u < 4; u++) { \
            int f_ = tid + 256 * u; \
            int row_ = f_ >> 3, c16_ = f_ & 7; \
            CPA16(kb_ + 18432 + row_ * 144 + c16_ * 16, \
                  bdb + (size_t)row_ * KLEN + kj0_ + c16_ * 8); \
        } \
        CP_COMMIT(); \
    } while (0)

    CPKV(0, 0);
    // Q tile + content bias, prescaled by SCL2
    const float2* bias2 = (const float2*)&rwb[h * DH];
#pragma unroll
    for (int u = 0; u < 4; u++) {
        int f = tid + 256 * u;
        int row = f >> 3, d8 = (f & 7) * 8;
        uint4 qv = *(const uint4*)&g_Qh[((size_t)(b * QL + qi0 + row)) * EMB + h * DH + d8];
        const uint32_t* qw = (const uint32_t*)&qv;
#pragma unroll
        for (int j = 0; j < 4; j++) {
            float2 qf = f2_of_bf16x2(qw[j]);
            float2 bbv = bias2[(d8 >> 1) + j];
            smd[row * 36 + (d8 >> 1) + j] =
                bf16x2_of((qf.x + bbv.x) * SCL2, (qf.y + bbv.y) * SCL2);
        }
    }

    float o[8][4];
#pragma unroll
    for (int nf = 0; nf < 8; nf++)
#pragma unroll
        for (int e = 0; e < 4; e++) o[nf][e] = 0.f;
    float lr[2] = {0.f, 0.f};

    const uint32_t qLd = sbase + (uint32_t)((wm * 16 + (lane & 15)) * 144 + (lane & 16));
    const uint32_t kLdOff = (uint32_t)((lane & 15) * 144 + (lane & 16));
    const uint32_t vLdOff = (uint32_t)(((lane & 7) + ((lane & 16) >> 1)) * 144 + (lane & 8) * 2);

    const int nkt = 2 * qt + 18;
    for (int kt = 0; kt < nkt; kt++) {
        const int buf = kt & 1;
        if (kt + 1 < nkt) {
            CPKV(kt + 1, (kt + 1) & 1);
            CP_WAIT1();
        } else {
            CP_WAIT0();
        }
        __syncthreads();

        const uint32_t Kb = sbase + 18432 + (uint32_t)buf * 36864;
        const uint32_t kLd = Kb + kLdOff;
        const uint32_t vLd = Kb + 9216 + vLdOff;
        const int kj0 = kt * 64;
        const bool edge = (kt >= nkt - 2);

        // init S accumulators from BD (C-fragment layout == smem band layout)
        float s[8][4];
#pragma unroll
        for (int e = 0; e < 2; e++) {
            const int iloc = wm * 16 + g + 8 * e;
            const uint32_t* bdp = smd + 9216 * (buf + 1) + iloc * 36 + tig;
#pragma unroll
            for (int nf = 0; nf < 8; nf++) {
                float2 bd = f2_of_bf16x2(bdp[nf * 4]);
                s[nf][2 * e] = bd.x;
                s[nf][2 * e + 1] = bd.y;
            }
        }

        // S += Q @ K^T (Q prescaled -> log2-domain)
#pragma unroll
        for (int ks = 0; ks < 4; ks++) {
            uint32_t a0, a1, a2, a3;
            LDSM_X4(a0, a1, a2, a3, qLd + ks * 32);
#pragma unroll
            for (int nf2 = 0; nf2 < 4; nf2++) {
                uint32_t b0, b1, b2, b3;
                LDSM_X4(b0, b1, b2, b3, kLd + nf2 * 2304 + ks * 32);
                MMA16816(s[2 * nf2],     a0, a1, a2, a3, b0, b2);
                MMA16816(s[2 * nf2 + 1], a0, a1, a2, a3, b1, b3);
            }
        }

        // mask (edge tiles only)
        if (edge) {
#pragma unroll
            for (int e = 0; e < 2; e++) {
                const int i = qi0 + wm * 16 + g + 8 * e;
                const int jb = kj0 + 2 * tig;
                const int jlim = i + ML;
#pragma unroll
                for (int nf = 0; nf < 8; nf++) {
                    int j0 = jb + nf * 8;
                    if (j0 > jlim)     s[nf][2 * e]     = -1e30f;
                    if (j0 + 1 > jlim) s[nf][2 * e + 1] = -1e30f;
                }
            }
        }

        // p = exp2(s); accumulate row sums (no max, no rescale)
#pragma unroll
        for (int e = 0; e < 2; e++) {
            float ps = 0.f;
#pragma unroll
            for (int nf = 0; nf < 8; nf++) {
                float p0 = ex2f(s[nf][2 * e]);
                float p1 = ex2f(s[nf][2 * e + 1]);
                s[nf][2 * e] = p0;
                s[nf][2 * e + 1] = p1;
                ps += p0 + p1;
            }
            lr[e] += ps;
        }

        // pack P fragments (C-layout == A-layout)
        uint32_t pa[4][4];
#pragma unroll
        for (int t = 0; t < 4; t++) {
            pa[t][0] = bf16x2_of(s[2 * t][0], s[2 * t][1]);
            pa[t][1] = bf16x2_of(s[2 * t][2], s[2 * t][3]);
            pa[t][2] = bf16x2_of(s[2 * t + 1][0], s[2 * t + 1][1]);
            pa[t][3] = bf16x2_of(s[2 * t + 1][2], s[2 * t + 1][3]);
        }

        // O += P @ V (V^T via ldmatrix.trans)
#pragma unroll
        for (int t = 0; t < 4; t++) {
#pragma unroll
            for (int nf2 = 0; nf2 < 4; nf2++) {
                uint32_t b0, b1, b2, b3;
                LDSM_X4_T(b0, b1, b2, b3, vLd + t * 2304 + nf2 * 32);
                MMA16816(o[2 * nf2],     pa[t][0], pa[t][1], pa[t][2], pa[t][3], b0, b2);
                MMA16816(o[2 * nf2 + 1], pa[t][0], pa[t][1], pa[t][2], pa[t][3], b1, b3);
            }
        }
        __syncthreads();
    }

    // final: quad-reduce row sums once, normalize, store
#pragma unroll
    for (int e = 0; e < 2; e++) {
        float ps = lr[e];
        ps += __shfl_xor_sync(0xffffffff, ps, 1);
        ps += __shfl_xor_sync(0xffffffff, ps, 2);
        float inv = 1.0f / ps;
        int i = qi0 + wm * 16 + g + 8 * e;
#pragma unroll
        for (int nf = 0; nf < 8; nf++) {
            float2 v = make_float2(o[nf][2 * e] * inv, o[nf][2 * e + 1] * inv);
            *(float2*)&g_AO[((size_t)b * QL + i) * EMB + h * DH + nf * 8 + 2 * tig] = v;
        }
    }
}

// ---------------- layernorm ----------------
__global__ __launch_bounds__(256) void ln_kernel(
    const float* __restrict__ gamma, const float* __restrict__ beta,
    float* __restrict__ out)
{
    const int row = blockIdx.x;
    const int tid = threadIdx.x;
    const float* x = g_X + (size_t)row * EMB;
    float4 v = ((const float4*)x)[tid];
    float s = v.x + v.y + v.z + v.w;
    float s2 = v.x * v.x + v.y * v.y + v.z * v.z + v.w * v.w;
#pragma unroll
    for (int w = 1; w < 32; w <<= 1) {
        s += __shfl_xor_sync(0xffffffff, s, w);
        s2 += __shfl_xor_sync(0xffffffff, s2, w);
    }
    __shared__ float sh[16];
    __shared__ float red[2];
    int wid = tid >> 5, lid = tid & 31;
    if (lid == 0) { sh[wid] = s; sh[wid + 8] = s2; }
    __syncthreads();
    if (tid == 0) {
        float ts = 0.f, ts2 = 0.f;
#pragma unroll
        for (int i = 0; i < 8; i++) { ts += sh[i]; ts2 += sh[i + 8]; }
        red[0] = ts; red[1] = ts2;
    }
    __syncthreads();
    float mean = red[0] * (1.0f / EMB);
    float var = red[1] * (1.0f / EMB) - mean * mean;
    float rs = rsqrtf(var + 1e-3f);
    float4 gg = ((const float4*)gamma)[tid];
    float4 bt = ((const float4*)beta)[tid];
    float4 ov;
    ov.x = (v.x - mean) * rs * gg.x + bt.x;
    ov.y = (v.y - mean) * rs * gg.y + bt.y;
    ov.z = (v.z - mean) * rs * gg.z + bt.z;
    ov.w = (v.w - mean) * rs * gg.w + bt.w;
    ((float4*)(out + (size_t)row * EMB))[tid] = ov;
}

// ---------------- launch ----------------
extern "C" void kernel_launch(void* const* d_in, const int* in_sizes, int n_in,
                              void* d_out, int out_size)
{
    const float* w      = (const float*)d_in[0];
    const float* r      = (const float*)d_in[1];
    const float* rwb    = (const float*)d_in[3];
    const float* rrb    = (const float*)d_in[4];
    const float* member = (const float*)d_in[5];
    const float* Wq     = (const float*)d_in[6];
    const float* Wk     = (const float*)d_in[7];
    const float* Wv     = (const float*)d_in[8];
    const float* Wr     = (const float*)d_in[9];
    const float* Wo     = (const float*)d_in[10];
    const float* gamma  = (const float*)d_in[11];
    const float* beta   = (const float*)d_in[12];
    float* out = (float*)d_out;

    dim3 blk(256);

    // 0) transpose + convert weights to bf16 [n][k]
    transposeW<<<dim3(32, 32, 5), blk>>>(Wq, Wk, Wv, Wr, Wo);

    // 1) ALL projections (Q, fused KV, R) in one launch: 768 tiles
    proj_gemm<<<768, blk>>>(w, member, r);

    // 2) BD with fused rel_shift (prescaled by SCL2)
    bd_mma<<<dim3(32, 8, 32), blk>>>(rrb);

    // 3) flash attention (dyn smem 92160B: Q + 2x(K|V|BD))
    static const int FLASH_SMEM = 92160;
    cudaFuncSetAttribute(flash_mma, cudaFuncAttributeMaxDynamicSharedMemorySize, FLASH_SMEM);
    flash_mma<<<dim3(8, NH, BB), blk, FLASH_SMEM>>>(rwb);

    // 4) output projection + residual (fp32 out)
    wo_gemm<<<dim3(8, 16), blk>>>(w);

    // 5) layernorm
    ln_kernel<<<BB * QL, blk>>>(gamma, beta, out);
}

// round 12
// speedup vs baseline: 5.1074x; 1.0121x over previous
#include <cuda_runtime.h>
#include <cuda_bf16.h>
#include <cstdint>

#define BB 2
#define QL 1024
#define ML 1024
#define KLEN 2048
#define EMB 1024
#define NH 16
#define DH 64

typedef __nv_bfloat16 bf16;
typedef __nv_bfloat162 bf162;

// scale folded into Q and BD: (1/sqrt(1024)) * log2(e)
#define SCL2 (0.03125f * 1.4426950408889634f)

// ---------------- scratch (static device, allocation-free) ----------------
__device__ bf16 g_Qh[BB * QL * EMB];
__device__ bf16 g_Kh[BB * KLEN * EMB];
__device__ bf16 g_Vh[BB * KLEN * EMB];
__device__ bf16 g_Rh[KLEN * EMB];
__device__ bf16 g_BDh[(size_t)BB * NH * QL * KLEN];
__device__ float g_AO[BB * QL * EMB];
__device__ float g_AOp[2][BB * QL * EMB];   // split-KV partial O (unnormalized)
__device__ float g_Lp[2][BB * NH * QL];     // split-KV partial row sums
__device__ float g_X[BB * QL * EMB];
__device__ bf16 g_WTb[5ull * 1024 * 1024];

__device__ __forceinline__ uint32_t smem_u32(const void* p) {
    uint32_t a;
    asm("{ .reg .u64 t; cvta.to.shared.u64 t, %1; cvt.u32.u64 %0, t; }" : "=r"(a) : "l"(p));
    return a;
}
__device__ __forceinline__ uint32_t bf16x2_of(float lo, float hi) {
    uint32_t o;
    asm("cvt.rn.bf16x2.f32 %0, %1, %2;" : "=r"(o) : "f"(hi), "f"(lo));
    return o;
}
__device__ __forceinline__ float2 f2_of_bf16x2(uint32_t w) {
    bf162 t = *reinterpret_cast<bf162*>(&w);
    return __bfloat1622float2(t);
}
__device__ __forceinline__ float ex2f(float x) {
    float y;
    asm("ex2.approx.f32 %0, %1;" : "=f"(y) : "f"(x));
    return y;
}
#define MMA16816(C, A0, A1, A2, A3, B0, B1) \
    asm volatile("mma.sync.aligned.m16n8k16.row.col.f32.bf16.bf16.f32 " \
        "{%0,%1,%2,%3}, {%4,%5,%6,%7}, {%8,%9}, {%0,%1,%2,%3};" \
        : "+f"((C)[0]), "+f"((C)[1]), "+f"((C)[2]), "+f"((C)[3]) \
        : "r"(A0), "r"(A1), "r"(A2), "r"(A3), "r"(B0), "r"(B1))
#define LDSM_X4(d0, d1, d2, d3, addr) \
    asm volatile("ldmatrix.sync.aligned.m8n8.x4.shared.b16 {%0,%1,%2,%3}, [%4];" \
        : "=r"(d0), "=r"(d1), "=r"(d2), "=r"(d3) : "r"(addr))
#define LDSM_X4_T(d0, d1, d2, d3, addr) \
    asm volatile("ldmatrix.sync.aligned.m8n8.x4.trans.shared.b16 {%0,%1,%2,%3}, [%4];" \
        : "=r"(d0), "=r"(d1), "=r"(d2), "=r"(d3) : "r"(addr))
#define CPA16(dst, src) \
    asm volatile("cp.async.cg.shared.global [%0], [%1], 16;" :: "r"(dst), "l"(src) : "memory")
#define CP_COMMIT() asm volatile("cp.async.commit_group;" ::: "memory")
#define CP_WAIT0()  asm volatile("cp.async.wait_group 0;" ::: "memory")
#define CP_WAIT1()  asm volatile("cp.async.wait_group 1;" ::: "memory")

// ---------------- weight transpose + bf16 convert ----------------
__global__ __launch_bounds__(256) void transposeW(
    const float* __restrict__ w0, const float* __restrict__ w1,
    const float* __restrict__ w2, const float* __restrict__ w3,
    const float* __restrict__ w4)
{
    __shared__ float t[32][33];
    const float* src;
    switch (blockIdx.z) {
        case 0: src = w0; break;
        case 1: src = w1; break;
        case 2: src = w2; break;
        case 3: src = w3; break;
        default: src = w4; break;
    }
    bf16* dst = g_WTb + ((size_t)blockIdx.z << 20);
    int tx = threadIdx.x & 31, ty = threadIdx.x >> 5;
    int x = blockIdx.x * 32 + tx;
    int y = blockIdx.y * 32 + ty;
#pragma unroll
    for (int j = 0; j < 32; j += 8)
        t[ty + j][tx] = src[(size_t)(y + j) * EMB + x];
    __syncthreads();
    x = blockIdx.y * 32 + tx;
    y = blockIdx.x * 32 + ty;
#pragma unroll
    for (int j = 0; j < 32; j += 8)
        dst[(size_t)(y + j) * EMB + x] = __float2bfloat16(t[tx][ty + j]);
}

// ================= shared GEMM body (128x128 tile, ldmatrix, cp.async) =================
template <bool OBF>
__device__ __forceinline__ void gemm_tile_body(
    const float* __restrict__ A, const float* __restrict__ A2,
    const bf16* __restrict__ WT,
    void* C0v, void* C1v, const float* __restrict__ resid,
    int mode, int m0, int n0, uint32_t* smw)
{
    const uint32_t sbase = smem_u32(smw);
    const int tid = threadIdx.x;
    const int lane = tid & 31, wid = tid >> 5;
    const int wm = wid >> 1, wn = wid & 1;
    const int g = lane >> 2, tig = lane & 3;

    const float* ap[4];
    uint32_t swA[4];
#pragma unroll
    for (int u = 0; u < 4; u++) {
        int f4 = tid + 256 * u;
        int rr = f4 >> 3, c4 = f4 & 7;
        int m = m0 + rr;
        const float* arow;
        if (mode == 0) {
            arow = A + (size_t)m * EMB;
        } else {
            int b = m >> 11, t = m & 2047;
            arow = (t < ML) ? (A + ((size_t)b * ML + t) * EMB)
                            : (A2 + ((size_t)b * QL + (t - ML)) * EMB);
        }
        ap[u] = arow + c4 * 4;
        swA[u] = (uint32_t)(rr * 20 + c4 * 2);
    }
    const bf16* bp[2];
    uint32_t dstB[2];
#pragma unroll
    for (int v = 0; v < 2; v++) {
        int f16 = tid + 256 * v;
        int rr = f16 >> 2, c16 = f16 & 3;
        bp[v] = WT + (size_t)(n0 + rr) * EMB + c16 * 8;
        dstB[v] = sbase + 10240 + (uint32_t)(rr * 80 + c16 * 16);
    }

    float4 ra[4];
#define LDGA(k0) do { \
        _Pragma("unroll") for (int u = 0; u < 4; u++) ra[u] = *(const float4*)(ap[u] + (k0)); \
    } while (0)
#define STSA(buf) do { \
        uint32_t* Aw_ = smw + (buf) * 5120; \
        _Pragma("unroll") for (int u = 0; u < 4; u++) { \
            Aw_[swA[u]]     = bf16x2_of(ra[u].x, ra[u].y); \
            Aw_[swA[u] + 1] = bf16x2_of(ra[u].z, ra[u].w); \
        } \
    } while (0)
#define CPB(buf, k0) do { \
        _Pragma("unroll") for (int v = 0; v < 2; v++) \
            CPA16(dstB[v] + (buf) * 20480, bp[v] + (k0)); \
        CP_COMMIT(); \
    } while (0)

    const uint32_t aLd = sbase + (uint32_t)((wm * 32 + (lane & 15)) * 80 + (lane & 16));
    const uint32_t bLd = sbase + 10240 + (uint32_t)((wn * 64 + (lane & 15)) * 80 + (lane & 16));

    float c[2][8][4];
#pragma unroll
    for (int mf = 0; mf < 2; mf++)
#pragma unroll
        for (int nf = 0; nf < 8; nf++)
#pragma unroll
            for (int e = 0; e < 4; e++) c[mf][nf][e] = 0.f;

    LDGA(0);
    CPB(0, 0);
    STSA(0);
    CP_WAIT0();
    __syncthreads();

    for (int it = 0; it < 32; it++) {
        if (it + 1 < 32) {
            LDGA((it + 1) * 32);
            CPB((it + 1) & 1, (it + 1) * 32);
        }
        const uint32_t bufB = (uint32_t)(it & 1) * 20480;
#pragma unroll
        for (int ks = 0; ks < 2; ks++) {
            uint32_t a0, a1, a2, a3, a4, a5, a6, a7;
            LDSM_X4(a0, a1, a2, a3, aLd + bufB + ks * 32);
            LDSM_X4(a4, a5, a6, a7, aLd + bufB + 1280 + ks * 32);
#pragma unroll
            for (int nf2 = 0; nf2 < 4; nf2++) {
                uint32_t b0, b1, b2, b3;
                LDSM_X4(b0, b1, b2, b3, bLd + bufB + nf2 * 1280 + ks * 32);
                MMA16816(c[0][2 * nf2],     a0, a1, a2, a3, b0, b2);
                MMA16816(c[0][2 * nf2 + 1], a0, a1, a2, a3, b1, b3);
                MMA16816(c[1][2 * nf2],     a4, a5, a6, a7, b0, b2);
                MMA16816(c[1][2 * nf2 + 1], a4, a5, a6, a7, b1, b3);
            }
        }
        if (it + 1 < 32) STSA((it + 1) & 1);
        CP_WAIT0();
        __syncthreads();
    }

    if (OBF) {
        bf16* C = (bf16*)((n0 < 1024) ? C0v : C1v);
        int col0 = (n0 & 1023) + wn * 64;
#pragma unroll
        for (int mf = 0; mf < 2; mf++) {
            int r0 = m0 + wm * 32 + mf * 16 + g;
#pragma unroll
            for (int nf = 0; nf < 8; nf++) {
                int col = col0 + nf * 8 + tig * 2;
                *(uint32_t*)&C[(size_t)r0 * EMB + col] = bf16x2_of(c[mf][nf][0], c[mf][nf][1]);
                *(uint32_t*)&C[(size_t)(r0 + 8) * EMB + col] = bf16x2_of(c[mf][nf][2], c[mf][nf][3]);
            }
        }
    } else {
        float* C = (float*)C0v;
#pragma unroll
        for (int mf = 0; mf < 2; mf++) {
            int r0 = m0 + wm * 32 + mf * 16 + g;
#pragma unroll
            for (int nf = 0; nf < 8; nf++) {
                int col = n0 + wn * 64 + nf * 8 + tig * 2;
                float2 v0 = make_float2(c[mf][nf][0], c[mf][nf][1]);
                float2 v1 = make_float2(c[mf][nf][2], c[mf][nf][3]);
                if (resid) {
                    float2 a0 = *(const float2*)(resid + (size_t)r0 * EMB + col);
                    float2 a1 = *(const float2*)(resid + (size_t)(r0 + 8) * EMB + col);
                    v0.x += a0.x; v0.y += a0.y;
                    v1.x += a1.x; v1.y += a1.y;
                }
                *(float2*)(C + (size_t)r0 * EMB + col) = v0;
                *(float2*)(C + (size_t)(r0 + 8) * EMB + col) = v1;
            }
        }
    }
#undef LDGA
#undef STSA
#undef CPB
}

// ---------------- fused projection GEMM: Q + KV + R in one launch ----------------
__global__ __launch_bounds__(256, 2) void proj_gemm(
    const float* __restrict__ w, const float* __restrict__ member,
    const float* __restrict__ r)
{
    __shared__ uint32_t smw[10240];
    const int t = blockIdx.x;
    const float *A, *A2 = nullptr;
    const bf16* WT;
    void *C0, *C1 = nullptr;
    int mode, m0, n0;
    if (t < 128) {
        A = w; WT = g_WTb; C0 = g_Qh; mode = 0;
        m0 = (t >> 3) * 128; n0 = (t & 7) * 128;
    } else if (t < 640) {
        int u = t - 128;
        A = member; A2 = w; WT = g_WTb + (1u << 20); C0 = g_Kh; C1 = g_Vh; mode = 1;
        m0 = (u >> 4) * 128; n0 = (u & 15) * 128;
    } else {
        int u = t - 640;
        A = r; WT = g_WTb + (3u << 20); C0 = g_Rh; mode = 0;
        m0 = (u >> 3) * 128; n0 = (u & 7) * 128;
    }
    gemm_tile_body<true>(A, A2, WT, C0, C1, nullptr, mode, m0, n0, smw);
}

// ---------------- Wo GEMM + residual (fp32 out) ----------------
__global__ __launch_bounds__(256, 2) void wo_gemm(const float* __restrict__ resid)
{
    __shared__ uint32_t smw[10240];
    const int m0 = blockIdx.y * 128, n0 = blockIdx.x * 128;
    gemm_tile_body<false>(g_AO, nullptr, g_WTb + (4u << 20), g_X, nullptr,
                          resid, 0, m0, n0, smw);
}

// ---------------- BD via bf16 mma (ldmatrix), pre-shifted band write (x SCL2) ----------------
__global__ __launch_bounds__(256, 2) void bd_mma(const float* __restrict__ rrb)
{
    const int pt = blockIdx.x, it = blockIdx.y, bh = blockIdx.z;
    const int i0 = it * 128, p0 = pt * 64;
    if (i0 + p0 < 833) return;
    const int b = bh >> 4, h = bh & 15;

    __shared__ uint32_t sm[6912];
    const uint32_t sbase = smem_u32(sm);
    const uint32_t Rb = sbase + 18432;
    const int tid = threadIdx.x, lane = tid & 31, wm = tid >> 5;
    const int g = lane >> 2, tig = lane & 3;

#pragma unroll
    for (int u = 0; u < 2; u++) {
        int f = tid + 256 * u;
        int row = f >> 3, c16 = f & 7;
        CPA16(Rb + row * 144 + c16 * 16,
              g_Rh + ((size_t)(p0 + row)) * EMB + h * DH + c16 * 8);
    }
    CP_COMMIT();

    const float2* bias2 = (const float2*)&rrb[h * DH];
#pragma unroll
    for (int u = 0; u < 4; u++) {
        int f = tid + 256 * u;
        int row = f >> 3, d8 = (f & 7) * 8;
        uint4 qv = *(const uint4*)&g_Qh[((size_t)(b * QL + i0 + row)) * EMB + h * DH + d8];
        const uint32_t* qw = (const uint32_t*)&qv;
#pragma unroll
        for (int j = 0; j < 4; j++) {
            float2 qf = f2_of_bf16x2(qw[j]);
            float2 bbv = bias2[(d8 >> 1) + j];
            sm[row * 36 + (d8 >> 1) + j] = bf16x2_of(qf.x + bbv.x, qf.y + bbv.y);
        }
    }
    CP_WAIT0();
    __syncthreads();

    const uint32_t aLd = sbase + (uint32_t)((wm * 16 + (lane & 15)) * 144 + (lane & 16));
    const uint32_t bLd = Rb + (uint32_t)((lane & 15) * 144 + (lane & 16));

    float s[8][4];
#pragma unroll
    for (int nf = 0; nf < 8; nf++)
#pragma unroll
        for (int e = 0; e < 4; e++) s[nf][e] = 0.f;

#pragma unroll
    for (int ks = 0; ks < 4; ks++) {
        uint32_t a0, a1, a2, a3;
        LDSM_X4(a0, a1, a2, a3, aLd + ks * 32);
#pragma unroll
        for (int nf2 = 0; nf2 < 4; nf2++) {
            uint32_t b0, b1, b2, b3;
            LDSM_X4(b0, b1, b2, b3, bLd + nf2 * 2304 + ks * 32);
            MMA16816(s[2 * nf2],     a0, a1, a2, a3, b0, b2);
            MMA16816(s[2 * nf2 + 1], a0, a1, a2, a3, b1, b3);
        }
    }

    bf16* bdb = g_BDh + (size_t)(b * NH + h) * QL * KLEN;
#pragma unroll
    for (int e = 0; e < 2; e++) {
        int i = i0 + wm * 16 + g + 8 * e;
#pragma unroll
        for (int nf = 0; nf < 8; nf++) {
            int p = p0 + nf * 8 + 2 * tig;
            int j0 = p - (QL - 1) + i;
            if (j0 >= 0)     bdb[(size_t)i * KLEN + j0]     = __float2bfloat16(s[nf][2 * e] * SCL2);
            if (j0 + 1 >= 0) bdb[(size_t)i * KLEN + j0 + 1] = __float2bfloat16(s[nf][2 * e + 1] * SCL2);
        }
    }
}

// ---------------- flash attention: split-KV streaming softmax ----------------
// grid.x in [0,16): qt = 7 - (x>>1), split = x&1. Each split handles nkt/2 ktiles.
// Writes unnormalized partial O + partial l to its split's fp32 buffers.
// smem bytes: Q [0,18432); buf b at 18432 + b*36864: K 9216 | V 9216 | BD 18432.
__global__ __launch_bounds__(256) void flash_mma(const float* __restrict__ rwb)
{
    extern __shared__ uint32_t smd[];
    const uint32_t sbase = smem_u32(smd);

    const int qt = 7 - (blockIdx.x >> 1), split = blockIdx.x & 1;
    const int h = blockIdx.y, b = blockIdx.z;
    const int qi0 = qt * 128;
    const int tid = threadIdx.x, lane = tid & 31, wm = tid >> 5;
    const int g = lane >> 2, tig = lane & 3;

    const int nkt = 2 * qt + 18;
    const int half = nkt >> 1;
    const int kt0 = split ? half : 0;
    const int kt1 = split ? nkt : half;

    const bf16* bdb = g_BDh + (size_t)(b * NH + h) * QL * KLEN + (size_t)qi0 * KLEN;

#define CPKV(kt, buf) do { \
        const int kj0_ = (kt) * 64; \
        uint32_t kb_ = sbase + 18432 + (uint32_t)(buf) * 36864; \
        _Pragma("unroll") for (int u = 0; u < 2; u++) { \
            int f_ = tid + 256 * u; \
            int row_ = f_ >> 3, c16_ = f_ & 7; \
            size_t go_ = ((size_t)(b * KLEN + kj0_ + row_)) * EMB + h * DH + c16_ * 8; \
            CPA16(kb_ + row_ * 144 + c16_ * 16, g_Kh + go_); \
            CPA16(kb_ + 9216 + row_ * 144 + c16_ * 16, g_Vh + go_); \
        } \
        _Pragma("unroll") for (int u = 0; u < 4; u++) { \
            int f_ = tid + 256 * u; \
            int row_ = f_ >> 3, c16_ = f_ & 7; \
            CPA16(kb_ + 18432 + row_ * 144 + c16_ * 16, \
                  bdb + (size_t)row_ * KLEN + kj0_ + c16_ * 8); \
        } \
        CP_COMMIT(); \
    } while (0)

    CPKV(kt0, kt0 & 1);
    // Q tile + content bias, prescaled by SCL2
    const float2* bias2 = (const float2*)&rwb[h * DH];
#pragma unroll
    for (int u = 0; u < 4; u++) {
        int f = tid + 256 * u;
        int row = f >> 3, d8 = (f & 7) * 8;
        uint4 qv = *(const uint4*)&g_Qh[((size_t)(b * QL + qi0 + row)) * EMB + h * DH + d8];
        const uint32_t* qw = (const uint32_t*)&qv;
#pragma unroll
        for (int j = 0; j < 4; j++) {
            float2 qf = f2_of_bf16x2(qw[j]);
            float2 bbv = bias2[(d8 >> 1) + j];
            smd[row * 36 + (d8 >> 1) + j] =
                bf16x2_of((qf.x + bbv.x) * SCL2, (qf.y + bbv.y) * SCL2);
        }
    }

    float o[8][4];
#pragma unroll
    for (int nf = 0; nf < 8; nf++)
#pragma unroll
        for (int e = 0; e < 4; e++) o[nf][e] = 0.f;
    float lr[2] = {0.f, 0.f};

    const uint32_t qLd = sbase + (uint32_t)((wm * 16 + (lane & 15)) * 144 + (lane & 16));
    const uint32_t kLdOff = (uint32_t)((lane & 15) * 144 + (lane & 16));
    const uint32_t vLdOff = (uint32_t)(((lane & 7) + ((lane & 16) >> 1)) * 144 + (lane & 8) * 2);

    for (int kt = kt0; kt < kt1; kt++) {
        const int buf = kt & 1;
        if (kt + 1 < kt1) {
            CPKV(kt + 1, (kt + 1) & 1);
            CP_WAIT1();
        } else {
            CP_WAIT0();
        }
        __syncthreads();

        const uint32_t Kb = sbase + 18432 + (uint32_t)buf * 36864;
        const uint32_t kLd = Kb + kLdOff;
        const uint32_t vLd = Kb + 9216 + vLdOff;
        const int kj0 = kt * 64;
        const bool edge = (kt >= nkt - 2);

        // init S accumulators from BD (C-fragment layout == smem band layout)
        float s[8][4];
#pragma unroll
        for (int e = 0; e < 2; e++) {
            const int iloc = wm * 16 + g + 8 * e;
            const uint32_t* bdp = smd + 9216 * (buf + 1) + iloc * 36 + tig;
#pragma unroll
            for (int nf = 0; nf < 8; nf++) {
                float2 bd = f2_of_bf16x2(bdp[nf * 4]);
                s[nf][2 * e] = bd.x;
                s[nf][2 * e + 1] = bd.y;
            }
        }

        // S += Q @ K^T (Q prescaled -> log2-domain)
#pragma unroll
        for (int ks = 0; ks < 4; ks++) {
            uint32_t a0, a1, a2, a3;
            LDSM_X4(a0, a1, a2, a3, qLd + ks * 32);
#pragma unroll
            for (int nf2 = 0; nf2 < 4; nf2++) {
                uint32_t b0, b1, b2, b3;
                LDSM_X4(b0, b1, b2, b3, kLd + nf2 * 2304 + ks * 32);
                MMA16816(s[2 * nf2],     a0, a1, a2, a3, b0, b2);
                MMA16816(s[2 * nf2 + 1], a0, a1, a2, a3, b1, b3);
            }
        }

        // mask (edge tiles only)
        if (edge) {
#pragma unroll
            for (int e = 0; e < 2; e++) {
                const int i = qi0 + wm * 16 + g + 8 * e;
                const int jb = kj0 + 2 * tig;
                const int jlim = i + ML;
#pragma unroll
                for (int nf = 0; nf < 8; nf++) {
                    int j0 = jb + nf * 8;
                    if (j0 > jlim)     s[nf][2 * e]     = -1e30f;
                    if (j0 + 1 > jlim) s[nf][2 * e + 1] = -1e30f;
                }
            }
        }

        // p = exp2(s); accumulate row sums (no max, no rescale)
#pragma unroll
        for (int e = 0; e < 2; e++) {
            float ps = 0.f;
#pragma unroll
            for (int nf = 0; nf < 8; nf++) {
                float p0 = ex2f(s[nf][2 * e]);
                float p1 = ex2f(s[nf][2 * e + 1]);
                s[nf][2 * e] = p0;
                s[nf][2 * e + 1] = p1;
                ps += p0 + p1;
            }
            lr[e] += ps;
        }

        // pack P fragments (C-layout == A-layout)
        uint32_t pa[4][4];
#pragma unroll
        for (int t = 0; t < 4; t++) {
            pa[t][0] = bf16x2_of(s[2 * t][0], s[2 * t][1]);
            pa[t][1] = bf16x2_of(s[2 * t][2], s[2 * t][3]);
            pa[t][2] = bf16x2_of(s[2 * t + 1][0], s[2 * t + 1][1]);
            pa[t][3] = bf16x2_of(s[2 * t + 1][2], s[2 * t + 1][3]);
        }

        // O += P @ V (V^T via ldmatrix.trans)
#pragma unroll
        for (int t = 0; t < 4; t++) {
#pragma unroll
            for (int nf2 = 0; nf2 < 4; nf2++) {
                uint32_t b0, b1, b2, b3;
                LDSM_X4_T(b0, b1, b2, b3, vLd + t * 2304 + nf2 * 32);
                MMA16816(o[2 * nf2],     pa[t][0], pa[t][1], pa[t][2], pa[t][3], b0, b2);
                MMA16816(o[2 * nf2 + 1], pa[t][0], pa[t][1], pa[t][2], pa[t][3], b1, b3);
            }
        }
        __syncthreads();
    }

    // store unnormalized partials
    float* AOp = g_AOp[split];
    float* Lp = g_Lp[split];
#pragma unroll
    for (int e = 0; e < 2; e++) {
        float ps = lr[e];
        ps += __shfl_xor_sync(0xffffffff, ps, 1);
        ps += __shfl_xor_sync(0xffffffff, ps, 2);
        int i = qi0 + wm * 16 + g + 8 * e;
        if (tig == 0)
            Lp[((size_t)b * NH + h) * QL + i] = ps;
#pragma unroll
        for (int nf = 0; nf < 8; nf++) {
            float2 v = make_float2(o[nf][2 * e], o[nf][2 * e + 1]);
            *(float2*)&AOp[((size_t)b * QL + i) * EMB + h * DH + nf * 8 + 2 * tig] = v;
        }
    }
}

// ---------------- combine split-KV partials: AO = (O0+O1)/(l0+l1) ----------------
__global__ __launch_bounds__(256) void combine_ao()
{
    const int row = blockIdx.x;            // b*QL + q
    const int tid = threadIdx.x;
    const int b = row >> 10, q = row & 1023;
    const int col = tid * 4;
    const int h = col >> 6;
    float l = g_Lp[0][((size_t)b * NH + h) * QL + q] +
              g_Lp[1][((size_t)b * NH + h) * QL + q];
    float inv = 1.0f / l;
    float4 v0 = *(const float4*)&g_AOp[0][(size_t)row * EMB + col];
    float4 v1 = *(const float4*)&g_AOp[1][(size_t)row * EMB + col];
    float4 ov;
    ov.x = (v0.x + v1.x) * inv;
    ov.y = (v0.y + v1.y) * inv;
    ov.z = (v0.z + v1.z) * inv;
    ov.w = (v0.w + v1.w) * inv;
    *(float4*)&g_AO[(size_t)row * EMB + col] = ov;
}

// ---------------- layernorm ----------------
__global__ __launch_bounds__(256) void ln_kernel(
    const float* __restrict__ gamma, const float* __restrict__ beta,
    float* __restrict__ out)
{
    const int row = blockIdx.x;
    const int tid = threadIdx.x;
    const float* x = g_X + (size_t)row * EMB;
    float4 v = ((const float4*)x)[tid];
    float s = v.x + v.y + v.z + v.w;
    float s2 = v.x * v.x + v.y * v.y + v.z * v.z + v.w * v.w;
#pragma unroll
    for (int w = 1; w < 32; w <<= 1) {
        s += __shfl_xor_sync(0xffffffff, s, w);
        s2 += __shfl_xor_sync(0xffffffff, s2, w);
    }
    __shared__ float sh[16];
    __shared__ float red[2];
    int wid = tid >> 5, lid = tid & 31;
    if (lid == 0) { sh[wid] = s; sh[wid + 8] = s2; }
    __syncthreads();
    if (tid == 0) {
        float ts = 0.f, ts2 = 0.f;
#pragma unroll
        for (int i = 0; i < 8; i++) { ts += sh[i]; ts2 += sh[i + 8]; }
        red[0] = ts; red[1] = ts2;
    }
    __syncthreads();
    float mean = red[0] * (1.0f / EMB);
    float var = red[1] * (1.0f / EMB) - mean * mean;
    float rs = rsqrtf(var + 1e-3f);
    float4 gg = ((const float4*)gamma)[tid];
    float4 bt = ((const float4*)beta)[tid];
    float4 ov;
    ov.x = (v.x - mean) * rs * gg.x + bt.x;
    ov.y = (v.y - mean) * rs * gg.y + bt.y;
    ov.z = (v.z - mean) * rs * gg.z + bt.z;
    ov.w = (v.w - mean) * rs * gg.w + bt.w;
    ((float4*)(out + (size_t)row * EMB))[tid] = ov;
}

// ---------------- launch ----------------
extern "C" void kernel_launch(void* const* d_in, const int* in_sizes, int n_in,
                              void* d_out, int out_size)
{
    const float* w      = (const float*)d_in[0];
    const float* r      = (const float*)d_in[1];
    const float* rwb    = (const float*)d_in[3];
    const float* rrb    = (const float*)d_in[4];
    const float* member = (const float*)d_in[5];
    const float* Wq     = (const float*)d_in[6];
    const float* Wk     = (const float*)d_in[7];
    const float* Wv     = (const float*)d_in[8];
    const float* Wr     = (const float*)d_in[9];
    const float* Wo     = (const float*)d_in[10];
    const float* gamma  = (const float*)d_in[11];
    const float* beta   = (const float*)d_in[12];
    float* out = (float*)d_out;

    dim3 blk(256);

    // 0) transpose + convert weights to bf16 [n][k]
    transposeW<<<dim3(32, 32, 5), blk>>>(Wq, Wk, Wv, Wr, Wo);

    // 1) ALL projections (Q, fused KV, R) in one launch: 768 tiles
    proj_gemm<<<768, blk>>>(w, member, r);

    // 2) BD with fused rel_shift (prescaled by SCL2)
    bd_mma<<<dim3(32, 8, 32), blk>>>(rrb);

    // 3) flash attention split-KV (grid 512, dyn smem 92160B)
    static const int FLASH_SMEM = 92160;
    cudaFuncSetAttribute(flash_mma, cudaFuncAttributeMaxDynamicSharedMemorySize, FLASH_SMEM);
    flash_mma<<<dim3(16, NH, BB), blk, FLASH_SMEM>>>(rwb);

    // 3b) combine partials
    combine_ao<<<BB * QL, blk>>>();

    // 4) output projection + residual (fp32 out)
    wo_gemm<<<dim3(8, 16), blk>>>(w);

    // 5) layernorm
    ln_kernel<<<BB * QL, blk>>>(gamma, beta, out);
}